// round 4
// baseline (speedup 1.0000x reference)
#include <cuda_runtime.h>
#include <math.h>

#define BB 16
#define NN 4096
#define CC 512
#define MM 32
#define NB (BB*NN)          // 65536 rows total
#define EPS_INV 20.0f       // 1/0.05

// ---------------- scratch (device globals; no allocation) ----------------
__device__ float g_yn[BB*MM*CC];            // normalized targets      1 MB
__device__ float g_tw2[BB*MM*CC];           // target @ W2             1 MB
__device__ float g_nu[BB*MM];
__device__ int   g_counts[BB*MM];
__device__ float g_Kt[(size_t)MM*NB];       // Gibbs kernel, TRANSPOSED [m][row]  8 MB
__device__ float g_cost[(size_t)NB*MM];     // cost matrix, row-major  8 MB
__device__ float g_pinorm[(size_t)NB*MM];   // row-normalized pi       8 MB
__device__ float g_u[NB];                   // Sinkhorn u              256 KB
__device__ float g_v[BB*MM];                // Sinkhorn v
__device__ float g_vpart[2][128][32];       // per-block K^T u partials (parity)
__device__ float g_errpart[2][128];         // per-block err partials
__device__ float g_otpart[128];             // per-block ot partials
__device__ int   g_donestep;                // iteration at which Sinkhorn froze

__device__ __forceinline__ float wred(float v) {
#pragma unroll
    for (int o = 16; o; o >>= 1) v += __shfl_xor_sync(0xffffffffu, v, o);
    return v;
}

// ---------------- init ----------------
__global__ void k_init() {
    int t = blockIdx.x * blockDim.x + threadIdx.x;   // <<<128,512>>> covers 65536
    g_u[t] = 0.0f;
    if (t < BB * MM) g_counts[t] = 0;
    if (t == 0) g_donestep = 99;
}

// ---------------- nu: argmax counts over score_map ----------------
__global__ void k_nu_count(const float* __restrict__ score) {
    int idx = blockIdx.x * 256 + threadIdx.x;        // b*4096 + hw
    int b = idx >> 12, hw = idx & 4095;
    const float* p = score + (size_t)b * MM * NN + hw;
    float best = p[0];
    int bi = 0;
#pragma unroll
    for (int k = 1; k < MM; k++) {
        float v = p[(size_t)k * NN];
        if (v > best) { best = v; bi = k; }          // first-max, like jnp.argmax
    }
    atomicAdd(&g_counts[b * MM + bi], 1);
}

__global__ void k_nu_final() {
    int b = blockIdx.x, k = threadIdx.x;             // <<<16,32>>>
    float c = (float)g_counts[b * MM + k];
    float nu = c / (4096.0f + 1e-8f) + 1e-6f;
    float s = wred(nu);
    g_nu[b * MM + k] = nu / s;
}

// ---------------- normalize target rows ----------------
__global__ void k_ynorm(const float* __restrict__ tgt) {
    int row = blockIdx.x;                            // <<<512,128>>>
    const float4* p = (const float4*)(tgt + (size_t)row * CC);
    int t = threadIdx.x;
    float4 v = p[t];
    float s = wred(v.x * v.x + v.y * v.y + v.z * v.z + v.w * v.w);
    __shared__ float ws[4];
    if ((t & 31) == 0) ws[t >> 5] = s;
    __syncthreads();
    float inv = rsqrtf(ws[0] + ws[1] + ws[2] + ws[3]);
    ((float4*)(g_yn + (size_t)row * CC))[t] =
        make_float4(v.x * inv, v.y * inv, v.z * inv, v.w * inv);
}

// ---------------- TW2 = target @ W2  (W2 = fusion_w rows 512..1023) ----------------
__global__ void __launch_bounds__(256) k_tw2(const float* __restrict__ tgt,
                                             const float* __restrict__ W) {
    __shared__ float ts[32 * 128];                   // 16 KB tile
    int blk = blockIdx.x;                            // b*8 + ctile, <<<128,256>>>
    int b = blk >> 3, ct = blk & 7;
    int t = threadIdx.x;
    int c = ct * 64 + (t & 63);
    int mg = t >> 6;                                 // 0..3 -> 8 m's each
    float acc[8];
#pragma unroll
    for (int i = 0; i < 8; i++) acc[i] = 0.0f;
    for (int kt = 0; kt < 4; kt++) {
        __syncthreads();
        for (int i = t; i < 32 * 128 / 4; i += 256) {
            int m = i >> 5, k4 = i & 31;
            ((float4*)ts)[i] =
                ((const float4*)(tgt + ((size_t)(b * 32 + m)) * CC + kt * 128))[k4];
        }
        __syncthreads();
        const float* Wp = W + (size_t)(CC + kt * 128) * CC + c;
        for (int k = 0; k < 128; k++) {
            float w = Wp[(size_t)k * CC];
#pragma unroll
            for (int i = 0; i < 8; i++) acc[i] += ts[(mg * 8 + i) * 128 + k] * w;
        }
    }
#pragma unroll
    for (int i = 0; i < 8; i++)
        g_tw2[(size_t)b * MM * CC + (size_t)(mg * 8 + i) * CC + c] = acc[i];
}

// ---------------- cost / Gibbs kernel matrix ----------------
__global__ void __launch_bounds__(512) k_cost(const float* __restrict__ src) {
    int b = blockIdx.y;
    __shared__ float yns[32 * 256];                  // 32 KB tile (half of C)
    int t = threadIdx.x;
    int warp = t >> 5, lane = t & 31;
    int n = blockIdx.x * 16 + warp;
    const float4* xr = (const float4*)(src + ((size_t)(b * NN + n)) * CC);
    float4 x4[4];
#pragma unroll
    for (int i = 0; i < 4; i++) x4[i] = xr[lane + 32 * i];
    float nrm = 0.0f;
#pragma unroll
    for (int i = 0; i < 4; i++)
        nrm += x4[i].x * x4[i].x + x4[i].y * x4[i].y + x4[i].z * x4[i].z + x4[i].w * x4[i].w;
    nrm = wred(nrm);
    float inv = rsqrtf(nrm);
    float dacc[32];
#pragma unroll
    for (int m = 0; m < 32; m++) dacc[m] = 0.0f;
    for (int ct = 0; ct < 2; ct++) {
        __syncthreads();
        for (int i = t; i < 32 * 256 / 4; i += 512) {
            int m = i >> 6, k4 = i & 63;
            ((float4*)yns)[i] =
                ((const float4*)(g_yn + ((size_t)(b * 32 + m)) * CC + ct * 256))[k4];
        }
        __syncthreads();
#pragma unroll
        for (int m = 0; m < 32; m++) {
            const float4* y4 = (const float4*)(yns + m * 256);
#pragma unroll
            for (int i = 0; i < 2; i++) {
                float4 yv = y4[lane + 32 * i];
                float4 xv = x4[ct * 2 + i];
                dacc[m] += xv.x * yv.x + xv.y * yv.y + xv.z * yv.z + xv.w * yv.w;
            }
        }
    }
    float ccv = 0.0f, kkv = 0.0f;
#pragma unroll
    for (int m = 0; m < 32; m++) {
        float d = wred(dacc[m]);
        if (lane == m) { ccv = 1.0f - d * inv; kkv = expf(ccv * -EPS_INV); }
    }
    int row = b * NN + n;
    g_Kt[(size_t)lane * NB + row] = kkv;             // transposed for Sinkhorn
    g_cost[(size_t)row * MM + lane] = ccv;           // row-major for epilogue
}

// ---------------- Sinkhorn iteration (one launch per iteration) ----------------
// K_i (iter=i): computes v_{i-1} from partials_{i-1} (i>=1), checks err_{i-1};
// if converged -> record donestep=i, freeze. Else u_i update + partials_i.
// iter==50 is the final v-only step.
__global__ void __launch_bounds__(512) k_sink_iter(int iter) {
    if (iter > g_donestep) return;                   // set only by EARLIER kernels
    int g = blockIdx.x, b = g >> 3, t = threadIdx.x; // <<<128,512>>>
    int lane = t & 31, warp = t >> 5;
    __shared__ float sv[32];
    __shared__ float wsum[16][33], werr[16];
    __shared__ int sdone;
    if (iter == 0) {
        if (t < 32) sv[t] = 0.0f;                    // v_0 = 0
        if (t == 32) sdone = 0;
    } else {
        int q = (iter - 1) & 1;
        if (t < 32) {
            float a = 0.0f;
#pragma unroll
            for (int k = 0; k < 8; k++) a += g_vpart[q][(b << 3) + k][t];
            float v = g_nu[b * 32 + t] / (a + 1e-8f);
            sv[t] = v;
            g_v[b * 32 + t] = v;                     // identical across the 8 blocks of b
        }
        if (t == 32) {
            float e = 0.0f;
            for (int k = 0; k < 128; k++) e += g_errpart[q][k];
            sdone = (e * (1.0f / 16.0f) < 0.1f) ? 1 : 0;
        }
    }
    __syncthreads();
    if (sdone) { if (t == 0) g_donestep = iter; return; }
    if (iter >= 50) return;                          // v-only final step

    int row = g * 512 + t;                           // = b*NN + n
    float kk[32];
#pragma unroll
    for (int m = 0; m < 32; m++) kk[m] = g_Kt[(size_t)m * NB + row];  // coalesced
    float denom = 0.0f;
#pragma unroll
    for (int m = 0; m < 32; m++) denom += kk[m] * sv[m];
    const float mu = 1.0f / 4096.0f;
    float un = mu / (denom + 1e-8f);
    float du = fabsf(un - g_u[row]);
    g_u[row] = un;
#pragma unroll
    for (int m = 0; m < 32; m++) {
        float val = wred(kk[m] * un);
        if (lane == 0) wsum[warp][m] = val;
    }
    du = wred(du);
    if (lane == 0) werr[warp] = du;
    __syncthreads();
    int p = iter & 1;
    if (t < 32) {
        float a = 0.0f;
#pragma unroll
        for (int w = 0; w < 16; w++) a += wsum[w][t];
        g_vpart[p][g][t] = a;
    } else if (t == 32) {
        float e = 0.0f;
#pragma unroll
        for (int w = 0; w < 16; w++) e += werr[w];
        g_errpart[p][g] = e;
    }
}

// ---------------- Sinkhorn epilogue: pi, pi_norm, ot partials ----------------
__global__ void __launch_bounds__(512) k_sink_epi(float* __restrict__ out_pi) {
    int g = blockIdx.x, b = g >> 3, t = threadIdx.x; // <<<128,512>>>
    int lane = t & 31, warp = t >> 5;
    __shared__ float sv[32], werr[16];
    if (t < 32) sv[t] = g_v[b * 32 + t];
    __syncthreads();
    int row = g * 512 + t;
    float u = g_u[row];
    float kk[32];
#pragma unroll
    for (int m = 0; m < 32; m++) kk[m] = g_Kt[(size_t)m * NB + row];
    float pi[32];
    float rs = 0.0f;
#pragma unroll
    for (int m = 0; m < 32; m++) { pi[m] = u * kk[m] * sv[m]; rs += pi[m]; }
    size_t rowbase = (size_t)row * MM;
    float* po = out_pi + rowbase;
#pragma unroll
    for (int m = 0; m < 32; m += 4)
        *(float4*)(po + m) = make_float4(pi[m], pi[m + 1], pi[m + 2], pi[m + 3]);
    float inv = 1.0f / (rs + 1e-8f);
#pragma unroll
    for (int m = 0; m < 32; m += 4)
        *(float4*)(g_pinorm + rowbase + m) =
            make_float4(pi[m] * inv, pi[m + 1] * inv, pi[m + 2] * inv, pi[m + 3] * inv);
    float oc = 0.0f;
#pragma unroll
    for (int m = 0; m < 32; m += 4) {
        float4 cq = *(const float4*)(g_cost + rowbase + m);
        oc += pi[m] * cq.x + pi[m + 1] * cq.y + pi[m + 2] * cq.z + pi[m + 3] * cq.w;
    }
    oc = wred(oc);
    if (lane == 0) werr[warp] = oc;
    __syncthreads();
    if (t == 0) {
        float e = 0.0f;
#pragma unroll
        for (int w = 0; w < 16; w++) e += werr[w];
        g_otpart[g] = e;                             // deterministic partial
    }
}

__global__ void k_ot_final(float* __restrict__ out_ot) {
    int b = threadIdx.x;                             // <<<1,16>>>
    float e = 0.0f;
#pragma unroll
    for (int k = 0; k < 8; k++) e += g_otpart[b * 8 + k];
    out_ot[b] = e;
}

// ---------------- fused GEMM: out = src@W1 + pinorm@TW2[b] + bias ----------------
// 128x128 block, 8x8 microtile, 256 threads.
__global__ void __launch_bounds__(256) k_gemm(const float* __restrict__ src,
                                              const float* __restrict__ W,
                                              const float* __restrict__ bias,
                                              float* __restrict__ out) {
    __shared__ float As[16][132];                    // padded (store conflicts ~2-way)
    __shared__ float Bs[16][128];
    int r0 = blockIdx.y * 128, c0 = blockIdx.x * 128;
    int b = r0 >> 12;
    int t = threadIdx.x;
    int tx = t & 15, ty = t >> 4;                    // 16x16 thread grid
    float acc[8][8];
#pragma unroll
    for (int i = 0; i < 8; i++)
#pragma unroll
        for (int j = 0; j < 8; j++) acc[i][j] = 0.0f;

    for (int kt = 0; kt < 34; kt++) {
        int k0 = kt * 16;
        if (k0 < CC) {
#pragma unroll
            for (int j = 0; j < 8; j++) {
                int e = t + j * 256;
                int row = e >> 4, kk = e & 15;
                As[kk][row] = src[(size_t)(r0 + row) * CC + k0 + kk];
            }
#pragma unroll
            for (int j = 0; j < 8; j++) {
                int e = t + j * 256;
                int kk = e >> 7, col = e & 127;
                Bs[kk][col] = W[(size_t)(k0 + kk) * CC + c0 + col];
            }
        } else {
            int kp = k0 - CC;
#pragma unroll
            for (int j = 0; j < 8; j++) {
                int e = t + j * 256;
                int row = e >> 4, kk = e & 15;
                As[kk][row] = g_pinorm[(size_t)(r0 + row) * MM + kp + kk];
            }
#pragma unroll
            for (int j = 0; j < 8; j++) {
                int e = t + j * 256;
                int kk = e >> 7, col = e & 127;
                Bs[kk][col] = g_tw2[(size_t)b * MM * CC + (size_t)(kp + kk) * CC + c0 + col];
            }
        }
        __syncthreads();
#pragma unroll
        for (int k = 0; k < 16; k++) {
            float a[8], bv[8];
            *(float4*)&a[0] = *(float4*)&As[k][ty * 8];
            *(float4*)&a[4] = *(float4*)&As[k][ty * 8 + 4];
            *(float4*)&bv[0] = *(float4*)&Bs[k][tx * 8];
            *(float4*)&bv[4] = *(float4*)&Bs[k][tx * 8 + 4];
#pragma unroll
            for (int i = 0; i < 8; i++)
#pragma unroll
                for (int j = 0; j < 8; j++) acc[i][j] += a[i] * bv[j];
        }
        __syncthreads();
    }
    float bi[8];
    *(float4*)&bi[0] = *(const float4*)(bias + c0 + tx * 8);
    *(float4*)&bi[4] = *(const float4*)(bias + c0 + tx * 8 + 4);
#pragma unroll
    for (int i = 0; i < 8; i++) {
        int r = r0 + ty * 8 + i;
        float* op = out + (size_t)r * CC + c0 + tx * 8;
        *(float4*)op = make_float4(acc[i][0] + bi[0], acc[i][1] + bi[1],
                                   acc[i][2] + bi[2], acc[i][3] + bi[3]);
        *(float4*)(op + 4) = make_float4(acc[i][4] + bi[4], acc[i][5] + bi[5],
                                         acc[i][6] + bi[6], acc[i][7] + bi[7]);
    }
}

// ---------------- LayerNorm, in-place on d_out ----------------
__global__ void k_ln(float* __restrict__ out,
                     const float* __restrict__ gamma,
                     const float* __restrict__ beta) {
    int row = blockIdx.x;                            // <<<65536,128>>>
    float4* p = (float4*)(out + (size_t)row * CC);
    int t = threadIdx.x;
    float4 v = p[t];
    __shared__ float ws[4];
    float s = wred(v.x + v.y + v.z + v.w);
    if ((t & 31) == 0) ws[t >> 5] = s;
    __syncthreads();
    float mean = (ws[0] + ws[1] + ws[2] + ws[3]) * (1.0f / 512.0f);
    float dx0 = v.x - mean, dx1 = v.y - mean, dx2 = v.z - mean, dx3 = v.w - mean;
    float s2 = wred(dx0 * dx0 + dx1 * dx1 + dx2 * dx2 + dx3 * dx3);
    __syncthreads();
    if ((t & 31) == 0) ws[t >> 5] = s2;
    __syncthreads();
    float var = (ws[0] + ws[1] + ws[2] + ws[3]) * (1.0f / 512.0f);
    float sc = rsqrtf(var + 1e-5f);
    float4 g = ((const float4*)gamma)[t];
    float4 bb = ((const float4*)beta)[t];
    v.x = dx0 * sc * g.x + bb.x;
    v.y = dx1 * sc * g.y + bb.y;
    v.z = dx2 * sc * g.z + bb.z;
    v.w = dx3 * sc * g.w + bb.w;
    p[t] = v;
}

// ---------------- launch ----------------
extern "C" void kernel_launch(void* const* d_in, const int* in_sizes, int n_in,
                              void* d_out, int out_size) {
    const float* src   = (const float*)d_in[0];   // [16,4096,512]
    const float* tgt   = (const float*)d_in[1];   // [16,32,512]
    const float* score = (const float*)d_in[2];   // [16,32,64,64]
    const float* W     = (const float*)d_in[3];   // [1024,512]
    const float* bias  = (const float*)d_in[4];   // [512]
    const float* gamma = (const float*)d_in[5];   // [512]
    const float* beta  = (const float*)d_in[6];   // [512]
    float* out = (float*)d_out;

    const size_t OUT_OT = (size_t)BB * NN * CC;   // out: 33554432 floats
    const size_t OUT_PI = OUT_OT + BB;            // then ot_loss[16], then pi
    float* out_ot = out + OUT_OT;
    float* out_pi = out + OUT_PI;

    k_init<<<128, 512>>>();
    k_nu_count<<<(BB * NN) / 256, 256>>>(score);
    k_nu_final<<<BB, MM>>>();
    k_ynorm<<<BB * MM, 128>>>(tgt);
    k_tw2<<<128, 256>>>(tgt, W);
    k_cost<<<dim3(NN / 16, BB), 512>>>(src);
    for (int it = 0; it <= 50; it++) k_sink_iter<<<128, 512>>>(it);
    k_sink_epi<<<128, 512>>>(out_pi);
    k_ot_final<<<1, 16>>>(out_ot);
    k_gemm<<<dim3(4, 512), 256>>>(src, W, bias, out);
    k_ln<<<BB * NN, 128>>>(out, gamma, beta);
}

// round 6
// speedup vs baseline: 1.0021x; 1.0021x over previous
#include <cuda_runtime.h>
#include <math.h>

#define BB 16
#define NN 4096
#define CC 512
#define MM 32
#define NB (BB*NN)          // 65536 rows total
#define EPS_INV 20.0f       // 1/0.05

// ---------------- scratch (device globals; no allocation) ----------------
__device__ float g_yn[BB*MM*CC];            // normalized targets      1 MB
__device__ float g_tw2[BB*MM*CC];           // target @ W2             1 MB
__device__ float g_nu[BB*MM];
__device__ int   g_counts[BB*MM];
__device__ float g_Kt[(size_t)MM*NB];       // Gibbs kernel, TRANSPOSED [m][row]  8 MB
__device__ float g_cost[(size_t)NB*MM];     // cost matrix, row-major  8 MB
__device__ float g_pinorm[(size_t)NB*MM];   // row-normalized pi       8 MB
__device__ float g_u[NB];                   // Sinkhorn u              256 KB
__device__ float g_v[BB*MM];                // Sinkhorn v
__device__ float g_vpart[2][128][32];       // per-block K^T u partials (parity)
__device__ float g_errpart[2][128];         // per-block err partials
__device__ float g_otpart[128];             // per-block ot partials
__device__ int   g_donestep;                // iteration at which Sinkhorn froze

__device__ __forceinline__ float wred(float v) {
#pragma unroll
    for (int o = 16; o; o >>= 1) v += __shfl_xor_sync(0xffffffffu, v, o);
    return v;
}

// ---------------- init ----------------
__global__ void k_init() {
    int t = blockIdx.x * blockDim.x + threadIdx.x;   // <<<128,512>>> covers 65536
    g_u[t] = 0.0f;
    if (t < BB * MM) g_counts[t] = 0;
    if (t == 0) g_donestep = 99;
}

// ---------------- nu: argmax counts over score_map ----------------
__global__ void k_nu_count(const float* __restrict__ score) {
    int idx = blockIdx.x * 256 + threadIdx.x;        // b*4096 + hw
    int b = idx >> 12, hw = idx & 4095;
    const float* p = score + (size_t)b * MM * NN + hw;
    float best = p[0];
    int bi = 0;
#pragma unroll
    for (int k = 1; k < MM; k++) {
        float v = p[(size_t)k * NN];
        if (v > best) { best = v; bi = k; }          // first-max, like jnp.argmax
    }
    atomicAdd(&g_counts[b * MM + bi], 1);
}

__global__ void k_nu_final() {
    int b = blockIdx.x, k = threadIdx.x;             // <<<16,32>>>
    float c = (float)g_counts[b * MM + k];
    float nu = c / (4096.0f + 1e-8f) + 1e-6f;
    float s = wred(nu);
    g_nu[b * MM + k] = nu / s;
}

// ---------------- normalize target rows ----------------
__global__ void k_ynorm(const float* __restrict__ tgt) {
    int row = blockIdx.x;                            // <<<512,128>>>
    const float4* p = (const float4*)(tgt + (size_t)row * CC);
    int t = threadIdx.x;
    float4 v = p[t];
    float s = wred(v.x * v.x + v.y * v.y + v.z * v.z + v.w * v.w);
    __shared__ float ws[4];
    if ((t & 31) == 0) ws[t >> 5] = s;
    __syncthreads();
    float inv = rsqrtf(ws[0] + ws[1] + ws[2] + ws[3]);
    ((float4*)(g_yn + (size_t)row * CC))[t] =
        make_float4(v.x * inv, v.y * inv, v.z * inv, v.w * inv);
}

// ---------------- TW2 = target @ W2  (W2 = fusion_w rows 512..1023) ----------------
__global__ void __launch_bounds__(256) k_tw2(const float* __restrict__ tgt,
                                             const float* __restrict__ W) {
    __shared__ float ts[32 * 128];                   // 16 KB tile
    int blk = blockIdx.x;                            // b*8 + ctile, <<<128,256>>>
    int b = blk >> 3, ct = blk & 7;
    int t = threadIdx.x;
    int c = ct * 64 + (t & 63);
    int mg = t >> 6;                                 // 0..3 -> 8 m's each
    float acc[8];
#pragma unroll
    for (int i = 0; i < 8; i++) acc[i] = 0.0f;
    for (int kt = 0; kt < 4; kt++) {
        __syncthreads();
        for (int i = t; i < 32 * 128 / 4; i += 256) {
            int m = i >> 5, k4 = i & 31;
            ((float4*)ts)[i] =
                ((const float4*)(tgt + ((size_t)(b * 32 + m)) * CC + kt * 128))[k4];
        }
        __syncthreads();
        const float* Wp = W + (size_t)(CC + kt * 128) * CC + c;
        for (int k = 0; k < 128; k++) {
            float w = Wp[(size_t)k * CC];
#pragma unroll
            for (int i = 0; i < 8; i++) acc[i] += ts[(mg * 8 + i) * 128 + k] * w;
        }
    }
#pragma unroll
    for (int i = 0; i < 8; i++)
        g_tw2[(size_t)b * MM * CC + (size_t)(mg * 8 + i) * CC + c] = acc[i];
}

// ---------------- cost / Gibbs kernel matrix ----------------
__global__ void __launch_bounds__(512) k_cost(const float* __restrict__ src) {
    int b = blockIdx.y;
    __shared__ float yns[32 * 256];                  // 32 KB tile (half of C)
    int t = threadIdx.x;
    int warp = t >> 5, lane = t & 31;
    int n = blockIdx.x * 16 + warp;
    const float4* xr = (const float4*)(src + ((size_t)(b * NN + n)) * CC);
    float4 x4[4];
#pragma unroll
    for (int i = 0; i < 4; i++) x4[i] = xr[lane + 32 * i];
    float nrm = 0.0f;
#pragma unroll
    for (int i = 0; i < 4; i++)
        nrm += x4[i].x * x4[i].x + x4[i].y * x4[i].y + x4[i].z * x4[i].z + x4[i].w * x4[i].w;
    nrm = wred(nrm);
    float inv = rsqrtf(nrm);
    float dacc[32];
#pragma unroll
    for (int m = 0; m < 32; m++) dacc[m] = 0.0f;
    for (int ct = 0; ct < 2; ct++) {
        __syncthreads();
        for (int i = t; i < 32 * 256 / 4; i += 512) {
            int m = i >> 6, k4 = i & 63;
            ((float4*)yns)[i] =
                ((const float4*)(g_yn + ((size_t)(b * 32 + m)) * CC + ct * 256))[k4];
        }
        __syncthreads();
#pragma unroll
        for (int m = 0; m < 32; m++) {
            const float4* y4 = (const float4*)(yns + m * 256);
#pragma unroll
            for (int i = 0; i < 2; i++) {
                float4 yv = y4[lane + 32 * i];
                float4 xv = x4[ct * 2 + i];
                dacc[m] += xv.x * yv.x + xv.y * yv.y + xv.z * yv.z + xv.w * yv.w;
            }
        }
    }
    float ccv = 0.0f, kkv = 0.0f;
#pragma unroll
    for (int m = 0; m < 32; m++) {
        float d = wred(dacc[m]);
        if (lane == m) { ccv = 1.0f - d * inv; kkv = expf(ccv * -EPS_INV); }
    }
    int row = b * NN + n;
    g_Kt[(size_t)lane * NB + row] = kkv;             // transposed for Sinkhorn
    g_cost[(size_t)row * MM + lane] = ccv;           // row-major for epilogue
}

// ---------------- Sinkhorn iteration (one launch per iteration) ----------------
// K_i (iter=i): computes v_{i-1} from partials_{i-1} (i>=1), checks err_{i-1};
// if converged -> record donestep=i, freeze. Else u_i update + partials_i.
// iter==50 is the final v-only step.
__global__ void __launch_bounds__(512) k_sink_iter(int iter) {
    if (iter > g_donestep) return;                   // set only by EARLIER kernels
    int g = blockIdx.x, b = g >> 3, t = threadIdx.x; // <<<128,512>>>
    int lane = t & 31, warp = t >> 5;
    __shared__ float sv[32];
    __shared__ float wsum[16][33], werr[16];
    __shared__ int sdone;
    if (iter == 0) {
        if (t < 32) sv[t] = 0.0f;                    // v_0 = 0
        if (t == 32) sdone = 0;
    } else {
        int q = (iter - 1) & 1;
        if (t < 32) {
            float a = 0.0f;
#pragma unroll
            for (int k = 0; k < 8; k++) a += g_vpart[q][(b << 3) + k][t];
            float v = g_nu[b * 32 + t] / (a + 1e-8f);
            sv[t] = v;
            g_v[b * 32 + t] = v;                     // identical across the 8 blocks of b
        }
        if (t == 32) {
            float e = 0.0f;
            for (int k = 0; k < 128; k++) e += g_errpart[q][k];
            sdone = (e * (1.0f / 16.0f) < 0.1f) ? 1 : 0;
        }
    }
    __syncthreads();
    if (sdone) { if (t == 0) g_donestep = iter; return; }
    if (iter >= 50) return;                          // v-only final step

    int row = g * 512 + t;                           // = b*NN + n
    float kk[32];
#pragma unroll
    for (int m = 0; m < 32; m++) kk[m] = g_Kt[(size_t)m * NB + row];  // coalesced
    float denom = 0.0f;
#pragma unroll
    for (int m = 0; m < 32; m++) denom += kk[m] * sv[m];
    const float mu = 1.0f / 4096.0f;
    float un = mu / (denom + 1e-8f);
    float du = fabsf(un - g_u[row]);
    g_u[row] = un;
#pragma unroll
    for (int m = 0; m < 32; m++) {
        float val = wred(kk[m] * un);
        if (lane == 0) wsum[warp][m] = val;
    }
    du = wred(du);
    if (lane == 0) werr[warp] = du;
    __syncthreads();
    int p = iter & 1;
    if (t < 32) {
        float a = 0.0f;
#pragma unroll
        for (int w = 0; w < 16; w++) a += wsum[w][t];
        g_vpart[p][g][t] = a;
    } else if (t == 32) {
        float e = 0.0f;
#pragma unroll
        for (int w = 0; w < 16; w++) e += werr[w];
        g_errpart[p][g] = e;
    }
}

// ---------------- Sinkhorn epilogue: pi, pi_norm, ot partials ----------------
__global__ void __launch_bounds__(512) k_sink_epi(float* __restrict__ out_pi) {
    int g = blockIdx.x, b = g >> 3, t = threadIdx.x; // <<<128,512>>>
    int lane = t & 31, warp = t >> 5;
    __shared__ float sv[32], werr[16];
    if (t < 32) sv[t] = g_v[b * 32 + t];
    __syncthreads();
    int row = g * 512 + t;
    float u = g_u[row];
    float kk[32];
#pragma unroll
    for (int m = 0; m < 32; m++) kk[m] = g_Kt[(size_t)m * NB + row];
    float pi[32];
    float rs = 0.0f;
#pragma unroll
    for (int m = 0; m < 32; m++) { pi[m] = u * kk[m] * sv[m]; rs += pi[m]; }
    size_t rowbase = (size_t)row * MM;
    float* po = out_pi + rowbase;
#pragma unroll
    for (int m = 0; m < 32; m += 4)
        *(float4*)(po + m) = make_float4(pi[m], pi[m + 1], pi[m + 2], pi[m + 3]);
    float inv = 1.0f / (rs + 1e-8f);
#pragma unroll
    for (int m = 0; m < 32; m += 4)
        *(float4*)(g_pinorm + rowbase + m) =
            make_float4(pi[m] * inv, pi[m + 1] * inv, pi[m + 2] * inv, pi[m + 3] * inv);
    float oc = 0.0f;
#pragma unroll
    for (int m = 0; m < 32; m += 4) {
        float4 cq = *(const float4*)(g_cost + rowbase + m);
        oc += pi[m] * cq.x + pi[m + 1] * cq.y + pi[m + 2] * cq.z + pi[m + 3] * cq.w;
    }
    oc = wred(oc);
    if (lane == 0) werr[warp] = oc;
    __syncthreads();
    if (t == 0) {
        float e = 0.0f;
#pragma unroll
        for (int w = 0; w < 16; w++) e += werr[w];
        g_otpart[g] = e;                             // deterministic partial
    }
}

__global__ void k_ot_final(float* __restrict__ out_ot) {
    int b = threadIdx.x;                             // <<<1,16>>>
    float e = 0.0f;
#pragma unroll
    for (int k = 0; k < 8; k++) e += g_otpart[b * 8 + k];
    out_ot[b] = e;
}

// ---------------- fused GEMM: out = src@W1 + pinorm@TW2[b] + bias ----------------
// 128x128 block, 8x8 microtile, 256 threads.
__global__ void __launch_bounds__(256) k_gemm(const float* __restrict__ src,
                                              const float* __restrict__ W,
                                              const float* __restrict__ bias,
                                              float* __restrict__ out) {
    __shared__ float As[16][132];                    // padded (store conflicts ~2-way)
    __shared__ float Bs[16][128];
    int r0 = blockIdx.y * 128, c0 = blockIdx.x * 128;
    int b = r0 >> 12;
    int t = threadIdx.x;
    int tx = t & 15, ty = t >> 4;                    // 16x16 thread grid
    float acc[8][8];
#pragma unroll
    for (int i = 0; i < 8; i++)
#pragma unroll
        for (int j = 0; j < 8; j++) acc[i][j] = 0.0f;

    for (int kt = 0; kt < 34; kt++) {
        int k0 = kt * 16;
        if (k0 < CC) {
#pragma unroll
            for (int j = 0; j < 8; j++) {
                int e = t + j * 256;
                int row = e >> 4, kk = e & 15;
                As[kk][row] = src[(size_t)(r0 + row) * CC + k0 + kk];
            }
#pragma unroll
            for (int j = 0; j < 8; j++) {
                int e = t + j * 256;
                int kk = e >> 7, col = e & 127;
                Bs[kk][col] = W[(size_t)(k0 + kk) * CC + c0 + col];
            }
        } else {
            int kp = k0 - CC;
#pragma unroll
            for (int j = 0; j < 8; j++) {
                int e = t + j * 256;
                int row = e >> 4, kk = e & 15;
                As[kk][row] = g_pinorm[(size_t)(r0 + row) * MM + kp + kk];
            }
#pragma unroll
            for (int j = 0; j < 8; j++) {
                int e = t + j * 256;
                int kk = e >> 7, col = e & 127;
                Bs[kk][col] = g_tw2[(size_t)b * MM * CC + (size_t)(kp + kk) * CC + c0 + col];
            }
        }
        __syncthreads();
#pragma unroll
        for (int k = 0; k < 16; k++) {
            float a[8], bv[8];
            *(float4*)&a[0] = *(float4*)&As[k][ty * 8];
            *(float4*)&a[4] = *(float4*)&As[k][ty * 8 + 4];
            *(float4*)&bv[0] = *(float4*)&Bs[k][tx * 8];
            *(float4*)&bv[4] = *(float4*)&Bs[k][tx * 8 + 4];
#pragma unroll
            for (int i = 0; i < 8; i++)
#pragma unroll
                for (int j = 0; j < 8; j++) acc[i][j] += a[i] * bv[j];
        }
        __syncthreads();
    }
    float bi[8];
    *(float4*)&bi[0] = *(const float4*)(bias + c0 + tx * 8);
    *(float4*)&bi[4] = *(const float4*)(bias + c0 + tx * 8 + 4);
#pragma unroll
    for (int i = 0; i < 8; i++) {
        int r = r0 + ty * 8 + i;
        float* op = out + (size_t)r * CC + c0 + tx * 8;
        *(float4*)op = make_float4(acc[i][0] + bi[0], acc[i][1] + bi[1],
                                   acc[i][2] + bi[2], acc[i][3] + bi[3]);
        *(float4*)(op + 4) = make_float4(acc[i][4] + bi[4], acc[i][5] + bi[5],
                                         acc[i][6] + bi[6], acc[i][7] + bi[7]);
    }
}

// ---------------- LayerNorm, in-place on d_out ----------------
__global__ void k_ln(float* __restrict__ out,
                     const float* __restrict__ gamma,
                     const float* __restrict__ beta) {
    int row = blockIdx.x;                            // <<<65536,128>>>
    float4* p = (float4*)(out + (size_t)row * CC);
    int t = threadIdx.x;
    float4 v = p[t];
    __shared__ float ws[4];
    float s = wred(v.x + v.y + v.z + v.w);
    if ((t & 31) == 0) ws[t >> 5] = s;
    __syncthreads();
    float mean = (ws[0] + ws[1] + ws[2] + ws[3]) * (1.0f / 512.0f);
    float dx0 = v.x - mean, dx1 = v.y - mean, dx2 = v.z - mean, dx3 = v.w - mean;
    float s2 = wred(dx0 * dx0 + dx1 * dx1 + dx2 * dx2 + dx3 * dx3);
    __syncthreads();
    if ((t & 31) == 0) ws[t >> 5] = s2;
    __syncthreads();
    float var = (ws[0] + ws[1] + ws[2] + ws[3]) * (1.0f / 512.0f);
    float sc = rsqrtf(var + 1e-5f);
    float4 g = ((const float4*)gamma)[t];
    float4 bb = ((const float4*)beta)[t];
    v.x = dx0 * sc * g.x + bb.x;
    v.y = dx1 * sc * g.y + bb.y;
    v.z = dx2 * sc * g.z + bb.z;
    v.w = dx3 * sc * g.w + bb.w;
    p[t] = v;
}

// ---------------- launch ----------------
extern "C" void kernel_launch(void* const* d_in, const int* in_sizes, int n_in,
                              void* d_out, int out_size) {
    const float* src   = (const float*)d_in[0];   // [16,4096,512]
    const float* tgt   = (const float*)d_in[1];   // [16,32,512]
    const float* score = (const float*)d_in[2];   // [16,32,64,64]
    const float* W     = (const float*)d_in[3];   // [1024,512]
    const float* bias  = (const float*)d_in[4];   // [512]
    const float* gamma = (const float*)d_in[5];   // [512]
    const float* beta  = (const float*)d_in[6];   // [512]
    float* out = (float*)d_out;

    const size_t OUT_OT = (size_t)BB * NN * CC;   // out: 33554432 floats
    const size_t OUT_PI = OUT_OT + BB;            // then ot_loss[16], then pi
    float* out_ot = out + OUT_OT;
    float* out_pi = out + OUT_PI;

    k_init<<<128, 512>>>();
    k_nu_count<<<(BB * NN) / 256, 256>>>(score);
    k_nu_final<<<BB, MM>>>();
    k_ynorm<<<BB * MM, 128>>>(tgt);
    k_tw2<<<128, 256>>>(tgt, W);
    k_cost<<<dim3(NN / 16, BB), 512>>>(src);
    for (int it = 0; it <= 50; it++) k_sink_iter<<<128, 512>>>(it);
    k_sink_epi<<<128, 512>>>(out_pi);
    k_ot_final<<<1, 16>>>(out_ot);
    k_gemm<<<dim3(4, 512), 256>>>(src, W, bias, out);
    k_ln<<<BB * NN, 128>>>(out, gamma, beta);
}

// round 8
// speedup vs baseline: 1.3899x; 1.3870x over previous
#include <cuda_runtime.h>
#include <cuda_bf16.h>
#include <math.h>
#include <stdint.h>

#define BB 16
#define NN 4096
#define CC 512
#define MM 32
#define NB (BB*NN)
#define EPS_INV 20.0f

// ---------------- scratch (device globals; no allocation) ----------------
__device__ float g_yn[BB*MM*CC];
__device__ float g_tw2[BB*MM*CC];
__device__ float g_nu[BB*MM];
__device__ int   g_counts[BB*MM];
__device__ float g_Kt[(size_t)MM*NB];       // Gibbs kernel transposed [m][row]
__device__ float g_cost[(size_t)NB*MM];     // cost row-major
__device__ float g_pinorm[(size_t)NB*MM];
__device__ float g_u[NB];
__device__ float g_v[BB*MM];
__device__ float g_vpart[2][128][32];
__device__ float g_errpart[2][128];
__device__ float g_otpart[128];
__device__ int   g_donestep;
// bf16 hi/lo images of W1^T ([n][k], k contiguous, 512x512) and TW2^T ([b][n][k], 512x32)
__device__ uint4 g_WH4[32768], g_WL4[32768];
__device__ uint4 g_TH4[32768], g_TL4[32768];

__device__ __forceinline__ float wred(float v) {
#pragma unroll
    for (int o = 16; o; o >>= 1) v += __shfl_xor_sync(0xffffffffu, v, o);
    return v;
}
__device__ __forceinline__ uint32_t smem_u32(const void* p) {
    uint32_t a;
    asm("{ .reg .u64 t; cvta.to.shared.u64 t, %1; cvt.u32.u64 %0, t; }" : "=r"(a) : "l"(p));
    return a;
}
// split fp32 float4 -> 4 bf16 hi + 4 bf16 lo, stored at ushort offset `off`
__device__ __forceinline__ void split4(ushort* hb, ushort* lb, int off, float4 v) {
    __nv_bfloat16 hx = __float2bfloat16(v.x), hy = __float2bfloat16(v.y),
                  hz = __float2bfloat16(v.z), hw = __float2bfloat16(v.w);
    unsigned h0 = ((unsigned)__bfloat16_as_ushort(hy) << 16) | __bfloat16_as_ushort(hx);
    unsigned h1 = ((unsigned)__bfloat16_as_ushort(hw) << 16) | __bfloat16_as_ushort(hz);
    __nv_bfloat16 ax = __float2bfloat16(v.x - __bfloat162float(hx));
    __nv_bfloat16 ay = __float2bfloat16(v.y - __bfloat162float(hy));
    __nv_bfloat16 az = __float2bfloat16(v.z - __bfloat162float(hz));
    __nv_bfloat16 aw = __float2bfloat16(v.w - __bfloat162float(hw));
    unsigned l0 = ((unsigned)__bfloat16_as_ushort(ay) << 16) | __bfloat16_as_ushort(ax);
    unsigned l1 = ((unsigned)__bfloat16_as_ushort(aw) << 16) | __bfloat16_as_ushort(az);
    *(uint2*)(hb + off) = make_uint2(h0, h1);
    *(uint2*)(lb + off) = make_uint2(l0, l1);
}
#define LDSM4(r, a)                                                                      \
    asm volatile("ldmatrix.sync.aligned.m8n8.x4.shared.b16 {%0,%1,%2,%3}, [%4];"         \
        : "=r"((r)[0]), "=r"((r)[1]), "=r"((r)[2]), "=r"((r)[3]) : "r"(a))
#define MMA16816(d, a, b0, b1)                                                           \
    asm volatile("mma.sync.aligned.m16n8k16.row.col.f32.bf16.bf16.f32 "                  \
        "{%0,%1,%2,%3}, {%4,%5,%6,%7}, {%8,%9}, {%0,%1,%2,%3};"                          \
        : "+f"((d)[0]), "+f"((d)[1]), "+f"((d)[2]), "+f"((d)[3])                         \
        : "r"((a)[0]), "r"((a)[1]), "r"((a)[2]), "r"((a)[3]), "r"(b0), "r"(b1))

// ---------------- init ----------------
__global__ void k_init() {
    int t = blockIdx.x * blockDim.x + threadIdx.x;   // <<<128,512>>>
    g_u[t] = 0.0f;
    if (t < BB * MM) g_counts[t] = 0;
    if (t == 0) g_donestep = 99;
}

// ---------------- nu ----------------
__global__ void k_nu_count(const float* __restrict__ score) {
    int idx = blockIdx.x * 256 + threadIdx.x;
    int b = idx >> 12, hw = idx & 4095;
    const float* p = score + (size_t)b * MM * NN + hw;
    float best = p[0]; int bi = 0;
#pragma unroll
    for (int k = 1; k < MM; k++) {
        float v = p[(size_t)k * NN];
        if (v > best) { best = v; bi = k; }
    }
    atomicAdd(&g_counts[b * MM + bi], 1);
}

__global__ void k_nu_final() {
    int b = blockIdx.x, k = threadIdx.x;             // <<<16,32>>>
    float c = (float)g_counts[b * MM + k];
    float nu = c / (4096.0f + 1e-8f) + 1e-6f;
    float s = wred(nu);
    g_nu[b * MM + k] = nu / s;
}

// ---------------- normalize target rows ----------------
__global__ void k_ynorm(const float* __restrict__ tgt) {
    int row = blockIdx.x;                            // <<<512,128>>>
    const float4* p = (const float4*)(tgt + (size_t)row * CC);
    int t = threadIdx.x;
    float4 v = p[t];
    float s = wred(v.x * v.x + v.y * v.y + v.z * v.z + v.w * v.w);
    __shared__ float ws[4];
    if ((t & 31) == 0) ws[t >> 5] = s;
    __syncthreads();
    float inv = rsqrtf(ws[0] + ws[1] + ws[2] + ws[3]);
    ((float4*)(g_yn + (size_t)row * CC))[t] =
        make_float4(v.x * inv, v.y * inv, v.z * inv, v.w * inv);
}

// ---------------- TW2 = target @ W2 ----------------
__global__ void __launch_bounds__(256) k_tw2(const float* __restrict__ tgt,
                                             const float* __restrict__ W) {
    __shared__ float ts[32 * 128];
    int blk = blockIdx.x;                            // <<<128,256>>>
    int b = blk >> 3, ct = blk & 7;
    int t = threadIdx.x;
    int c = ct * 64 + (t & 63);
    int mg = t >> 6;
    float acc[8];
#pragma unroll
    for (int i = 0; i < 8; i++) acc[i] = 0.0f;
    for (int kt = 0; kt < 4; kt++) {
        __syncthreads();
        for (int i = t; i < 32 * 128 / 4; i += 256) {
            int m = i >> 5, k4 = i & 31;
            ((float4*)ts)[i] = ((const float4*)(tgt + ((size_t)(b * 32 + m)) * CC + kt * 128))[k4];
        }
        __syncthreads();
        const float* Wp = W + (size_t)(CC + kt * 128) * CC + c;
        for (int k = 0; k < 128; k++) {
            float w = Wp[(size_t)k * CC];
#pragma unroll
            for (int i = 0; i < 8; i++) acc[i] += ts[(mg * 8 + i) * 128 + k] * w;
        }
    }
#pragma unroll
    for (int i = 0; i < 8; i++)
        g_tw2[(size_t)b * MM * CC + (size_t)(mg * 8 + i) * CC + c] = acc[i];
}

// ---------------- prep bf16 hi/lo images of W1^T and TW2^T ----------------
__global__ void k_prep_w(const float* __restrict__ W) {
    int idx = blockIdx.x * 256 + threadIdx.x;        // <<<256,256>>> = 512n x 128kq
    int n = idx & 511, kq = idx >> 9;
    int k0 = kq * 4;
    float4 v = make_float4(W[(size_t)k0 * CC + n], W[(size_t)(k0 + 1) * CC + n],
                           W[(size_t)(k0 + 2) * CC + n], W[(size_t)(k0 + 3) * CC + n]);
    split4((ushort*)g_WH4, (ushort*)g_WL4, n * 512 + k0, v);
}
__global__ void k_prep_tail() {
    int idx = blockIdx.x * 256 + threadIdx.x;        // <<<256,256>>> = 16b x 512n x 8kq
    int b = idx >> 12, rem = idx & 4095;
    int n = rem & 511, k0 = ((rem >> 9) & 7) * 4;
    const float* tp = g_tw2 + (size_t)b * MM * CC;
    float4 v = make_float4(tp[(size_t)k0 * CC + n], tp[(size_t)(k0 + 1) * CC + n],
                           tp[(size_t)(k0 + 2) * CC + n], tp[(size_t)(k0 + 3) * CC + n]);
    split4((ushort*)g_TH4, (ushort*)g_TL4, b * 16384 + n * 32 + k0, v);
}

// ---------------- cost / Gibbs matrix (fp32, validated) ----------------
__global__ void __launch_bounds__(512) k_cost(const float* __restrict__ src) {
    int b = blockIdx.y;
    __shared__ float yns[32 * 256];
    int t = threadIdx.x;
    int warp = t >> 5, lane = t & 31;
    int n = blockIdx.x * 16 + warp;
    const float4* xr = (const float4*)(src + ((size_t)(b * NN + n)) * CC);
    float4 x4[4];
#pragma unroll
    for (int i = 0; i < 4; i++) x4[i] = xr[lane + 32 * i];
    float nrm = 0.0f;
#pragma unroll
    for (int i = 0; i < 4; i++)
        nrm += x4[i].x * x4[i].x + x4[i].y * x4[i].y + x4[i].z * x4[i].z + x4[i].w * x4[i].w;
    nrm = wred(nrm);
    float inv = rsqrtf(nrm);
    float dacc[32];
#pragma unroll
    for (int m = 0; m < 32; m++) dacc[m] = 0.0f;
    for (int ct = 0; ct < 2; ct++) {
        __syncthreads();
        for (int i = t; i < 32 * 256 / 4; i += 512) {
            int m = i >> 6, k4 = i & 63;
            ((float4*)yns)[i] = ((const float4*)(g_yn + ((size_t)(b * 32 + m)) * CC + ct * 256))[k4];
        }
        __syncthreads();
#pragma unroll
        for (int m = 0; m < 32; m++) {
            const float4* y4 = (const float4*)(yns + m * 256);
#pragma unroll
            for (int i = 0; i < 2; i++) {
                float4 yv = y4[lane + 32 * i];
                float4 xv = x4[ct * 2 + i];
                dacc[m] += xv.x * yv.x + xv.y * yv.y + xv.z * yv.z + xv.w * yv.w;
            }
        }
    }
    float ccv = 0.0f, kkv = 0.0f;
#pragma unroll
    for (int m = 0; m < 32; m++) {
        float d = wred(dacc[m]);
        if (lane == m) { ccv = 1.0f - d * inv; kkv = expf(ccv * -EPS_INV); }
    }
    int row = b * NN + n;
    g_Kt[(size_t)lane * NB + row] = kkv;
    g_cost[(size_t)row * MM + lane] = ccv;
}

// ---------------- Sinkhorn (validated) ----------------
__global__ void __launch_bounds__(512) k_sink_iter(int iter) {
    if (iter > g_donestep) return;
    int g = blockIdx.x, b = g >> 3, t = threadIdx.x; // <<<128,512>>>
    int lane = t & 31, warp = t >> 5;
    __shared__ float sv[32];
    __shared__ float wsum[16][33], werr[16];
    __shared__ int sdone;
    if (iter == 0) {
        if (t < 32) sv[t] = 0.0f;
        if (t == 32) sdone = 0;
    } else {
        int q = (iter - 1) & 1;
        if (t < 32) {
            float a = 0.0f;
#pragma unroll
            for (int k = 0; k < 8; k++) a += g_vpart[q][(b << 3) + k][t];
            float v = g_nu[b * 32 + t] / (a + 1e-8f);
            sv[t] = v;
            g_v[b * 32 + t] = v;
        }
        if (t == 32) {
            float e = 0.0f;
            for (int k = 0; k < 128; k++) e += g_errpart[q][k];
            sdone = (e * (1.0f / 16.0f) < 0.1f) ? 1 : 0;
        }
    }
    __syncthreads();
    if (sdone) { if (t == 0) g_donestep = iter; return; }
    if (iter >= 50) return;

    int row = g * 512 + t;
    float kk[32];
#pragma unroll
    for (int m = 0; m < 32; m++) kk[m] = g_Kt[(size_t)m * NB + row];
    float denom = 0.0f;
#pragma unroll
    for (int m = 0; m < 32; m++) denom += kk[m] * sv[m];
    float un = (1.0f / 4096.0f) / (denom + 1e-8f);
    float du = fabsf(un - g_u[row]);
    g_u[row] = un;
#pragma unroll
    for (int m = 0; m < 32; m++) {
        float val = wred(kk[m] * un);
        if (lane == 0) wsum[warp][m] = val;
    }
    du = wred(du);
    if (lane == 0) werr[warp] = du;
    __syncthreads();
    int p = iter & 1;
    if (t < 32) {
        float a = 0.0f;
#pragma unroll
        for (int w = 0; w < 16; w++) a += wsum[w][t];
        g_vpart[p][g][t] = a;
    } else if (t == 32) {
        float e = 0.0f;
#pragma unroll
        for (int w = 0; w < 16; w++) e += werr[w];
        g_errpart[p][g] = e;
    }
}

__global__ void __launch_bounds__(512) k_sink_epi(float* __restrict__ out_pi) {
    int g = blockIdx.x, b = g >> 3, t = threadIdx.x; // <<<128,512>>>
    int lane = t & 31, warp = t >> 5;
    __shared__ float sv[32], werr[16];
    if (t < 32) sv[t] = g_v[b * 32 + t];
    __syncthreads();
    int row = g * 512 + t;
    float u = g_u[row];
    float kk[32], pi[32];
#pragma unroll
    for (int m = 0; m < 32; m++) kk[m] = g_Kt[(size_t)m * NB + row];
    float rs = 0.0f;
#pragma unroll
    for (int m = 0; m < 32; m++) { pi[m] = u * kk[m] * sv[m]; rs += pi[m]; }
    size_t rowbase = (size_t)row * MM;
#pragma unroll
    for (int m = 0; m < 32; m += 4)
        *(float4*)(out_pi + rowbase + m) = make_float4(pi[m], pi[m + 1], pi[m + 2], pi[m + 3]);
    float inv = 1.0f / (rs + 1e-8f);
#pragma unroll
    for (int m = 0; m < 32; m += 4)
        *(float4*)(g_pinorm + rowbase + m) =
            make_float4(pi[m] * inv, pi[m + 1] * inv, pi[m + 2] * inv, pi[m + 3] * inv);
    float oc = 0.0f;
#pragma unroll
    for (int m = 0; m < 32; m += 4) {
        float4 cq = *(const float4*)(g_cost + rowbase + m);
        oc += pi[m] * cq.x + pi[m + 1] * cq.y + pi[m + 2] * cq.z + pi[m + 3] * cq.w;
    }
    oc = wred(oc);
    if (lane == 0) werr[warp] = oc;
    __syncthreads();
    if (t == 0) {
        float e = 0.0f;
#pragma unroll
        for (int w = 0; w < 16; w++) e += werr[w];
        g_otpart[g] = e;
    }
}

__global__ void k_ot_final(float* __restrict__ out_ot) {
    int b = threadIdx.x;                             // <<<1,16>>>
    float e = 0.0f;
#pragma unroll
    for (int k = 0; k < 8; k++) e += g_otpart[b * 8 + k];
    out_ot[b] = e;
}

// ---------------- HMMA fused GEMM: out = [src|pinorm] @ [W1;TW2_b] + bias ----------------
// CTA 128x128, 8 warps (4m x 2n), warp tile 32x64, K chunks of 32 (17 chunks).
// 3-pass bf16 split: hi*hi + hi*lo + lo*hi, fp32 accum. Padded smem stride 40 (conflict-free).
__global__ void __launch_bounds__(256) k_gemm_hmma(const float* __restrict__ src,
                                                   const float* __restrict__ bias,
                                                   float* __restrict__ out) {
    __shared__ uint4 sAh4[640], sAl4[640], sBh4[640], sBl4[640];   // 128 x 40 ushort each
    ushort* Ah = (ushort*)sAh4; ushort* Al = (ushort*)sAl4;
    ushort* Bh = (ushort*)sBh4; ushort* Bl = (ushort*)sBl4;
    int t = threadIdx.x, lane = t & 31, w = t >> 5;
    int r0 = blockIdx.y * 128, c0 = blockIdx.x * 128;
    int b = r0 >> 12;
    int wm = (w & 3) * 32, wn = (w >> 2) * 64;

    float acc[2][8][4];
#pragma unroll
    for (int i = 0; i < 2; i++)
#pragma unroll
        for (int j = 0; j < 8; j++)
#pragma unroll
            for (int q = 0; q < 4; q++) acc[i][j][q] = 0.0f;

    // ldmatrix per-thread address components
    int arow = lane & 15, ak = (lane >> 4) * 8;
    int brow = (lane & 7) + ((lane >> 4) & 1) * 8, bk = ((lane >> 3) & 1) * 8;

    for (int c = 0; c < 17; c++) {
        __syncthreads();
        // ---- A tile: fp32 -> bf16 hi/lo ----
        if (c < 16) {
            const float* Ap = src + (size_t)r0 * CC + c * 32;
#pragma unroll
            for (int j = 0; j < 4; j++) {
                int e = t + j * 256;
                int row = e >> 3, kq = e & 7;
                float4 v = *(const float4*)(Ap + (size_t)row * CC + kq * 4);
                split4(Ah, Al, row * 40 + kq * 4, v);
            }
        } else {
            const float* Ap = g_pinorm + (size_t)r0 * MM;
#pragma unroll
            for (int j = 0; j < 4; j++) {
                int e = t + j * 256;
                int row = e >> 3, kq = e & 7;
                float4 v = *(const float4*)(Ap + (size_t)row * MM + kq * 4);
                split4(Ah, Al, row * 40 + kq * 4, v);
            }
        }
        // ---- B tile: copy pre-split images ----
        {
            const ushort* bh; const ushort* bl; int stride;
            if (c < 16) {
                bh = (const ushort*)g_WH4 + (size_t)c0 * 512 + c * 32;
                bl = (const ushort*)g_WL4 + (size_t)c0 * 512 + c * 32;
                stride = 512;
            } else {
                bh = (const ushort*)g_TH4 + (size_t)b * 16384 + (size_t)c0 * 32;
                bl = (const ushort*)g_TL4 + (size_t)b * 16384 + (size_t)c0 * 32;
                stride = 32;
            }
#pragma unroll
            for (int j = 0; j < 2; j++) {
                int e = t + j * 256;
                int row = e >> 2, q = e & 3;
                ((uint4*)Bh)[row * 5 + q] = *(const uint4*)(bh + (size_t)row * stride + q * 8);
                ((uint4*)Bl)[row * 5 + q] = *(const uint4*)(bl + (size_t)row * stride + q * 8);
            }
        }
        __syncthreads();
        // ---- MMA: 2 k16 steps x 3 passes ----
#pragma unroll
        for (int ks = 0; ks < 2; ks++) {
            int k_off = ks * 16;
#pragma unroll
            for (int pass = 0; pass < 3; pass++) {
                ushort* Asel = (pass == 2) ? Al : Ah;
                ushort* Bsel = (pass == 1) ? Bl : Bh;
                uint32_t a[2][4];
#pragma unroll
                for (int mi = 0; mi < 2; mi++) {
                    uint32_t ad = smem_u32(Asel + (wm + mi * 16 + arow) * 40 + k_off + ak);
                    LDSM4(a[mi], ad);
                }
                uint32_t bb[4][4];
#pragma unroll
                for (int nj2 = 0; nj2 < 4; nj2++) {
                    uint32_t bd = smem_u32(Bsel + (wn + nj2 * 16 + brow) * 40 + k_off + bk);
                    LDSM4(bb[nj2], bd);
                }
#pragma unroll
                for (int mi = 0; mi < 2; mi++)
#pragma unroll
                    for (int nj2 = 0; nj2 < 4; nj2++) {
                        MMA16816(acc[mi][nj2 * 2],     a[mi], bb[nj2][0], bb[nj2][1]);
                        MMA16816(acc[mi][nj2 * 2 + 1], a[mi], bb[nj2][2], bb[nj2][3]);
                    }
            }
        }
    }
    // ---- epilogue: +bias, store ----
    int g4 = lane >> 2, l2 = (lane & 3) * 2;
#pragma unroll
    for (int mi = 0; mi < 2; mi++)
#pragma unroll
        for (int nj = 0; nj < 8; nj++) {
            int rr = r0 + wm + mi * 16 + g4;
            int cc = c0 + wn + nj * 8 + l2;
            float2 bi = *(const float2*)(bias + cc);
            *(float2*)(out + (size_t)rr * CC + cc) =
                make_float2(acc[mi][nj][0] + bi.x, acc[mi][nj][1] + bi.y);
            *(float2*)(out + (size_t)(rr + 8) * CC + cc) =
                make_float2(acc[mi][nj][2] + bi.x, acc[mi][nj][3] + bi.y);
        }
}

// ---------------- LayerNorm, in-place ----------------
__global__ void k_ln(float* __restrict__ out,
                     const float* __restrict__ gamma,
                     const float* __restrict__ beta) {
    int row = blockIdx.x;                            // <<<65536,128>>>
    float4* p = (float4*)(out + (size_t)row * CC);
    int t = threadIdx.x;
    float4 v = p[t];
    __shared__ float ws[4];
    float s = wred(v.x + v.y + v.z + v.w);
    if ((t & 31) == 0) ws[t >> 5] = s;
    __syncthreads();
    float mean = (ws[0] + ws[1] + ws[2] + ws[3]) * (1.0f / 512.0f);
    float dx0 = v.x - mean, dx1 = v.y - mean, dx2 = v.z - mean, dx3 = v.w - mean;
    float s2 = wred(dx0 * dx0 + dx1 * dx1 + dx2 * dx2 + dx3 * dx3);
    __syncthreads();
    if ((t & 31) == 0) ws[t >> 5] = s2;
    __syncthreads();
    float var = (ws[0] + ws[1] + ws[2] + ws[3]) * (1.0f / 512.0f);
    float sc = rsqrtf(var + 1e-5f);
    float4 g = ((const float4*)gamma)[t];
    float4 bb = ((const float4*)beta)[t];
    v.x = dx0 * sc * g.x + bb.x;
    v.y = dx1 * sc * g.y + bb.y;
    v.z = dx2 * sc * g.z + bb.z;
    v.w = dx3 * sc * g.w + bb.w;
    p[t] = v;
}

// ---------------- launch ----------------
extern "C" void kernel_launch(void* const* d_in, const int* in_sizes, int n_in,
                              void* d_out, int out_size) {
    const float* src   = (const float*)d_in[0];
    const float* tgt   = (const float*)d_in[1];
    const float* score = (const float*)d_in[2];
    const float* W     = (const float*)d_in[3];
    const float* bias  = (const float*)d_in[4];
    const float* gamma = (const float*)d_in[5];
    const float* beta  = (const float*)d_in[6];
    float* out = (float*)d_out;

    const size_t OUT_OT = (size_t)BB * NN * CC;
    float* out_ot = out + OUT_OT;
    float* out_pi = out + OUT_OT + BB;

    k_init<<<128, 512>>>();
    k_nu_count<<<(BB * NN) / 256, 256>>>(score);
    k_nu_final<<<BB, MM>>>();
    k_ynorm<<<BB * MM, 128>>>(tgt);
    k_tw2<<<128, 256>>>(tgt, W);
    k_prep_w<<<256, 256>>>(W);
    k_prep_tail<<<256, 256>>>();
    k_cost<<<dim3(NN / 16, BB), 512>>>(src);
    for (int it = 0; it <= 50; it++) k_sink_iter<<<128, 512>>>(it);
    k_sink_epi<<<128, 512>>>(out_pi);
    k_ot_final<<<1, 16>>>(out_ot);
    k_gemm_hmma<<<dim3(4, 512), 256>>>(src, bias, out);
    k_ln<<<BB * NN, 128>>>(out, gamma, beta);
}

// round 9
// speedup vs baseline: 1.9892x; 1.4311x over previous
#include <cuda_runtime.h>
#include <cuda_bf16.h>
#include <math.h>
#include <stdint.h>

#define BB 16
#define NN 4096
#define CC 512
#define MM 32
#define NB (BB*NN)
#define EPS_INV 20.0f

// ---------------- scratch (device globals; no allocation) ----------------
__device__ float g_tw2[BB*MM*CC];
__device__ float g_nu[BB*MM];
__device__ int   g_counts[BB*MM];
__device__ float g_Kt[(size_t)MM*NB];       // Gibbs kernel transposed [m][row]
__device__ float g_cost[(size_t)NB*MM];     // cost row-major
__device__ float g_pinorm[(size_t)NB*MM];
__device__ float g_u[NB];
__device__ float g_v[BB*MM];
__device__ float g_vpart[2][128][32];
__device__ float g_errpart[2][128];
__device__ float g_otpart[128];
__device__ int   g_donestep;
// bf16 hi/lo images: W1^T [n][k] 512x512, TW2^T [b][n][k] 512x32, yn [b][m][k] 32x512
__device__ uint4 g_WH4[32768], g_WL4[32768];
__device__ uint4 g_TH4[32768], g_TL4[32768];
__device__ uint4 g_YH4[32768], g_YL4[32768];

__device__ __forceinline__ float wred(float v) {
#pragma unroll
    for (int o = 16; o; o >>= 1) v += __shfl_xor_sync(0xffffffffu, v, o);
    return v;
}
__device__ __forceinline__ uint32_t smem_u32(const void* p) {
    uint32_t a;
    asm("{ .reg .u64 t; cvta.to.shared.u64 t, %1; cvt.u32.u64 %0, t; }" : "=r"(a) : "l"(p));
    return a;
}
__device__ __forceinline__ void split4(ushort* hb, ushort* lb, int off, float4 v) {
    __nv_bfloat16 hx = __float2bfloat16(v.x), hy = __float2bfloat16(v.y),
                  hz = __float2bfloat16(v.z), hw = __float2bfloat16(v.w);
    unsigned h0 = ((unsigned)__bfloat16_as_ushort(hy) << 16) | __bfloat16_as_ushort(hx);
    unsigned h1 = ((unsigned)__bfloat16_as_ushort(hw) << 16) | __bfloat16_as_ushort(hz);
    __nv_bfloat16 ax = __float2bfloat16(v.x - __bfloat162float(hx));
    __nv_bfloat16 ay = __float2bfloat16(v.y - __bfloat162float(hy));
    __nv_bfloat16 az = __float2bfloat16(v.z - __bfloat162float(hz));
    __nv_bfloat16 aw = __float2bfloat16(v.w - __bfloat162float(hw));
    unsigned l0 = ((unsigned)__bfloat16_as_ushort(ay) << 16) | __bfloat16_as_ushort(ax);
    unsigned l1 = ((unsigned)__bfloat16_as_ushort(aw) << 16) | __bfloat16_as_ushort(az);
    *(uint2*)(hb + off) = make_uint2(h0, h1);
    *(uint2*)(lb + off) = make_uint2(l0, l1);
}
#define LDSM4(r, a)                                                                      \
    asm volatile("ldmatrix.sync.aligned.m8n8.x4.shared.b16 {%0,%1,%2,%3}, [%4];"         \
        : "=r"((r)[0]), "=r"((r)[1]), "=r"((r)[2]), "=r"((r)[3]) : "r"(a))
#define MMA16816(d, a, b0, b1)                                                           \
    asm volatile("mma.sync.aligned.m16n8k16.row.col.f32.bf16.bf16.f32 "                  \
        "{%0,%1,%2,%3}, {%4,%5,%6,%7}, {%8,%9}, {%0,%1,%2,%3};"                          \
        : "+f"((d)[0]), "+f"((d)[1]), "+f"((d)[2]), "+f"((d)[3])                         \
        : "r"((a)[0]), "r"((a)[1]), "r"((a)[2]), "r"((a)[3]), "r"(b0), "r"(b1))

// ---------------- init ----------------
__global__ void k_init() {
    int t = blockIdx.x * blockDim.x + threadIdx.x;   // <<<128,512>>>
    g_u[t] = 0.0f;
    if (t < BB * MM) g_counts[t] = 0;
    if (t == 0) g_donestep = 99;
}

// ---------------- nu ----------------
__global__ void k_nu_count(const float* __restrict__ score) {
    int idx = blockIdx.x * 256 + threadIdx.x;
    int b = idx >> 12, hw = idx & 4095;
    const float* p = score + (size_t)b * MM * NN + hw;
    float best = p[0]; int bi = 0;
#pragma unroll
    for (int k = 1; k < MM; k++) {
        float v = p[(size_t)k * NN];
        if (v > best) { best = v; bi = k; }
    }
    atomicAdd(&g_counts[b * MM + bi], 1);
}

__global__ void k_nu_final() {
    int b = blockIdx.x, k = threadIdx.x;             // <<<16,32>>>
    float c = (float)g_counts[b * MM + k];
    float nu = c / (4096.0f + 1e-8f) + 1e-6f;
    float s = wred(nu);
    g_nu[b * MM + k] = nu / s;
}

// ---------------- normalize target rows -> bf16 hi/lo yn images ----------------
__global__ void k_ynorm(const float* __restrict__ tgt) {
    int row = blockIdx.x;                            // <<<512,128>>> = b*32+m
    const float4* p = (const float4*)(tgt + (size_t)row * CC);
    int t = threadIdx.x;
    float4 v = p[t];
    float s = wred(v.x * v.x + v.y * v.y + v.z * v.z + v.w * v.w);
    __shared__ float ws[4];
    if ((t & 31) == 0) ws[t >> 5] = s;
    __syncthreads();
    float inv = rsqrtf(ws[0] + ws[1] + ws[2] + ws[3]);
    float4 o = make_float4(v.x * inv, v.y * inv, v.z * inv, v.w * inv);
    split4((ushort*)g_YH4, (ushort*)g_YL4, row * 512 + t * 4, o);
}

// ---------------- TW2 = target @ W2 ----------------
__global__ void __launch_bounds__(256) k_tw2(const float* __restrict__ tgt,
                                             const float* __restrict__ W) {
    __shared__ float ts[32 * 128];
    int blk = blockIdx.x;                            // <<<128,256>>>
    int b = blk >> 3, ct = blk & 7;
    int t = threadIdx.x;
    int c = ct * 64 + (t & 63);
    int mg = t >> 6;
    float acc[8];
#pragma unroll
    for (int i = 0; i < 8; i++) acc[i] = 0.0f;
    for (int kt = 0; kt < 4; kt++) {
        __syncthreads();
        for (int i = t; i < 32 * 128 / 4; i += 256) {
            int m = i >> 5, k4 = i & 31;
            ((float4*)ts)[i] = ((const float4*)(tgt + ((size_t)(b * 32 + m)) * CC + kt * 128))[k4];
        }
        __syncthreads();
        const float* Wp = W + (size_t)(CC + kt * 128) * CC + c;
        for (int k = 0; k < 128; k++) {
            float w = Wp[(size_t)k * CC];
#pragma unroll
            for (int i = 0; i < 8; i++) acc[i] += ts[(mg * 8 + i) * 128 + k] * w;
        }
    }
#pragma unroll
    for (int i = 0; i < 8; i++)
        g_tw2[(size_t)b * MM * CC + (size_t)(mg * 8 + i) * CC + c] = acc[i];
}

// ---------------- prep bf16 hi/lo images of W1^T and TW2^T ----------------
__global__ void k_prep_w(const float* __restrict__ W) {
    int idx = blockIdx.x * 256 + threadIdx.x;        // <<<256,256>>>
    int n = idx & 511, kq = idx >> 9;
    int k0 = kq * 4;
    float4 v = make_float4(W[(size_t)k0 * CC + n], W[(size_t)(k0 + 1) * CC + n],
                           W[(size_t)(k0 + 2) * CC + n], W[(size_t)(k0 + 3) * CC + n]);
    split4((ushort*)g_WH4, (ushort*)g_WL4, n * 512 + k0, v);
}
__global__ void k_prep_tail() {
    int idx = blockIdx.x * 256 + threadIdx.x;        // <<<256,256>>>
    int b = idx >> 12, rem = idx & 4095;
    int n = rem & 511, k0 = ((rem >> 9) & 7) * 4;
    const float* tp = g_tw2 + (size_t)b * MM * CC;
    float4 v = make_float4(tp[(size_t)k0 * CC + n], tp[(size_t)(k0 + 1) * CC + n],
                           tp[(size_t)(k0 + 2) * CC + n], tp[(size_t)(k0 + 3) * CC + n]);
    split4((ushort*)g_TH4, (ushort*)g_TL4, b * 16384 + n * 32 + k0, v);
}

// ---------------- cost / Gibbs matrix via HMMA (3-pass bf16 split) ----------------
// CTA: 128 rows x 32 cols, K=512 in 16 chunks of 32. Warp tile 16x32 (8 warps).
__global__ void __launch_bounds__(256) k_cost_hmma(const float* __restrict__ src) {
    __shared__ char sm[30208];
    ushort* Ah = (ushort*)sm;                        // 128 x 40
    ushort* Al = (ushort*)(sm + 10240);
    ushort* Bh = (ushort*)(sm + 20480);              // 32 x 40
    ushort* Bl = (ushort*)(sm + 23040);
    float* nrmp  = (float*)(sm + 25600);             // [8][128]
    float* sinv  = (float*)(sm + 29696);             // [128]
    float* scost = (float*)sm;                       // reuse A area: [32][132]
    int t = threadIdx.x, lane = t & 31, w = t >> 5;
    int r0 = blockIdx.x * 128, b = blockIdx.x >> 5;  // <<<512,256>>>

    float acc[4][4];
#pragma unroll
    for (int i = 0; i < 4; i++)
#pragma unroll
        for (int q = 0; q < 4; q++) acc[i][q] = 0.0f;
    float nrm[4] = {0.0f, 0.0f, 0.0f, 0.0f};
    int arow = lane & 15, ak = (lane >> 4) * 8;
    int brow = (lane & 7) + ((lane >> 4) & 1) * 8, bk = ((lane >> 3) & 1) * 8;
    const ushort* yh = (const ushort*)g_YH4 + (size_t)b * 16384;
    const ushort* yl = (const ushort*)g_YL4 + (size_t)b * 16384;

    for (int c = 0; c < 16; c++) {
        __syncthreads();
        const float* Ap = src + (size_t)r0 * CC + c * 32;
#pragma unroll
        for (int j = 0; j < 4; j++) {
            int e = t + j * 256;
            int row = e >> 3, kq = e & 7;
            float4 v = *(const float4*)(Ap + (size_t)row * CC + kq * 4);
            nrm[j] += v.x * v.x + v.y * v.y + v.z * v.z + v.w * v.w;
            split4(Ah, Al, row * 40 + kq * 4, v);
        }
        if (t < 128) {
            int row = t >> 2, q = t & 3;
            *(uint4*)(Bh + row * 40 + q * 8) = *(const uint4*)(yh + (size_t)row * 512 + c * 32 + q * 8);
        } else {
            int tt = t - 128;
            int row = tt >> 2, q = tt & 3;
            *(uint4*)(Bl + row * 40 + q * 8) = *(const uint4*)(yl + (size_t)row * 512 + c * 32 + q * 8);
        }
        __syncthreads();
#pragma unroll
        for (int ks = 0; ks < 2; ks++) {
            int k_off = ks * 16;
#pragma unroll
            for (int pass = 0; pass < 3; pass++) {
                ushort* Asel = (pass == 2) ? Al : Ah;
                ushort* Bsel = (pass == 1) ? Bl : Bh;
                uint32_t a[4];
                LDSM4(a, smem_u32(Asel + (w * 16 + arow) * 40 + k_off + ak));
                uint32_t bb2[2][4];
#pragma unroll
                for (int nj2 = 0; nj2 < 2; nj2++)
                    LDSM4(bb2[nj2], smem_u32(Bsel + (nj2 * 16 + brow) * 40 + k_off + bk));
                MMA16816(acc[0], a, bb2[0][0], bb2[0][1]);
                MMA16816(acc[1], a, bb2[0][2], bb2[0][3]);
                MMA16816(acc[2], a, bb2[1][0], bb2[1][1]);
                MMA16816(acc[3], a, bb2[1][2], bb2[1][3]);
            }
        }
    }
    __syncthreads();
#pragma unroll
    for (int j = 0; j < 4; j++) nrmp[(t & 7) * 128 + (t >> 3) + 32 * j] = nrm[j];
    __syncthreads();
    if (t < 128) {
        float s = 0.0f;
#pragma unroll
        for (int i = 0; i < 8; i++) s += nrmp[i * 128 + t];
        sinv[t] = rsqrtf(s);
    }
    __syncthreads();
    int g4 = lane >> 2, l2 = (lane & 3) * 2;
    int rA = w * 16 + g4, rB = rA + 8;
    float ia = sinv[rA], ib = sinv[rB];
#pragma unroll
    for (int nj = 0; nj < 4; nj++) {
        int cc = nj * 8 + l2;
        float c00 = 1.0f - acc[nj][0] * ia, c01 = 1.0f - acc[nj][1] * ia;
        float c10 = 1.0f - acc[nj][2] * ib, c11 = 1.0f - acc[nj][3] * ib;
        *(float2*)(g_cost + (size_t)(r0 + rA) * MM + cc) = make_float2(c00, c01);
        *(float2*)(g_cost + (size_t)(r0 + rB) * MM + cc) = make_float2(c10, c11);
        scost[cc * 132 + rA] = c00; scost[(cc + 1) * 132 + rA] = c01;
        scost[cc * 132 + rB] = c10; scost[(cc + 1) * 132 + rB] = c11;
    }
    __syncthreads();
    for (int i = t; i < 4096; i += 256) {
        int m = i >> 7, r = i & 127;
        g_Kt[(size_t)m * NB + r0 + r] = expf(scost[m * 132 + r] * -EPS_INV);
    }
}

// ---------------- Sinkhorn (validated) ----------------
__global__ void __launch_bounds__(512) k_sink_iter(int iter) {
    if (iter > g_donestep) return;
    int g = blockIdx.x, b = g >> 3, t = threadIdx.x; // <<<128,512>>>
    int lane = t & 31, warp = t >> 5;
    __shared__ float sv[32];
    __shared__ float wsum[16][33], werr[16];
    __shared__ int sdone;
    if (iter == 0) {
        if (t < 32) sv[t] = 0.0f;
        if (t == 32) sdone = 0;
    } else {
        int q = (iter - 1) & 1;
        if (t < 32) {
            float a = 0.0f;
#pragma unroll
            for (int k = 0; k < 8; k++) a += g_vpart[q][(b << 3) + k][t];
            float v = g_nu[b * 32 + t] / (a + 1e-8f);
            sv[t] = v;
            g_v[b * 32 + t] = v;
        }
        if (t == 32) {
            float e = 0.0f;
            for (int k = 0; k < 128; k++) e += g_errpart[q][k];
            sdone = (e * (1.0f / 16.0f) < 0.1f) ? 1 : 0;
        }
    }
    __syncthreads();
    if (sdone) { if (t == 0) g_donestep = iter; return; }
    if (iter >= 50) return;

    int row = g * 512 + t;
    float kk[32];
#pragma unroll
    for (int m = 0; m < 32; m++) kk[m] = g_Kt[(size_t)m * NB + row];
    float denom = 0.0f;
#pragma unroll
    for (int m = 0; m < 32; m++) denom += kk[m] * sv[m];
    float un = (1.0f / 4096.0f) / (denom + 1e-8f);
    float du = fabsf(un - g_u[row]);
    g_u[row] = un;
#pragma unroll
    for (int m = 0; m < 32; m++) {
        float val = wred(kk[m] * un);
        if (lane == 0) wsum[warp][m] = val;
    }
    du = wred(du);
    if (lane == 0) werr[warp] = du;
    __syncthreads();
    int p = iter & 1;
    if (t < 32) {
        float a = 0.0f;
#pragma unroll
        for (int w = 0; w < 16; w++) a += wsum[w][t];
        g_vpart[p][g][t] = a;
    } else if (t == 32) {
        float e = 0.0f;
#pragma unroll
        for (int w = 0; w < 16; w++) e += werr[w];
        g_errpart[p][g] = e;
    }
}

__global__ void __launch_bounds__(512) k_sink_epi(float* __restrict__ out_pi) {
    int g = blockIdx.x, b = g >> 3, t = threadIdx.x; // <<<128,512>>>
    int lane = t & 31, warp = t >> 5;
    __shared__ float sv[32], werr[16];
    if (t < 32) sv[t] = g_v[b * 32 + t];
    __syncthreads();
    int row = g * 512 + t;
    float u = g_u[row];
    float kk[32], pi[32];
#pragma unroll
    for (int m = 0; m < 32; m++) kk[m] = g_Kt[(size_t)m * NB + row];
    float rs = 0.0f;
#pragma unroll
    for (int m = 0; m < 32; m++) { pi[m] = u * kk[m] * sv[m]; rs += pi[m]; }
    size_t rowbase = (size_t)row * MM;
#pragma unroll
    for (int m = 0; m < 32; m += 4)
        *(float4*)(out_pi + rowbase + m) = make_float4(pi[m], pi[m + 1], pi[m + 2], pi[m + 3]);
    float inv = 1.0f / (rs + 1e-8f);
#pragma unroll
    for (int m = 0; m < 32; m += 4)
        *(float4*)(g_pinorm + rowbase + m) =
            make_float4(pi[m] * inv, pi[m + 1] * inv, pi[m + 2] * inv, pi[m + 3] * inv);
    float oc = 0.0f;
#pragma unroll
    for (int m = 0; m < 32; m += 4) {
        float4 cq = *(const float4*)(g_cost + rowbase + m);
        oc += pi[m] * cq.x + pi[m + 1] * cq.y + pi[m + 2] * cq.z + pi[m + 3] * cq.w;
    }
    oc = wred(oc);
    if (lane == 0) werr[warp] = oc;
    __syncthreads();
    if (t == 0) {
        float e = 0.0f;
#pragma unroll
        for (int w = 0; w < 16; w++) e += werr[w];
        g_otpart[g] = e;
    }
}

__global__ void k_ot_final(float* __restrict__ out_ot) {
    int b = threadIdx.x;                             // <<<1,16>>>
    float e = 0.0f;
#pragma unroll
    for (int k = 0; k < 8; k++) e += g_otpart[b * 8 + k];
    out_ot[b] = e;
}

// ---------------- pipelined HMMA fused GEMM ----------------
// CTA 128x128, 8 warps (4m x 2n), warp tile 32x64, 17 K-chunks of 32, reg-prefetch pipeline.
__global__ void __launch_bounds__(256) k_gemm_hmma(const float* __restrict__ src,
                                                   const float* __restrict__ bias,
                                                   float* __restrict__ out) {
    __shared__ uint4 sAh4[640], sAl4[640], sBh4[640], sBl4[640];   // 128 x 40 ushort each
    ushort* Ah = (ushort*)sAh4; ushort* Al = (ushort*)sAl4;
    ushort* Bh = (ushort*)sBh4; ushort* Bl = (ushort*)sBl4;
    int t = threadIdx.x, lane = t & 31, w = t >> 5;
    int r0 = blockIdx.y * 128, c0 = blockIdx.x * 128;
    int b = r0 >> 12;
    int wm = (w & 3) * 32, wn = (w >> 2) * 64;

    float acc[2][8][4];
#pragma unroll
    for (int i = 0; i < 2; i++)
#pragma unroll
        for (int j = 0; j < 8; j++)
#pragma unroll
            for (int q = 0; q < 4; q++) acc[i][j][q] = 0.0f;

    int arow = lane & 15, ak = (lane >> 4) * 8;
    int brow = (lane & 7) + ((lane >> 4) & 1) * 8, bk = ((lane >> 3) & 1) * 8;
    int aRow = t >> 3, aKq = t & 7;                  // A ldg mapping (j adds 32 rows)
    int bRow = t >> 2, bQ = t & 3;                   // B ldg mapping (j adds 64 rows)

    float4 ra[4];
    uint4 rbh[2], rbl[2];
    // prefetch chunk 0
    {
        const float* Ap = src + (size_t)r0 * CC;
#pragma unroll
        for (int j = 0; j < 4; j++)
            ra[j] = *(const float4*)(Ap + (size_t)(aRow + 32 * j) * CC + aKq * 4);
        const ushort* bh = (const ushort*)g_WH4 + (size_t)c0 * 512;
        const ushort* bl = (const ushort*)g_WL4 + (size_t)c0 * 512;
#pragma unroll
        for (int j = 0; j < 2; j++) {
            rbh[j] = *(const uint4*)(bh + (size_t)(bRow + 64 * j) * 512 + bQ * 8);
            rbl[j] = *(const uint4*)(bl + (size_t)(bRow + 64 * j) * 512 + bQ * 8);
        }
    }

    for (int c = 0; c < 17; c++) {
        // store staged regs to smem
#pragma unroll
        for (int j = 0; j < 4; j++)
            split4(Ah, Al, (aRow + 32 * j) * 40 + aKq * 4, ra[j]);
#pragma unroll
        for (int j = 0; j < 2; j++) {
            int row = bRow + 64 * j;
            *(uint4*)(Bh + row * 40 + bQ * 8) = rbh[j];
            *(uint4*)(Bl + row * 40 + bQ * 8) = rbl[j];
        }
        __syncthreads();
        // prefetch next chunk into regs (overlaps with MMA below)
        if (c < 16) {
            int cn = c + 1;
            if (cn < 16) {
                const float* Ap = src + (size_t)r0 * CC + cn * 32;
#pragma unroll
                for (int j = 0; j < 4; j++)
                    ra[j] = *(const float4*)(Ap + (size_t)(aRow + 32 * j) * CC + aKq * 4);
                const ushort* bh = (const ushort*)g_WH4 + (size_t)c0 * 512 + cn * 32;
                const ushort* bl = (const ushort*)g_WL4 + (size_t)c0 * 512 + cn * 32;
#pragma unroll
                for (int j = 0; j < 2; j++) {
                    rbh[j] = *(const uint4*)(bh + (size_t)(bRow + 64 * j) * 512 + bQ * 8);
                    rbl[j] = *(const uint4*)(bl + (size_t)(bRow + 64 * j) * 512 + bQ * 8);
                }
            } else {
                const float* Ap = g_pinorm + (size_t)r0 * MM;
#pragma unroll
                for (int j = 0; j < 4; j++)
                    ra[j] = *(const float4*)(Ap + (size_t)(aRow + 32 * j) * MM + aKq * 4);
                const ushort* bh = (const ushort*)g_TH4 + (size_t)b * 16384 + (size_t)c0 * 32;
                const ushort* bl = (const ushort*)g_TL4 + (size_t)b * 16384 + (size_t)c0 * 32;
#pragma unroll
                for (int j = 0; j < 2; j++) {
                    rbh[j] = *(const uint4*)(bh + (size_t)(bRow + 64 * j) * 32 + bQ * 8);
                    rbl[j] = *(const uint4*)(bl + (size_t)(bRow + 64 * j) * 32 + bQ * 8);
                }
            }
        }
        // MMA on current smem tiles
#pragma unroll
        for (int ks = 0; ks < 2; ks++) {
            int k_off = ks * 16;
#pragma unroll
            for (int pass = 0; pass < 3; pass++) {
                ushort* Asel = (pass == 2) ? Al : Ah;
                ushort* Bsel = (pass == 1) ? Bl : Bh;
                uint32_t a[2][4];
#pragma unroll
                for (int mi = 0; mi < 2; mi++)
                    LDSM4(a[mi], smem_u32(Asel + (wm + mi * 16 + arow) * 40 + k_off + ak));
                uint32_t bb[4][4];
#pragma unroll
                for (int nj2 = 0; nj2 < 4; nj2++)
                    LDSM4(bb[nj2], smem_u32(Bsel + (wn + nj2 * 16 + brow) * 40 + k_off + bk));
#pragma unroll
                for (int mi = 0; mi < 2; mi++)
#pragma unroll
                    for (int nj2 = 0; nj2 < 4; nj2++) {
                        MMA16816(acc[mi][nj2 * 2],     a[mi], bb[nj2][0], bb[nj2][1]);
                        MMA16816(acc[mi][nj2 * 2 + 1], a[mi], bb[nj2][2], bb[nj2][3]);
                    }
            }
        }
        __syncthreads();
    }
    // epilogue: +bias, store
    int g4 = lane >> 2, l2 = (lane & 3) * 2;
#pragma unroll
    for (int mi = 0; mi < 2; mi++)
#pragma unroll
        for (int nj = 0; nj < 8; nj++) {
            int rr = r0 + wm + mi * 16 + g4;
            int cc = c0 + wn + nj * 8 + l2;
            float2 bi = *(const float2*)(bias + cc);
            *(float2*)(out + (size_t)rr * CC + cc) =
                make_float2(acc[mi][nj][0] + bi.x, acc[mi][nj][1] + bi.y);
            *(float2*)(out + (size_t)(rr + 8) * CC + cc) =
                make_float2(acc[mi][nj][2] + bi.x, acc[mi][nj][3] + bi.y);
        }
}

// ---------------- LayerNorm, in-place ----------------
__global__ void k_ln(float* __restrict__ out,
                     const float* __restrict__ gamma,
                     const float* __restrict__ beta) {
    int row = blockIdx.x;                            // <<<65536,128>>>
    float4* p = (float4*)(out + (size_t)row * CC);
    int t = threadIdx.x;
    float4 v = p[t];
    __shared__ float ws[4];
    float s = wred(v.x + v.y + v.z + v.w);
    if ((t & 31) == 0) ws[t >> 5] = s;
    __syncthreads();
    float mean = (ws[0] + ws[1] + ws[2] + ws[3]) * (1.0f / 512.0f);
    float dx0 = v.x - mean, dx1 = v.y - mean, dx2 = v.z - mean, dx3 = v.w - mean;
    float s2 = wred(dx0 * dx0 + dx1 * dx1 + dx2 * dx2 + dx3 * dx3);
    __syncthreads();
    if ((t & 31) == 0) ws[t >> 5] = s2;
    __syncthreads();
    float var = (ws[0] + ws[1] + ws[2] + ws[3]) * (1.0f / 512.0f);
    float sc = rsqrtf(var + 1e-5f);
    float4 g = ((const float4*)gamma)[t];
    float4 bb = ((const float4*)beta)[t];
    v.x = dx0 * sc * g.x + bb.x;
    v.y = dx1 * sc * g.y + bb.y;
    v.z = dx2 * sc * g.z + bb.z;
    v.w = dx3 * sc * g.w + bb.w;
    p[t] = v;
}

// ---------------- launch ----------------
extern "C" void kernel_launch(void* const* d_in, const int* in_sizes, int n_in,
                              void* d_out, int out_size) {
    const float* src   = (const float*)d_in[0];
    const float* tgt   = (const float*)d_in[1];
    const float* score = (const float*)d_in[2];
    const float* W     = (const float*)d_in[3];
    const float* bias  = (const float*)d_in[4];
    const float* gamma = (const float*)d_in[5];
    const float* beta  = (const float*)d_in[6];
    float* out = (float*)d_out;

    const size_t OUT_OT = (size_t)BB * NN * CC;
    float* out_ot = out + OUT_OT;
    float* out_pi = out + OUT_OT + BB;

    k_init<<<128, 512>>>();
    k_nu_count<<<(BB * NN) / 256, 256>>>(score);
    k_nu_final<<<BB, MM>>>();
    k_ynorm<<<BB * MM, 128>>>(tgt);
    k_tw2<<<128, 256>>>(tgt, W);
    k_prep_w<<<256, 256>>>(W);
    k_prep_tail<<<256, 256>>>();
    k_cost_hmma<<<512, 256>>>(src);
    for (int it = 0; it <= 50; it++) k_sink_iter<<<128, 512>>>(it);
    k_sink_epi<<<128, 512>>>(out_pi);
    k_ot_final<<<1, 16>>>(out_ot);
    k_gemm_hmma<<<dim3(4, 512), 256>>>(src, bias, out);
    k_ln<<<BB * NN, 128>>>(out, gamma, beta);
}

// round 10
// speedup vs baseline: 2.0406x; 1.0258x over previous
#include <cuda_runtime.h>
#include <cuda_bf16.h>
#include <math.h>
#include <stdint.h>

#define BB 16
#define NN 4096
#define CC 512
#define MM 32
#define NB (BB*NN)
#define EPS_INV 20.0f

// ---------------- scratch (device globals; no allocation) ----------------
__device__ float g_tw2[BB*MM*CC];
__device__ float g_nu[BB*MM];
__device__ int   g_counts[BB*MM];
__device__ float g_Kt[(size_t)MM*NB];       // Gibbs kernel transposed [m][row]
__device__ float g_cost[(size_t)NB*MM];     // cost row-major
__device__ float g_pinorm[(size_t)NB*MM];
__device__ float g_vtraj[50*BB*MM];         // v trajectory per iteration
__device__ float g_errtraj8[50*128];        // per-CTA err partials per iteration
__device__ float g_otpart[128];
__device__ int   g_kidx;
// bf16 hi/lo images: W1^T [n][k] 512x512, TW2^T [b][n][k] 512x32, yn [b][m][k] 32x512
__device__ uint4 g_WH4[32768], g_WL4[32768];
__device__ uint4 g_TH4[32768], g_TL4[32768];
__device__ uint4 g_YH4[32768], g_YL4[32768];

__device__ __forceinline__ float wred(float v) {
#pragma unroll
    for (int o = 16; o; o >>= 1) v += __shfl_xor_sync(0xffffffffu, v, o);
    return v;
}
__device__ __forceinline__ uint32_t smem_u32(const void* p) {
    uint32_t a;
    asm("{ .reg .u64 t; cvta.to.shared.u64 t, %1; cvt.u32.u64 %0, t; }" : "=r"(a) : "l"(p));
    return a;
}
__device__ __forceinline__ float dsmem_ld(uint32_t laddr, uint32_t rank) {
    uint32_t ra; float v;
    asm("mapa.shared::cluster.u32 %0, %1, %2;" : "=r"(ra) : "r"(laddr), "r"(rank));
    asm volatile("ld.shared::cluster.f32 %0, [%1];" : "=f"(v) : "r"(ra) : "memory");
    return v;
}
#define CLUSTER_SYNC() do {                                             \
    asm volatile("barrier.cluster.arrive.aligned;" ::: "memory");       \
    asm volatile("barrier.cluster.wait.aligned;" ::: "memory");         \
} while (0)
__device__ __forceinline__ void split4(ushort* hb, ushort* lb, int off, float4 v) {
    __nv_bfloat16 hx = __float2bfloat16(v.x), hy = __float2bfloat16(v.y),
                  hz = __float2bfloat16(v.z), hw = __float2bfloat16(v.w);
    unsigned h0 = ((unsigned)__bfloat16_as_ushort(hy) << 16) | __bfloat16_as_ushort(hx);
    unsigned h1 = ((unsigned)__bfloat16_as_ushort(hw) << 16) | __bfloat16_as_ushort(hz);
    __nv_bfloat16 ax = __float2bfloat16(v.x - __bfloat162float(hx));
    __nv_bfloat16 ay = __float2bfloat16(v.y - __bfloat162float(hy));
    __nv_bfloat16 az = __float2bfloat16(v.z - __bfloat162float(hz));
    __nv_bfloat16 aw = __float2bfloat16(v.w - __bfloat162float(hw));
    unsigned l0 = ((unsigned)__bfloat16_as_ushort(ay) << 16) | __bfloat16_as_ushort(ax);
    unsigned l1 = ((unsigned)__bfloat16_as_ushort(aw) << 16) | __bfloat16_as_ushort(az);
    *(uint2*)(hb + off) = make_uint2(h0, h1);
    *(uint2*)(lb + off) = make_uint2(l0, l1);
}
#define LDSM4(r, a)                                                                      \
    asm volatile("ldmatrix.sync.aligned.m8n8.x4.shared.b16 {%0,%1,%2,%3}, [%4];"         \
        : "=r"((r)[0]), "=r"((r)[1]), "=r"((r)[2]), "=r"((r)[3]) : "r"(a))
#define MMA16816(d, a, b0, b1)                                                           \
    asm volatile("mma.sync.aligned.m16n8k16.row.col.f32.bf16.bf16.f32 "                  \
        "{%0,%1,%2,%3}, {%4,%5,%6,%7}, {%8,%9}, {%0,%1,%2,%3};"                          \
        : "+f"((d)[0]), "+f"((d)[1]), "+f"((d)[2]), "+f"((d)[3])                         \
        : "r"((a)[0]), "r"((a)[1]), "r"((a)[2]), "r"((a)[3]), "r"(b0), "r"(b1))

// ---------------- init ----------------
__global__ void k_init() {
    int t = threadIdx.x;                             // <<<1,512>>>
    if (t < BB * MM) g_counts[t] = 0;
}

// ---------------- nu ----------------
__global__ void k_nu_count(const float* __restrict__ score) {
    int idx = blockIdx.x * 256 + threadIdx.x;
    int b = idx >> 12, hw = idx & 4095;
    const float* p = score + (size_t)b * MM * NN + hw;
    float best = p[0]; int bi = 0;
#pragma unroll
    for (int k = 1; k < MM; k++) {
        float v = p[(size_t)k * NN];
        if (v > best) { best = v; bi = k; }
    }
    atomicAdd(&g_counts[b * MM + bi], 1);
}

__global__ void k_nu_final() {
    int b = blockIdx.x, k = threadIdx.x;             // <<<16,32>>>
    float c = (float)g_counts[b * MM + k];
    float nu = c / (4096.0f + 1e-8f) + 1e-6f;
    float s = wred(nu);
    g_nu[b * MM + k] = nu / s;
}

// ---------------- normalize target rows -> bf16 hi/lo yn images ----------------
__global__ void k_ynorm(const float* __restrict__ tgt) {
    int row = blockIdx.x;                            // <<<512,128>>>
    const float4* p = (const float4*)(tgt + (size_t)row * CC);
    int t = threadIdx.x;
    float4 v = p[t];
    float s = wred(v.x * v.x + v.y * v.y + v.z * v.z + v.w * v.w);
    __shared__ float ws[4];
    if ((t & 31) == 0) ws[t >> 5] = s;
    __syncthreads();
    float inv = rsqrtf(ws[0] + ws[1] + ws[2] + ws[3]);
    float4 o = make_float4(v.x * inv, v.y * inv, v.z * inv, v.w * inv);
    split4((ushort*)g_YH4, (ushort*)g_YL4, row * 512 + t * 4, o);
}

// ---------------- TW2 = target @ W2 ----------------
__global__ void __launch_bounds__(256) k_tw2(const float* __restrict__ tgt,
                                             const float* __restrict__ W) {
    __shared__ float ts[32 * 128];
    int blk = blockIdx.x;                            // <<<128,256>>>
    int b = blk >> 3, ct = blk & 7;
    int t = threadIdx.x;
    int c = ct * 64 + (t & 63);
    int mg = t >> 6;
    float acc[8];
#pragma unroll
    for (int i = 0; i < 8; i++) acc[i] = 0.0f;
    for (int kt = 0; kt < 4; kt++) {
        __syncthreads();
        for (int i = t; i < 32 * 128 / 4; i += 256) {
            int m = i >> 5, k4 = i & 31;
            ((float4*)ts)[i] = ((const float4*)(tgt + ((size_t)(b * 32 + m)) * CC + kt * 128))[k4];
        }
        __syncthreads();
        const float* Wp = W + (size_t)(CC + kt * 128) * CC + c;
        for (int k = 0; k < 128; k++) {
            float w = Wp[(size_t)k * CC];
#pragma unroll
            for (int i = 0; i < 8; i++) acc[i] += ts[(mg * 8 + i) * 128 + k] * w;
        }
    }
#pragma unroll
    for (int i = 0; i < 8; i++)
        g_tw2[(size_t)b * MM * CC + (size_t)(mg * 8 + i) * CC + c] = acc[i];
}

// ---------------- prep bf16 hi/lo images ----------------
__global__ void k_prep_w(const float* __restrict__ W) {
    int idx = blockIdx.x * 256 + threadIdx.x;        // <<<256,256>>>
    int n = idx & 511, kq = idx >> 9;
    int k0 = kq * 4;
    float4 v = make_float4(W[(size_t)k0 * CC + n], W[(size_t)(k0 + 1) * CC + n],
                           W[(size_t)(k0 + 2) * CC + n], W[(size_t)(k0 + 3) * CC + n]);
    split4((ushort*)g_WH4, (ushort*)g_WL4, n * 512 + k0, v);
}
__global__ void k_prep_tail() {
    int idx = blockIdx.x * 256 + threadIdx.x;        // <<<256,256>>>
    int b = idx >> 12, rem = idx & 4095;
    int n = rem & 511, k0 = ((rem >> 9) & 7) * 4;
    const float* tp = g_tw2 + (size_t)b * MM * CC;
    float4 v = make_float4(tp[(size_t)k0 * CC + n], tp[(size_t)(k0 + 1) * CC + n],
                           tp[(size_t)(k0 + 2) * CC + n], tp[(size_t)(k0 + 3) * CC + n]);
    split4((ushort*)g_TH4, (ushort*)g_TL4, b * 16384 + n * 32 + k0, v);
}

// ---------------- cost / Gibbs matrix via HMMA (validated R8) ----------------
__global__ void __launch_bounds__(256) k_cost_hmma(const float* __restrict__ src) {
    __shared__ char sm[30208];
    ushort* Ah = (ushort*)sm;
    ushort* Al = (ushort*)(sm + 10240);
    ushort* Bh = (ushort*)(sm + 20480);
    ushort* Bl = (ushort*)(sm + 23040);
    float* nrmp  = (float*)(sm + 25600);
    float* sinv  = (float*)(sm + 29696);
    float* scost = (float*)sm;
    int t = threadIdx.x, lane = t & 31, w = t >> 5;
    int r0 = blockIdx.x * 128, b = blockIdx.x >> 5;  // <<<512,256>>>

    float acc[4][4];
#pragma unroll
    for (int i = 0; i < 4; i++)
#pragma unroll
        for (int q = 0; q < 4; q++) acc[i][q] = 0.0f;
    float nrm[4] = {0.0f, 0.0f, 0.0f, 0.0f};
    int arow = lane & 15, ak = (lane >> 4) * 8;
    int brow = (lane & 7) + ((lane >> 4) & 1) * 8, bk = ((lane >> 3) & 1) * 8;
    const ushort* yh = (const ushort*)g_YH4 + (size_t)b * 16384;
    const ushort* yl = (const ushort*)g_YL4 + (size_t)b * 16384;

    for (int c = 0; c < 16; c++) {
        __syncthreads();
        const float* Ap = src + (size_t)r0 * CC + c * 32;
#pragma unroll
        for (int j = 0; j < 4; j++) {
            int e = t + j * 256;
            int row = e >> 3, kq = e & 7;
            float4 v = *(const float4*)(Ap + (size_t)row * CC + kq * 4);
            nrm[j] += v.x * v.x + v.y * v.y + v.z * v.z + v.w * v.w;
            split4(Ah, Al, row * 40 + kq * 4, v);
        }
        if (t < 128) {
            int row = t >> 2, q = t & 3;
            *(uint4*)(Bh + row * 40 + q * 8) = *(const uint4*)(yh + (size_t)row * 512 + c * 32 + q * 8);
        } else {
            int tt = t - 128;
            int row = tt >> 2, q = tt & 3;
            *(uint4*)(Bl + row * 40 + q * 8) = *(const uint4*)(yl + (size_t)row * 512 + c * 32 + q * 8);
        }
        __syncthreads();
#pragma unroll
        for (int ks = 0; ks < 2; ks++) {
            int k_off = ks * 16;
#pragma unroll
            for (int pass = 0; pass < 3; pass++) {
                ushort* Asel = (pass == 2) ? Al : Ah;
                ushort* Bsel = (pass == 1) ? Bl : Bh;
                uint32_t a[4];
                LDSM4(a, smem_u32(Asel + (w * 16 + arow) * 40 + k_off + ak));
                uint32_t bb2[2][4];
#pragma unroll
                for (int nj2 = 0; nj2 < 2; nj2++)
                    LDSM4(bb2[nj2], smem_u32(Bsel + (nj2 * 16 + brow) * 40 + k_off + bk));
                MMA16816(acc[0], a, bb2[0][0], bb2[0][1]);
                MMA16816(acc[1], a, bb2[0][2], bb2[0][3]);
                MMA16816(acc[2], a, bb2[1][0], bb2[1][1]);
                MMA16816(acc[3], a, bb2[1][2], bb2[1][3]);
            }
        }
    }
    __syncthreads();
#pragma unroll
    for (int j = 0; j < 4; j++) nrmp[(t & 7) * 128 + (t >> 3) + 32 * j] = nrm[j];
    __syncthreads();
    if (t < 128) {
        float s = 0.0f;
#pragma unroll
        for (int i = 0; i < 8; i++) s += nrmp[i * 128 + t];
        sinv[t] = rsqrtf(s);
    }
    __syncthreads();
    int g4 = lane >> 2, l2 = (lane & 3) * 2;
    int rA = w * 16 + g4, rB = rA + 8;
    float ia = sinv[rA], ib = sinv[rB];
#pragma unroll
    for (int nj = 0; nj < 4; nj++) {
        int cc = nj * 8 + l2;
        float c00 = 1.0f - acc[nj][0] * ia, c01 = 1.0f - acc[nj][1] * ia;
        float c10 = 1.0f - acc[nj][2] * ib, c11 = 1.0f - acc[nj][3] * ib;
        *(float2*)(g_cost + (size_t)(r0 + rA) * MM + cc) = make_float2(c00, c01);
        *(float2*)(g_cost + (size_t)(r0 + rB) * MM + cc) = make_float2(c10, c11);
        scost[cc * 132 + rA] = c00; scost[(cc + 1) * 132 + rA] = c01;
        scost[cc * 132 + rB] = c10; scost[(cc + 1) * 132 + rB] = c11;
    }
    __syncthreads();
    for (int i = t; i < 4096; i += 256) {
        int m = i >> 7, r = i & 127;
        g_Kt[(size_t)m * NB + r0 + r] = expf(scost[m * 132 + r] * -EPS_INV);
    }
}

// ---------------- Sinkhorn: ALL 50 iterations in ONE kernel (8-CTA clusters) ----------------
// Cluster = one batch b (8 CTAs x 512 rows). Cross-CTA K^T u reduction via DSMEM.
// Trajectories recorded; the global early-stop decision is applied afterwards (k_pick).
__global__ void __launch_bounds__(512, 1) __cluster_dims__(8, 1, 1)
k_sink_all() {
    int g = blockIdx.x, b = g >> 3, t = threadIdx.x; // <<<128,512>>>
    int lane = t & 31, warp = t >> 5, rank0 = ((g & 7) == 0);
    __shared__ float sv[32], snu[32];
    __shared__ float cpart[2][34];                   // [parity][Kt-u partials 0..31, err at 32]
    __shared__ float wsum[16][33], werr[16];
    if (t < 32) { sv[t] = 0.0f; snu[t] = g_nu[b * 32 + t]; }
    __syncthreads();

    int row = g * 512 + t;
    float kk[32];
#pragma unroll
    for (int m = 0; m < 32; m++) kk[m] = g_Kt[(size_t)m * NB + row];
    float u = 0.0f;
    const float mu = 1.0f / 4096.0f;

    for (int it = 0; it < 50; it++) {
        float denom = 0.0f;
#pragma unroll
        for (int m = 0; m < 32; m++) denom += kk[m] * sv[m];
        float un = mu / (denom + 1e-8f);
        float du = fabsf(un - u);
        u = un;
#pragma unroll
        for (int m = 0; m < 32; m++) {
            float val = wred(kk[m] * un);
            if (lane == 0) wsum[warp][m] = val;
        }
        du = wred(du);
        if (lane == 0) werr[warp] = du;
        __syncthreads();
        int p = it & 1;
        if (t < 32) {
            float a = 0.0f;
#pragma unroll
            for (int w2 = 0; w2 < 16; w2++) a += wsum[w2][t];
            cpart[p][t] = a;
        } else if (t == 32) {
            float e = 0.0f;
#pragma unroll
            for (int w2 = 0; w2 < 16; w2++) e += werr[w2];
            cpart[p][32] = e;
            g_errtraj8[it * 128 + g] = e;            // exact old 0..127 ordering
        }
        CLUSTER_SYNC();
        if (t < 32) {
            uint32_t laddr = smem_u32(&cpart[p][t]);
            float a = 0.0f;
#pragma unroll
            for (int r = 0; r < 8; r++) a += dsmem_ld(laddr, (uint32_t)r);
            float v = snu[t] / (a + 1e-8f);
            sv[t] = v;
            if (rank0) g_vtraj[(it * 16 + b) * 32 + t] = v;
        }
        __syncthreads();
    }
    // no CTA may exit while peers might still read its cpart: final cluster sync
    CLUSTER_SYNC();
}

// pick kept iteration: first it with mean_b err < 0.1 (else 49)
__global__ void k_pick() {
    __shared__ int midx;
    int t = threadIdx.x;                             // <<<1,64>>>
    if (t == 0) midx = 49;
    __syncthreads();
    if (t < 50) {
        float e = 0.0f;
        const float* ep = g_errtraj8 + t * 128;
        for (int k = 0; k < 128; k++) e += ep[k];    // old deterministic order
        if (e * (1.0f / 16.0f) < 0.1f) atomicMin(&midx, t);
    }
    __syncthreads();
    if (t == 0) g_kidx = midx;
}

// ---------------- Sinkhorn epilogue: recompute u from v_{k-1}, build pi ----------------
__global__ void __launch_bounds__(512) k_sink_epi(float* __restrict__ out_pi) {
    int g = blockIdx.x, b = g >> 3, t = threadIdx.x; // <<<128,512>>>
    int lane = t & 31, warp = t >> 5;
    __shared__ float sv[32], svp[32], werr[16];
    int kidx = g_kidx;
    if (t < 32) {
        sv[t] = g_vtraj[(kidx * 16 + b) * 32 + t];
        svp[t] = (kidx > 0) ? g_vtraj[((kidx - 1) * 16 + b) * 32 + t] : 0.0f;
    }
    __syncthreads();
    int row = g * 512 + t;
    float kk[32], pi[32];
#pragma unroll
    for (int m = 0; m < 32; m++) kk[m] = g_Kt[(size_t)m * NB + row];
    float denom = 0.0f;
#pragma unroll
    for (int m = 0; m < 32; m++) denom += kk[m] * svp[m];
    float u = (1.0f / 4096.0f) / (denom + 1e-8f);
    float rs = 0.0f;
#pragma unroll
    for (int m = 0; m < 32; m++) { pi[m] = u * kk[m] * sv[m]; rs += pi[m]; }
    size_t rowbase = (size_t)row * MM;
#pragma unroll
    for (int m = 0; m < 32; m += 4)
        *(float4*)(out_pi + rowbase + m) = make_float4(pi[m], pi[m + 1], pi[m + 2], pi[m + 3]);
    float inv = 1.0f / (rs + 1e-8f);
#pragma unroll
    for (int m = 0; m < 32; m += 4)
        *(float4*)(g_pinorm + rowbase + m) =
            make_float4(pi[m] * inv, pi[m + 1] * inv, pi[m + 2] * inv, pi[m + 3] * inv);
    float oc = 0.0f;
#pragma unroll
    for (int m = 0; m < 32; m += 4) {
        float4 cq = *(const float4*)(g_cost + rowbase + m);
        oc += pi[m] * cq.x + pi[m + 1] * cq.y + pi[m + 2] * cq.z + pi[m + 3] * cq.w;
    }
    oc = wred(oc);
    if (lane == 0) werr[warp] = oc;
    __syncthreads();
    if (t == 0) {
        float e = 0.0f;
#pragma unroll
        for (int w = 0; w < 16; w++) e += werr[w];
        g_otpart[g] = e;
    }
}

__global__ void k_ot_final(float* __restrict__ out_ot) {
    int b = threadIdx.x;                             // <<<1,16>>>
    float e = 0.0f;
#pragma unroll
    for (int k = 0; k < 8; k++) e += g_otpart[b * 8 + k];
    out_ot[b] = e;
}

// ---------------- pipelined HMMA fused GEMM (validated R8) ----------------
__global__ void __launch_bounds__(256) k_gemm_hmma(const float* __restrict__ src,
                                                   const float* __restrict__ bias,
                                                   float* __restrict__ out) {
    __shared__ uint4 sAh4[640], sAl4[640], sBh4[640], sBl4[640];
    ushort* Ah = (ushort*)sAh4; ushort* Al = (ushort*)sAl4;
    ushort* Bh = (ushort*)sBh4; ushort* Bl = (ushort*)sBl4;
    int t = threadIdx.x, lane = t & 31, w = t >> 5;
    int r0 = blockIdx.y * 128, c0 = blockIdx.x * 128;
    int b = r0 >> 12;
    int wm = (w & 3) * 32, wn = (w >> 2) * 64;

    float acc[2][8][4];
#pragma unroll
    for (int i = 0; i < 2; i++)
#pragma unroll
        for (int j = 0; j < 8; j++)
#pragma unroll
            for (int q = 0; q < 4; q++) acc[i][j][q] = 0.0f;

    int arow = lane & 15, ak = (lane >> 4) * 8;
    int brow = (lane & 7) + ((lane >> 4) & 1) * 8, bk = ((lane >> 3) & 1) * 8;
    int aRow = t >> 3, aKq = t & 7;
    int bRow = t >> 2, bQ = t & 3;

    float4 ra[4];
    uint4 rbh[2], rbl[2];
    {
        const float* Ap = src + (size_t)r0 * CC;
#pragma unroll
        for (int j = 0; j < 4; j++)
            ra[j] = *(const float4*)(Ap + (size_t)(aRow + 32 * j) * CC + aKq * 4);
        const ushort* bh = (const ushort*)g_WH4 + (size_t)c0 * 512;
        const ushort* bl = (const ushort*)g_WL4 + (size_t)c0 * 512;
#pragma unroll
        for (int j = 0; j < 2; j++) {
            rbh[j] = *(const uint4*)(bh + (size_t)(bRow + 64 * j) * 512 + bQ * 8);
            rbl[j] = *(const uint4*)(bl + (size_t)(bRow + 64 * j) * 512 + bQ * 8);
        }
    }

    for (int c = 0; c < 17; c++) {
#pragma unroll
        for (int j = 0; j < 4; j++)
            split4(Ah, Al, (aRow + 32 * j) * 40 + aKq * 4, ra[j]);
#pragma unroll
        for (int j = 0; j < 2; j++) {
            int row = bRow + 64 * j;
            *(uint4*)(Bh + row * 40 + bQ * 8) = rbh[j];
            *(uint4*)(Bl + row * 40 + bQ * 8) = rbl[j];
        }
        __syncthreads();
        if (c < 16) {
            int cn = c + 1;
            if (cn < 16) {
                const float* Ap = src + (size_t)r0 * CC + cn * 32;
#pragma unroll
                for (int j = 0; j < 4; j++)
                    ra[j] = *(const float4*)(Ap + (size_t)(aRow + 32 * j) * CC + aKq * 4);
                const ushort* bh = (const ushort*)g_WH4 + (size_t)c0 * 512 + cn * 32;
                const ushort* bl = (const ushort*)g_WL4 + (size_t)c0 * 512 + cn * 32;
#pragma unroll
                for (int j = 0; j < 2; j++) {
                    rbh[j] = *(const uint4*)(bh + (size_t)(bRow + 64 * j) * 512 + bQ * 8);
                    rbl[j] = *(const uint4*)(bl + (size_t)(bRow + 64 * j) * 512 + bQ * 8);
                }
            } else {
                const float* Ap = g_pinorm + (size_t)r0 * MM;
#pragma unroll
                for (int j = 0; j < 4; j++)
                    ra[j] = *(const float4*)(Ap + (size_t)(aRow + 32 * j) * MM + aKq * 4);
                const ushort* bh = (const ushort*)g_TH4 + (size_t)b * 16384 + (size_t)c0 * 32;
                const ushort* bl = (const ushort*)g_TL4 + (size_t)b * 16384 + (size_t)c0 * 32;
#pragma unroll
                for (int j = 0; j < 2; j++) {
                    rbh[j] = *(const uint4*)(bh + (size_t)(bRow + 64 * j) * 32 + bQ * 8);
                    rbl[j] = *(const uint4*)(bl + (size_t)(bRow + 64 * j) * 32 + bQ * 8);
                }
            }
        }
#pragma unroll
        for (int ks = 0; ks < 2; ks++) {
            int k_off = ks * 16;
#pragma unroll
            for (int pass = 0; pass < 3; pass++) {
                ushort* Asel = (pass == 2) ? Al : Ah;
                ushort* Bsel = (pass == 1) ? Bl : Bh;
                uint32_t a[2][4];
#pragma unroll
                for (int mi = 0; mi < 2; mi++)
                    LDSM4(a[mi], smem_u32(Asel + (wm + mi * 16 + arow) * 40 + k_off + ak));
                uint32_t bb[4][4];
#pragma unroll
                for (int nj2 = 0; nj2 < 4; nj2++)
                    LDSM4(bb[nj2], smem_u32(Bsel + (wn + nj2 * 16 + brow) * 40 + k_off + bk));
#pragma unroll
                for (int mi = 0; mi < 2; mi++)
#pragma unroll
                    for (int nj2 = 0; nj2 < 4; nj2++) {
                        MMA16816(acc[mi][nj2 * 2],     a[mi], bb[nj2][0], bb[nj2][1]);
                        MMA16816(acc[mi][nj2 * 2 + 1], a[mi], bb[nj2][2], bb[nj2][3]);
                    }
            }
        }
        __syncthreads();
    }
    int g4 = lane >> 2, l2 = (lane & 3) * 2;
#pragma unroll
    for (int mi = 0; mi < 2; mi++)
#pragma unroll
        for (int nj = 0; nj < 8; nj++) {
            int rr = r0 + wm + mi * 16 + g4;
            int cc = c0 + wn + nj * 8 + l2;
            float2 bi = *(const float2*)(bias + cc);
            *(float2*)(out + (size_t)rr * CC + cc) =
                make_float2(acc[mi][nj][0] + bi.x, acc[mi][nj][1] + bi.y);
            *(float2*)(out + (size_t)(rr + 8) * CC + cc) =
                make_float2(acc[mi][nj][2] + bi.x, acc[mi][nj][3] + bi.y);
        }
}

// ---------------- LayerNorm, in-place ----------------
__global__ void k_ln(float* __restrict__ out,
                     const float* __restrict__ gamma,
                     const float* __restrict__ beta) {
    int row = blockIdx.x;                            // <<<65536,128>>>
    float4* p = (float4*)(out + (size_t)row * CC);
    int t = threadIdx.x;
    float4 v = p[t];
    __shared__ float ws[4];
    float s = wred(v.x + v.y + v.z + v.w);
    if ((t & 31) == 0) ws[t >> 5] = s;
    __syncthreads();
    float mean = (ws[0] + ws[1] + ws[2] + ws[3]) * (1.0f / 512.0f);
    float dx0 = v.x - mean, dx1 = v.y - mean, dx2 = v.z - mean, dx3 = v.w - mean;
    float s2 = wred(dx0 * dx0 + dx1 * dx1 + dx2 * dx2 + dx3 * dx3);
    __syncthreads();
    if ((t & 31) == 0) ws[t >> 5] = s2;
    __syncthreads();
    float var = (ws[0] + ws[1] + ws[2] + ws[3]) * (1.0f / 512.0f);
    float sc = rsqrtf(var + 1e-5f);
    float4 g = ((const float4*)gamma)[t];
    float4 bb = ((const float4*)beta)[t];
    v.x = dx0 * sc * g.x + bb.x;
    v.y = dx1 * sc * g.y + bb.y;
    v.z = dx2 * sc * g.z + bb.z;
    v.w = dx3 * sc * g.w + bb.w;
    p[t] = v;
}

// ---------------- launch ----------------
extern "C" void kernel_launch(void* const* d_in, const int* in_sizes, int n_in,
                              void* d_out, int out_size) {
    const float* src   = (const float*)d_in[0];
    const float* tgt   = (const float*)d_in[1];
    const float* score = (const float*)d_in[2];
    const float* W     = (const float*)d_in[3];
    const float* bias  = (const float*)d_in[4];
    const float* gamma = (const float*)d_in[5];
    const float* beta  = (const float*)d_in[6];
    float* out = (float*)d_out;

    const size_t OUT_OT = (size_t)BB * NN * CC;
    float* out_ot = out + OUT_OT;
    float* out_pi = out + OUT_OT + BB;

    k_init<<<1, 512>>>();
    k_nu_count<<<(BB * NN) / 256, 256>>>(score);
    k_nu_final<<<BB, MM>>>();
    k_ynorm<<<BB * MM, 128>>>(tgt);
    k_tw2<<<128, 256>>>(tgt, W);
    k_prep_w<<<256, 256>>>(W);
    k_prep_tail<<<256, 256>>>();
    k_cost_hmma<<<512, 256>>>(src);
    k_sink_all<<<128, 512>>>();
    k_pick<<<1, 64>>>();
    k_sink_epi<<<128, 512>>>(out_pi);
    k_ot_final<<<1, 16>>>(out_ot);
    k_gemm_hmma<<<dim3(4, 512), 256>>>(src, bias, out);
    k_ln<<<BB * NN, 128>>>(out, gamma, beta);
}

// round 11
// speedup vs baseline: 2.3081x; 1.1311x over previous
#include <cuda_runtime.h>
#include <cuda_bf16.h>
#include <math.h>
#include <stdint.h>

#define BB 16
#define NN 4096
#define CC 512
#define MM 32
#define NB (BB*NN)
#define EPS_INV 20.0f

// ---------------- scratch (device globals; no allocation) ----------------
__device__ float g_tw2[BB*MM*CC];
__device__ float g_nu[BB*MM];
__device__ int   g_counts[BB*MM];
__device__ float g_Kt[(size_t)MM*NB];
__device__ float g_cost[(size_t)NB*MM];
__device__ float g_pinorm[(size_t)NB*MM];
__device__ float g_vtraj[50*BB*MM];
__device__ float g_errtraj8[50*128];
__device__ float g_otpart[128];
__device__ int   g_kidx;
__device__ uint4 g_WH4[32768], g_WL4[32768];
__device__ uint4 g_TH4[32768], g_TL4[32768];
__device__ uint4 g_YH4[32768], g_YL4[32768];

__device__ __forceinline__ float wred(float v) {
#pragma unroll
    for (int o = 16; o; o >>= 1) v += __shfl_xor_sync(0xffffffffu, v, o);
    return v;
}
__device__ __forceinline__ uint32_t smem_u32(const void* p) {
    uint32_t a;
    asm("{ .reg .u64 t; cvta.to.shared.u64 t, %1; cvt.u32.u64 %0, t; }" : "=r"(a) : "l"(p));
    return a;
}
__device__ __forceinline__ float dsmem_ld(uint32_t laddr, uint32_t rank) {
    uint32_t ra; float v;
    asm("mapa.shared::cluster.u32 %0, %1, %2;" : "=r"(ra) : "r"(laddr), "r"(rank));
    asm volatile("ld.shared::cluster.f32 %0, [%1];" : "=f"(v) : "r"(ra) : "memory");
    return v;
}
__device__ __forceinline__ float2 dsmem_ld2(uint32_t laddr, uint32_t rank) {
    uint32_t ra; float2 v;
    asm("mapa.shared::cluster.u32 %0, %1, %2;" : "=r"(ra) : "r"(laddr), "r"(rank));
    asm volatile("ld.shared::cluster.v2.f32 {%0,%1}, [%2];" : "=f"(v.x), "=f"(v.y) : "r"(ra) : "memory");
    return v;
}
#define CLUSTER_SYNC() do {                                             \
    asm volatile("barrier.cluster.arrive.aligned;" ::: "memory");       \
    asm volatile("barrier.cluster.wait.aligned;" ::: "memory");         \
} while (0)
__device__ __forceinline__ void split4(ushort* hb, ushort* lb, int off, float4 v) {
    __nv_bfloat16 hx = __float2bfloat16(v.x), hy = __float2bfloat16(v.y),
                  hz = __float2bfloat16(v.z), hw = __float2bfloat16(v.w);
    unsigned h0 = ((unsigned)__bfloat16_as_ushort(hy) << 16) | __bfloat16_as_ushort(hx);
    unsigned h1 = ((unsigned)__bfloat16_as_ushort(hw) << 16) | __bfloat16_as_ushort(hz);
    __nv_bfloat16 ax = __float2bfloat16(v.x - __bfloat162float(hx));
    __nv_bfloat16 ay = __float2bfloat16(v.y - __bfloat162float(hy));
    __nv_bfloat16 az = __float2bfloat16(v.z - __bfloat162float(hz));
    __nv_bfloat16 aw = __float2bfloat16(v.w - __bfloat162float(hw));
    unsigned l0 = ((unsigned)__bfloat16_as_ushort(ay) << 16) | __bfloat16_as_ushort(ax);
    unsigned l1 = ((unsigned)__bfloat16_as_ushort(aw) << 16) | __bfloat16_as_ushort(az);
    *(uint2*)(hb + off) = make_uint2(h0, h1);
    *(uint2*)(lb + off) = make_uint2(l0, l1);
}
#define LDSM4(r, a)                                                                      \
    asm volatile("ldmatrix.sync.aligned.m8n8.x4.shared.b16 {%0,%1,%2,%3}, [%4];"         \
        : "=r"((r)[0]), "=r"((r)[1]), "=r"((r)[2]), "=r"((r)[3]) : "r"(a))
#define MMA16816(d, a, b0, b1)                                                           \
    asm volatile("mma.sync.aligned.m16n8k16.row.col.f32.bf16.bf16.f32 "                  \
        "{%0,%1,%2,%3}, {%4,%5,%6,%7}, {%8,%9}, {%0,%1,%2,%3};"                          \
        : "+f"((d)[0]), "+f"((d)[1]), "+f"((d)[2]), "+f"((d)[3])                         \
        : "r"((a)[0]), "r"((a)[1]), "r"((a)[2]), "r"((a)[3]), "r"(b0), "r"(b1))

// ---------------- init ----------------
__global__ void k_init() {
    int t = threadIdx.x;                             // <<<1,512>>>
    if (t < BB * MM) g_counts[t] = 0;
}

// ---------------- nu ----------------
__global__ void k_nu_count(const float* __restrict__ score) {
    int idx = blockIdx.x * 256 + threadIdx.x;
    int b = idx >> 12, hw = idx & 4095;
    const float* p = score + (size_t)b * MM * NN + hw;
    float best = p[0]; int bi = 0;
#pragma unroll
    for (int k = 1; k < MM; k++) {
        float v = p[(size_t)k * NN];
        if (v > best) { best = v; bi = k; }
    }
    atomicAdd(&g_counts[b * MM + bi], 1);
}

__global__ void k_nu_final() {
    int b = blockIdx.x, k = threadIdx.x;             // <<<16,32>>>
    float c = (float)g_counts[b * MM + k];
    float nu = c / (4096.0f + 1e-8f) + 1e-6f;
    float s = wred(nu);
    g_nu[b * MM + k] = nu / s;
}

// ---------------- normalize target rows -> bf16 hi/lo yn images ----------------
__global__ void k_ynorm(const float* __restrict__ tgt) {
    int row = blockIdx.x;                            // <<<512,128>>>
    const float4* p = (const float4*)(tgt + (size_t)row * CC);
    int t = threadIdx.x;
    float4 v = p[t];
    float s = wred(v.x * v.x + v.y * v.y + v.z * v.z + v.w * v.w);
    __shared__ float ws[4];
    if ((t & 31) == 0) ws[t >> 5] = s;
    __syncthreads();
    float inv = rsqrtf(ws[0] + ws[1] + ws[2] + ws[3]);
    float4 o = make_float4(v.x * inv, v.y * inv, v.z * inv, v.w * inv);
    split4((ushort*)g_YH4, (ushort*)g_YL4, row * 512 + t * 4, o);
}

// ---------------- TW2 = target @ W2 ----------------
__global__ void __launch_bounds__(256) k_tw2(const float* __restrict__ tgt,
                                             const float* __restrict__ W) {
    __shared__ float ts[32 * 128];
    int blk = blockIdx.x;                            // <<<128,256>>>
    int b = blk >> 3, ct = blk & 7;
    int t = threadIdx.x;
    int c = ct * 64 + (t & 63);
    int mg = t >> 6;
    float acc[8];
#pragma unroll
    for (int i = 0; i < 8; i++) acc[i] = 0.0f;
    for (int kt = 0; kt < 4; kt++) {
        __syncthreads();
        for (int i = t; i < 32 * 128 / 4; i += 256) {
            int m = i >> 5, k4 = i & 31;
            ((float4*)ts)[i] = ((const float4*)(tgt + ((size_t)(b * 32 + m)) * CC + kt * 128))[k4];
        }
        __syncthreads();
        const float* Wp = W + (size_t)(CC + kt * 128) * CC + c;
        for (int k = 0; k < 128; k++) {
            float w = Wp[(size_t)k * CC];
#pragma unroll
            for (int i = 0; i < 8; i++) acc[i] += ts[(mg * 8 + i) * 128 + k] * w;
        }
    }
#pragma unroll
    for (int i = 0; i < 8; i++)
        g_tw2[(size_t)b * MM * CC + (size_t)(mg * 8 + i) * CC + c] = acc[i];
}

// ---------------- prep bf16 hi/lo images ----------------
__global__ void k_prep_w(const float* __restrict__ W) {
    int idx = blockIdx.x * 256 + threadIdx.x;        // <<<256,256>>>
    int n = idx & 511, kq = idx >> 9;
    int k0 = kq * 4;
    float4 v = make_float4(W[(size_t)k0 * CC + n], W[(size_t)(k0 + 1) * CC + n],
                           W[(size_t)(k0 + 2) * CC + n], W[(size_t)(k0 + 3) * CC + n]);
    split4((ushort*)g_WH4, (ushort*)g_WL4, n * 512 + k0, v);
}
__global__ void k_prep_tail() {
    int idx = blockIdx.x * 256 + threadIdx.x;        // <<<256,256>>>
    int b = idx >> 12, rem = idx & 4095;
    int n = rem & 511, k0 = ((rem >> 9) & 7) * 4;
    const float* tp = g_tw2 + (size_t)b * MM * CC;
    float4 v = make_float4(tp[(size_t)k0 * CC + n], tp[(size_t)(k0 + 1) * CC + n],
                           tp[(size_t)(k0 + 2) * CC + n], tp[(size_t)(k0 + 3) * CC + n]);
    split4((ushort*)g_TH4, (ushort*)g_TL4, b * 16384 + n * 32 + k0, v);
}

// ---------------- cost / Gibbs matrix via HMMA (validated R8) ----------------
__global__ void __launch_bounds__(256) k_cost_hmma(const float* __restrict__ src) {
    __shared__ char sm[30208];
    ushort* Ah = (ushort*)sm;
    ushort* Al = (ushort*)(sm + 10240);
    ushort* Bh = (ushort*)(sm + 20480);
    ushort* Bl = (ushort*)(sm + 23040);
    float* nrmp  = (float*)(sm + 25600);
    float* sinv  = (float*)(sm + 29696);
    float* scost = (float*)sm;
    int t = threadIdx.x, lane = t & 31, w = t >> 5;
    int r0 = blockIdx.x * 128, b = blockIdx.x >> 5;  // <<<512,256>>>

    float acc[4][4];
#pragma unroll
    for (int i = 0; i < 4; i++)
#pragma unroll
        for (int q = 0; q < 4; q++) acc[i][q] = 0.0f;
    float nrm[4] = {0.0f, 0.0f, 0.0f, 0.0f};
    int arow = lane & 15, ak = (lane >> 4) * 8;
    int brow = (lane & 7) + ((lane >> 4) & 1) * 8, bk = ((lane >> 3) & 1) * 8;
    const ushort* yh = (const ushort*)g_YH4 + (size_t)b * 16384;
    const ushort* yl = (const ushort*)g_YL4 + (size_t)b * 16384;

    for (int c = 0; c < 16; c++) {
        __syncthreads();
        const float* Ap = src + (size_t)r0 * CC + c * 32;
#pragma unroll
        for (int j = 0; j < 4; j++) {
            int e = t + j * 256;
            int row = e >> 3, kq = e & 7;
            float4 v = *(const float4*)(Ap + (size_t)row * CC + kq * 4);
            nrm[j] += v.x * v.x + v.y * v.y + v.z * v.z + v.w * v.w;
            split4(Ah, Al, row * 40 + kq * 4, v);
        }
        if (t < 128) {
            int row = t >> 2, q = t & 3;
            *(uint4*)(Bh + row * 40 + q * 8) = *(const uint4*)(yh + (size_t)row * 512 + c * 32 + q * 8);
        } else {
            int tt = t - 128;
            int row = tt >> 2, q = tt & 3;
            *(uint4*)(Bl + row * 40 + q * 8) = *(const uint4*)(yl + (size_t)row * 512 + c * 32 + q * 8);
        }
        __syncthreads();
#pragma unroll
        for (int ks = 0; ks < 2; ks++) {
            int k_off = ks * 16;
#pragma unroll
            for (int pass = 0; pass < 4; pass++) {
                ushort* Asel = (pass >= 2) ? Al : Ah;
                ushort* Bsel = (pass & 1) ? Bl : Bh;
                uint32_t a[4];
                LDSM4(a, smem_u32(Asel + (w * 16 + arow) * 40 + k_off + ak));
                uint32_t bb2[2][4];
#pragma unroll
                for (int nj2 = 0; nj2 < 2; nj2++)
                    LDSM4(bb2[nj2], smem_u32(Bsel + (nj2 * 16 + brow) * 40 + k_off + bk));
                MMA16816(acc[0], a, bb2[0][0], bb2[0][1]);
                MMA16816(acc[1], a, bb2[0][2], bb2[0][3]);
                MMA16816(acc[2], a, bb2[1][0], bb2[1][1]);
                MMA16816(acc[3], a, bb2[1][2], bb2[1][3]);
            }
        }
    }
    __syncthreads();
#pragma unroll
    for (int j = 0; j < 4; j++) nrmp[(t & 7) * 128 + (t >> 3) + 32 * j] = nrm[j];
    __syncthreads();
    if (t < 128) {
        float s = 0.0f;
#pragma unroll
        for (int i = 0; i < 8; i++) s += nrmp[i * 128 + t];
        sinv[t] = rsqrtf(s);
    }
    __syncthreads();
    int g4 = lane >> 2, l2 = (lane & 3) * 2;
    int rA = w * 16 + g4, rB = rA + 8;
    float ia = sinv[rA], ib = sinv[rB];
#pragma unroll
    for (int nj = 0; nj < 4; nj++) {
        int cc = nj * 8 + l2;
        float c00 = 1.0f - acc[nj][0] * ia, c01 = 1.0f - acc[nj][1] * ia;
        float c10 = 1.0f - acc[nj][2] * ib, c11 = 1.0f - acc[nj][3] * ib;
        *(float2*)(g_cost + (size_t)(r0 + rA) * MM + cc) = make_float2(c00, c01);
        *(float2*)(g_cost + (size_t)(r0 + rB) * MM + cc) = make_float2(c10, c11);
        scost[cc * 132 + rA] = c00; scost[(cc + 1) * 132 + rA] = c01;
        scost[cc * 132 + rB] = c10; scost[(cc + 1) * 132 + rB] = c11;
    }
    __syncthreads();
    for (int i = t; i < 4096; i += 256) {
        int m = i >> 7, r = i & 127;
        g_Kt[(size_t)m * NB + r0 + r] = expf(scost[m * 132 + r] * -EPS_INV);
    }
}

// ---------------- Sinkhorn: 50 iterations, one kernel, 8-CTA clusters ----------------
// Transpose-reduce network: same xor-pair tree as wred -> bit-identical partials.
__global__ void __launch_bounds__(512, 1) __cluster_dims__(8, 1, 1)
k_sink_all() {
    int g = blockIdx.x, b = g >> 3, t = threadIdx.x; // <<<128,512>>>
    int lane = t & 31, warp = t >> 5, rank0 = ((g & 7) == 0);
    __shared__ float sv[32], snu[32];
    __shared__ float cpart[2][34];
    __shared__ float wsum[16][33], werr[16];
    if (t < 32) { sv[t] = 0.0f; snu[t] = g_nu[b * 32 + t]; }
    __syncthreads();

    int row = g * 512 + t;
    float kk[32];
#pragma unroll
    for (int m = 0; m < 32; m++) kk[m] = g_Kt[(size_t)m * NB + row];
    float u = 0.0f;
    const float mu = 1.0f / 4096.0f;

    for (int it = 0; it < 50; it++) {
        float denom = 0.0f;
#pragma unroll
        for (int m = 0; m < 32; m++) denom += kk[m] * sv[m];
        float un = mu / (denom + 1e-8f);
        float du = fabsf(un - u);
        u = un;
        // transpose-reduce: lane m ends with sum over lanes of kk[m]*un
        float red[32];
#pragma unroll
        for (int m = 0; m < 32; m++) red[m] = kk[m] * un;
#pragma unroll
        for (int o = 16; o; o >>= 1) {
            bool hi = (lane & o) != 0;
#pragma unroll
            for (int j = 0; j < o; j++) {
                float send = hi ? red[j] : red[j + o];
                float recv = __shfl_xor_sync(0xffffffffu, send, o);
                red[j] = (hi ? red[j + o] : red[j]) + recv;
            }
        }
        wsum[warp][lane] = red[0];
        du = wred(du);
        if (lane == 0) werr[warp] = du;
        __syncthreads();
        int p = it & 1;
        if (t < 32) {
            float a = 0.0f;
#pragma unroll
            for (int w2 = 0; w2 < 16; w2++) a += wsum[w2][t];
            cpart[p][t] = a;
        } else if (t == 32) {
            float e = 0.0f;
#pragma unroll
            for (int w2 = 0; w2 < 16; w2++) e += werr[w2];
            cpart[p][32] = e;
            g_errtraj8[it * 128 + g] = e;
        }
        CLUSTER_SYNC();
        if (t < 32) {
            uint32_t laddr = smem_u32(&cpart[p][t]);
            float a = 0.0f;
#pragma unroll
            for (int r = 0; r < 8; r++) a += dsmem_ld(laddr, (uint32_t)r);
            float v = snu[t] / (a + 1e-8f);
            sv[t] = v;
            if (rank0) g_vtraj[(it * 16 + b) * 32 + t] = v;
        }
        __syncthreads();
    }
    CLUSTER_SYNC();
}

// pick kept iteration
__global__ void k_pick() {
    __shared__ int midx;
    int t = threadIdx.x;                             // <<<1,64>>>
    if (t == 0) midx = 49;
    __syncthreads();
    if (t < 50) {
        float e = 0.0f;
        const float* ep = g_errtraj8 + t * 128;
        for (int k = 0; k < 128; k++) e += ep[k];
        if (e * (1.0f / 16.0f) < 0.1f) atomicMin(&midx, t);
    }
    __syncthreads();
    if (t == 0) g_kidx = midx;
}

// ---------------- Sinkhorn epilogue ----------------
__global__ void __launch_bounds__(512) k_sink_epi(float* __restrict__ out_pi) {
    int g = blockIdx.x, b = g >> 3, t = threadIdx.x; // <<<128,512>>>
    int lane = t & 31, warp = t >> 5;
    __shared__ float sv[32], svp[32], werr[16];
    int kidx = g_kidx;
    if (t < 32) {
        sv[t] = g_vtraj[(kidx * 16 + b) * 32 + t];
        svp[t] = (kidx > 0) ? g_vtraj[((kidx - 1) * 16 + b) * 32 + t] : 0.0f;
    }
    __syncthreads();
    int row = g * 512 + t;
    float kk[32], pi[32];
#pragma unroll
    for (int m = 0; m < 32; m++) kk[m] = g_Kt[(size_t)m * NB + row];
    float denom = 0.0f;
#pragma unroll
    for (int m = 0; m < 32; m++) denom += kk[m] * svp[m];
    float u = (1.0f / 4096.0f) / (denom + 1e-8f);
    float rs = 0.0f;
#pragma unroll
    for (int m = 0; m < 32; m++) { pi[m] = u * kk[m] * sv[m]; rs += pi[m]; }
    size_t rowbase = (size_t)row * MM;
#pragma unroll
    for (int m = 0; m < 32; m += 4)
        *(float4*)(out_pi + rowbase + m) = make_float4(pi[m], pi[m + 1], pi[m + 2], pi[m + 3]);
    float inv = 1.0f / (rs + 1e-8f);
#pragma unroll
    for (int m = 0; m < 32; m += 4)
        *(float4*)(g_pinorm + rowbase + m) =
            make_float4(pi[m] * inv, pi[m + 1] * inv, pi[m + 2] * inv, pi[m + 3] * inv);
    float oc = 0.0f;
#pragma unroll
    for (int m = 0; m < 32; m += 4) {
        float4 cq = *(const float4*)(g_cost + rowbase + m);
        oc += pi[m] * cq.x + pi[m + 1] * cq.y + pi[m + 2] * cq.z + pi[m + 3] * cq.w;
    }
    oc = wred(oc);
    if (lane == 0) werr[warp] = oc;
    __syncthreads();
    if (t == 0) {
        float e = 0.0f;
#pragma unroll
        for (int w = 0; w < 16; w++) e += werr[w];
        g_otpart[g] = e;
    }
}

__global__ void k_ot_final(float* __restrict__ out_ot) {
    int b = threadIdx.x;                             // <<<1,16>>>
    float e = 0.0f;
#pragma unroll
    for (int k = 0; k < 8; k++) e += g_otpart[b * 8 + k];
    out_ot[b] = e;
}

// ---------------- pipelined HMMA fused GEMM + clustered LayerNorm ----------------
// Cluster = 4 column-tile CTAs of one 128-row block; LN row stats via DSMEM.
__global__ void __launch_bounds__(256) __cluster_dims__(4, 1, 1)
k_gemm_hmma(const float* __restrict__ src, const float* __restrict__ bias,
            const float* __restrict__ gamma, const float* __restrict__ beta,
            float* __restrict__ out) {
    __shared__ uint4 sAh4[640], sAl4[640], sBh4[640], sBl4[640];
    __shared__ float sstat[2][128][2];               // [n-half][row][sum,sq]
    __shared__ float2 cst[128];                      // cluster-visible row partials
    __shared__ float2 srow[128];                     // (mean, rstd)
    ushort* Ah = (ushort*)sAh4; ushort* Al = (ushort*)sAl4;
    ushort* Bh = (ushort*)sBh4; ushort* Bl = (ushort*)sBl4;
    int t = threadIdx.x, lane = t & 31, w = t >> 5;
    int r0 = blockIdx.y * 128, c0 = blockIdx.x * 128;
    int b = r0 >> 12;
    int wm = (w & 3) * 32, wn = (w >> 2) * 64;

    float acc[2][8][4];
#pragma unroll
    for (int i = 0; i < 2; i++)
#pragma unroll
        for (int j = 0; j < 8; j++)
#pragma unroll
            for (int q = 0; q < 4; q++) acc[i][j][q] = 0.0f;

    int arow = lane & 15, ak = (lane >> 4) * 8;
    int brow = (lane & 7) + ((lane >> 4) & 1) * 8, bk = ((lane >> 3) & 1) * 8;
    int aRow = t >> 3, aKq = t & 7;
    int bRow = t >> 2, bQ = t & 3;

    float4 ra[4];
    uint4 rbh[2], rbl[2];
    {
        const float* Ap = src + (size_t)r0 * CC;
#pragma unroll
        for (int j = 0; j < 4; j++)
            ra[j] = *(const float4*)(Ap + (size_t)(aRow + 32 * j) * CC + aKq * 4);
        const ushort* bh = (const ushort*)g_WH4 + (size_t)c0 * 512;
        const ushort* bl = (const ushort*)g_WL4 + (size_t)c0 * 512;
#pragma unroll
        for (int j = 0; j < 2; j++) {
            rbh[j] = *(const uint4*)(bh + (size_t)(bRow + 64 * j) * 512 + bQ * 8);
            rbl[j] = *(const uint4*)(bl + (size_t)(bRow + 64 * j) * 512 + bQ * 8);
        }
    }

    for (int c = 0; c < 17; c++) {
#pragma unroll
        for (int j = 0; j < 4; j++)
            split4(Ah, Al, (aRow + 32 * j) * 40 + aKq * 4, ra[j]);
#pragma unroll
        for (int j = 0; j < 2; j++) {
            int row = bRow + 64 * j;
            *(uint4*)(Bh + row * 40 + bQ * 8) = rbh[j];
            *(uint4*)(Bl + row * 40 + bQ * 8) = rbl[j];
        }
        __syncthreads();
        if (c < 16) {
            int cn = c + 1;
            if (cn < 16) {
                const float* Ap = src + (size_t)r0 * CC + cn * 32;
#pragma unroll
                for (int j = 0; j < 4; j++)
                    ra[j] = *(const float4*)(Ap + (size_t)(aRow + 32 * j) * CC + aKq * 4);
                const ushort* bh = (const ushort*)g_WH4 + (size_t)c0 * 512 + cn * 32;
                const ushort* bl = (const ushort*)g_WL4 + (size_t)c0 * 512 + cn * 32;
#pragma unroll
                for (int j = 0; j < 2; j++) {
                    rbh[j] = *(const uint4*)(bh + (size_t)(bRow + 64 * j) * 512 + bQ * 8);
                    rbl[j] = *(const uint4*)(bl + (size_t)(bRow + 64 * j) * 512 + bQ * 8);
                }
            } else {
                const float* Ap = g_pinorm + (size_t)r0 * MM;
#pragma unroll
                for (int j = 0; j < 4; j++)
                    ra[j] = *(const float4*)(Ap + (size_t)(aRow + 32 * j) * MM + aKq * 4);
                const ushort* bh = (const ushort*)g_TH4 + (size_t)b * 16384 + (size_t)c0 * 32;
                const ushort* bl = (const ushort*)g_TL4 + (size_t)b * 16384 + (size_t)c0 * 32;
#pragma unroll
                for (int j = 0; j < 2; j++) {
                    rbh[j] = *(const uint4*)(bh + (size_t)(bRow + 64 * j) * 32 + bQ * 8);
                    rbl[j] = *(const uint4*)(bl + (size_t)(bRow + 64 * j) * 32 + bQ * 8);
                }
            }
        }
#pragma unroll
        for (int ks = 0; ks < 2; ks++) {
            int k_off = ks * 16;
#pragma unroll
            for (int pass = 0; pass < 3; pass++) {
                ushort* Asel = (pass == 2) ? Al : Ah;
                ushort* Bsel = (pass == 1) ? Bl : Bh;
                uint32_t a[2][4];
#pragma unroll
                for (int mi = 0; mi < 2; mi++)
                    LDSM4(a[mi], smem_u32(Asel + (wm + mi * 16 + arow) * 40 + k_off + ak));
                uint32_t bb[4][4];
#pragma unroll
                for (int nj2 = 0; nj2 < 4; nj2++)
                    LDSM4(bb[nj2], smem_u32(Bsel + (wn + nj2 * 16 + brow) * 40 + k_off + bk));
#pragma unroll
                for (int mi = 0; mi < 2; mi++)
#pragma unroll
                    for (int nj2 = 0; nj2 < 4; nj2++) {
                        MMA16816(acc[mi][nj2 * 2],     a[mi], bb[nj2][0], bb[nj2][1]);
                        MMA16816(acc[mi][nj2 * 2 + 1], a[mi], bb[nj2][2], bb[nj2][3]);
                    }
            }
        }
        __syncthreads();
    }

    // ---- epilogue: +bias, row stats, cluster LN, store ----
    int g4 = lane >> 2, l2 = (lane & 3) * 2;
#pragma unroll
    for (int nj = 0; nj < 8; nj++) {
        float2 bi = *(const float2*)(bias + c0 + wn + nj * 8 + l2);
#pragma unroll
        for (int mi = 0; mi < 2; mi++) {
            acc[mi][nj][0] += bi.x; acc[mi][nj][1] += bi.y;
            acc[mi][nj][2] += bi.x; acc[mi][nj][3] += bi.y;
        }
    }
    // per-thread partial sum/sq for its 4 rows (16 values each)
    float rs4[4], rq4[4];
#pragma unroll
    for (int mi = 0; mi < 2; mi++)
#pragma unroll
        for (int h = 0; h < 2; h++) {
            float s = 0.0f, q = 0.0f;
#pragma unroll
            for (int nj = 0; nj < 8; nj++) {
                float a0 = acc[mi][nj][h * 2], a1 = acc[mi][nj][h * 2 + 1];
                s += a0 + a1; q += a0 * a0 + a1 * a1;
            }
            rs4[mi * 2 + h] = s; rq4[mi * 2 + h] = q;
        }
#pragma unroll
    for (int i = 0; i < 4; i++) {
        rs4[i] += __shfl_xor_sync(0xffffffffu, rs4[i], 1);
        rs4[i] += __shfl_xor_sync(0xffffffffu, rs4[i], 2);
        rq4[i] += __shfl_xor_sync(0xffffffffu, rq4[i], 1);
        rq4[i] += __shfl_xor_sync(0xffffffffu, rq4[i], 2);
    }
    int nh = w >> 2;
    if ((lane & 3) == 0) {
#pragma unroll
        for (int mi = 0; mi < 2; mi++)
#pragma unroll
            for (int h = 0; h < 2; h++) {
                int lr = wm + mi * 16 + h * 8 + g4;
                sstat[nh][lr][0] = rs4[mi * 2 + h];
                sstat[nh][lr][1] = rq4[mi * 2 + h];
            }
    }
    __syncthreads();
    if (t < 128)
        cst[t] = make_float2(sstat[0][t][0] + sstat[1][t][0],
                             sstat[0][t][1] + sstat[1][t][1]);
    CLUSTER_SYNC();
    if (t < 128) {
        uint32_t laddr = smem_u32(&cst[t]);
        float s = 0.0f, q = 0.0f;
#pragma unroll
        for (int r = 0; r < 4; r++) {
            float2 v = dsmem_ld2(laddr, (uint32_t)r);
            s += v.x; q += v.y;
        }
        float mean = s * (1.0f / 512.0f);
        float var = q * (1.0f / 512.0f) - mean * mean;
        srow[t] = make_float2(mean, rsqrtf(var + 1e-5f));
    }
    __syncthreads();
#pragma unroll
    for (int mi = 0; mi < 2; mi++)
#pragma unroll
        for (int nj = 0; nj < 8; nj++) {
            int lr = wm + mi * 16 + g4;
            int cc = c0 + wn + nj * 8 + l2;
            float2 gm = *(const float2*)(gamma + cc);
            float2 bt = *(const float2*)(beta + cc);
            float2 st0 = srow[lr], st1 = srow[lr + 8];
            *(float2*)(out + (size_t)(r0 + lr) * CC + cc) = make_float2(
                (acc[mi][nj][0] - st0.x) * st0.y * gm.x + bt.x,
                (acc[mi][nj][1] - st0.x) * st0.y * gm.y + bt.y);
            *(float2*)(out + (size_t)(r0 + lr + 8) * CC + cc) = make_float2(
                (acc[mi][nj][2] - st1.x) * st1.y * gm.x + bt.x,
                (acc[mi][nj][3] - st1.x) * st1.y * gm.y + bt.y);
        }
    CLUSTER_SYNC();
}

// ---------------- launch ----------------
extern "C" void kernel_launch(void* const* d_in, const int* in_sizes, int n_in,
                              void* d_out, int out_size) {
    const float* src   = (const float*)d_in[0];
    const float* tgt   = (const float*)d_in[1];
    const float* score = (const float*)d_in[2];
    const float* W     = (const float*)d_in[3];
    const float* bias  = (const float*)d_in[4];
    const float* gamma = (const float*)d_in[5];
    const float* beta  = (const float*)d_in[6];
    float* out = (float*)d_out;

    const size_t OUT_OT = (size_t)BB * NN * CC;
    float* out_ot = out + OUT_OT;
    float* out_pi = out + OUT_OT + BB;

    k_init<<<1, 512>>>();
    k_nu_count<<<(BB * NN) / 256, 256>>>(score);
    k_nu_final<<<BB, MM>>>();
    k_ynorm<<<BB * MM, 128>>>(tgt);
    k_tw2<<<128, 256>>>(tgt, W);
    k_prep_w<<<256, 256>>>(W);
    k_prep_tail<<<256, 256>>>();
    k_cost_hmma<<<512, 256>>>(src);
    k_sink_all<<<128, 512>>>();
    k_pick<<<1, 64>>>();
    k_sink_epi<<<128, 512>>>(out_pi);
    k_ot_final<<<1, 16>>>(out_ot);
    k_gemm_hmma<<<dim3(4, 512), 256>>>(src, bias, gamma, beta, out);
}

// round 14
// speedup vs baseline: 2.4444x; 1.0591x over previous
#include <cuda_runtime.h>
#include <cuda_bf16.h>
#include <math.h>
#include <stdint.h>

#define BB 16
#define NN 4096
#define CC 512
#define MM 32
#define NB (BB*NN)
#define EPS_INV 20.0f

// ---------------- scratch (device globals; no allocation) ----------------
__device__ float g_tw2[BB*MM*CC];
__device__ float g_nu[BB*MM];
__device__ int   g_counts[BB*MM];
__device__ float g_Kt[(size_t)MM*NB];
__device__ float g_cost[(size_t)NB*MM];
__device__ float g_rnorm[NB];               // rsqrt(row norm^2) of src
__device__ float g_vtraj[50*BB*MM];
__device__ float g_errtraj8[50*128];
__device__ float g_otpart[128];
__device__ int   g_kidx;
// bf16 hi/lo images
__device__ uint4 g_WH4[32768], g_WL4[32768];        // W1^T [n][k] 512x512
__device__ uint4 g_TH4[32768], g_TL4[32768];        // TW2^T [b][n][k] 512x32
__device__ uint4 g_YH4[32768], g_YL4[32768];        // yn [b][m][k] 32x512
__device__ uint4 g_SH4[4194304], g_SL4[4194304];    // src [row][k] 65536x512 (64 MB each)
__device__ uint4 g_PH4[262144], g_PL4[262144];      // pinorm [row][m] 65536x32 (4 MB each)

__device__ __forceinline__ float wred(float v) {
#pragma unroll
    for (int o = 16; o; o >>= 1) v += __shfl_xor_sync(0xffffffffu, v, o);
    return v;
}
__device__ __forceinline__ uint32_t smem_u32(const void* p) {
    uint32_t a;
    asm("{ .reg .u64 t; cvta.to.shared.u64 t, %1; cvt.u32.u64 %0, t; }" : "=r"(a) : "l"(p));
    return a;
}
__device__ __forceinline__ float dsmem_ld(uint32_t laddr, uint32_t rank) {
    uint32_t ra; float v;
    asm("mapa.shared::cluster.u32 %0, %1, %2;" : "=r"(ra) : "r"(laddr), "r"(rank));
    asm volatile("ld.shared::cluster.f32 %0, [%1];" : "=f"(v) : "r"(ra) : "memory");
    return v;
}
__device__ __forceinline__ float2 dsmem_ld2(uint32_t laddr, uint32_t rank) {
    uint32_t ra; float2 v;
    asm("mapa.shared::cluster.u32 %0, %1, %2;" : "=r"(ra) : "r"(laddr), "r"(rank));
    asm volatile("ld.shared::cluster.v2.f32 {%0,%1}, [%2];" : "=f"(v.x), "=f"(v.y) : "r"(ra) : "memory");
    return v;
}
#define CLUSTER_SYNC() do {                                             \
    asm volatile("barrier.cluster.arrive.aligned;" ::: "memory");       \
    asm volatile("barrier.cluster.wait.aligned;" ::: "memory");         \
} while (0)
__device__ __forceinline__ void split4(ushort* hb, ushort* lb, int off, float4 v) {
    __nv_bfloat16 hx = __float2bfloat16(v.x), hy = __float2bfloat16(v.y),
                  hz = __float2bfloat16(v.z), hw = __float2bfloat16(v.w);
    unsigned h0 = ((unsigned)__bfloat16_as_ushort(hy) << 16) | __bfloat16_as_ushort(hx);
    unsigned h1 = ((unsigned)__bfloat16_as_ushort(hw) << 16) | __bfloat16_as_ushort(hz);
    __nv_bfloat16 ax = __float2bfloat16(v.x - __bfloat162float(hx));
    __nv_bfloat16 ay = __float2bfloat16(v.y - __bfloat162float(hy));
    __nv_bfloat16 az = __float2bfloat16(v.z - __bfloat162float(hz));
    __nv_bfloat16 aw = __float2bfloat16(v.w - __bfloat162float(hw));
    unsigned l0 = ((unsigned)__bfloat16_as_ushort(ay) << 16) | __bfloat16_as_ushort(ax);
    unsigned l1 = ((unsigned)__bfloat16_as_ushort(aw) << 16) | __bfloat16_as_ushort(az);
    *(uint2*)(hb + off) = make_uint2(h0, h1);
    *(uint2*)(lb + off) = make_uint2(l0, l1);
}
#define LDSM4(r, a)                                                                      \
    asm volatile("ldmatrix.sync.aligned.m8n8.x4.shared.b16 {%0,%1,%2,%3}, [%4];"         \
        : "=r"((r)[0]), "=r"((r)[1]), "=r"((r)[2]), "=r"((r)[3]) : "r"(a))
#define MMA16816(d, a, b0, b1)                                                           \
    asm volatile("mma.sync.aligned.m16n8k16.row.col.f32.bf16.bf16.f32 "                  \
        "{%0,%1,%2,%3}, {%4,%5,%6,%7}, {%8,%9}, {%0,%1,%2,%3};"                          \
        : "+f"((d)[0]), "+f"((d)[1]), "+f"((d)[2]), "+f"((d)[3])                         \
        : "r"((a)[0]), "r"((a)[1]), "r"((a)[2]), "r"((a)[3]), "r"(b0), "r"(b1))

// ---------------- init ----------------
__global__ void k_init() {
    int t = threadIdx.x;                             // <<<1,512>>>
    if (t < BB * MM) g_counts[t] = 0;
}

// ---------------- nu ----------------
__global__ void k_nu_count(const float* __restrict__ score) {
    int idx = blockIdx.x * 256 + threadIdx.x;
    int b = idx >> 12, hw = idx & 4095;
    const float* p = score + (size_t)b * MM * NN + hw;
    float best = p[0]; int bi = 0;
#pragma unroll
    for (int k = 1; k < MM; k++) {
        float v = p[(size_t)k * NN];
        if (v > best) { best = v; bi = k; }
    }
    atomicAdd(&g_counts[b * MM + bi], 1);
}

__global__ void k_nu_final() {
    int b = blockIdx.x, k = threadIdx.x;             // <<<16,32>>>
    float c = (float)g_counts[b * MM + k];
    float nu = c / (4096.0f + 1e-8f) + 1e-6f;
    float s = wred(nu);
    g_nu[b * MM + k] = nu / s;
}

// ---------------- src -> bf16 hi/lo images + row norms ----------------
__global__ void k_prep_src(const float* __restrict__ src) {
    int row = blockIdx.x;                            // <<<65536,128>>>
    const float4* p = (const float4*)(src + (size_t)row * CC);
    int t = threadIdx.x;
    float4 v = p[t];
    float s = wred(v.x * v.x + v.y * v.y + v.z * v.z + v.w * v.w);
    __shared__ float ws[4];
    if ((t & 31) == 0) ws[t >> 5] = s;
    __syncthreads();
    if (t == 0) g_rnorm[row] = rsqrtf(ws[0] + ws[1] + ws[2] + ws[3]);
    split4((ushort*)g_SH4, (ushort*)g_SL4, (int)(row * 512 + t * 4), v);
}

// ---------------- normalize target rows -> bf16 hi/lo yn images ----------------
__global__ void k_ynorm(const float* __restrict__ tgt) {
    int row = blockIdx.x;                            // <<<512,128>>>
    const float4* p = (const float4*)(tgt + (size_t)row * CC);
    int t = threadIdx.x;
    float4 v = p[t];
    float s = wred(v.x * v.x + v.y * v.y + v.z * v.z + v.w * v.w);
    __shared__ float ws[4];
    if ((t & 31) == 0) ws[t >> 5] = s;
    __syncthreads();
    float inv = rsqrtf(ws[0] + ws[1] + ws[2] + ws[3]);
    float4 o = make_float4(v.x * inv, v.y * inv, v.z * inv, v.w * inv);
    split4((ushort*)g_YH4, (ushort*)g_YL4, row * 512 + t * 4, o);
}

// ---------------- TW2 = target @ W2 ----------------
__global__ void __launch_bounds__(256) k_tw2(const float* __restrict__ tgt,
                                             const float* __restrict__ W) {
    __shared__ float ts[32 * 128];
    int blk = blockIdx.x;                            // <<<128,256>>>
    int b = blk >> 3, ct = blk & 7;
    int t = threadIdx.x;
    int c = ct * 64 + (t & 63);
    int mg = t >> 6;
    float acc[8];
#pragma unroll
    for (int i = 0; i < 8; i++) acc[i] = 0.0f;
    for (int kt = 0; kt < 4; kt++) {
        __syncthreads();
        for (int i = t; i < 32 * 128 / 4; i += 256) {
            int m = i >> 5, k4 = i & 31;
            ((float4*)ts)[i] = ((const float4*)(tgt + ((size_t)(b * 32 + m)) * CC + kt * 128))[k4];
        }
        __syncthreads();
        const float* Wp = W + (size_t)(CC + kt * 128) * CC + c;
        for (int k = 0; k < 128; k++) {
            float w = Wp[(size_t)k * CC];
#pragma unroll
            for (int i = 0; i < 8; i++) acc[i] += ts[(mg * 8 + i) * 128 + k] * w;
        }
    }
#pragma unroll
    for (int i = 0; i < 8; i++)
        g_tw2[(size_t)b * MM * CC + (size_t)(mg * 8 + i) * CC + c] = acc[i];
}

// ---------------- prep bf16 hi/lo images of W1^T and TW2^T ----------------
__global__ void k_prep_w(const float* __restrict__ W) {
    int idx = blockIdx.x * 256 + threadIdx.x;        // <<<256,256>>>
    int n = idx & 511, kq = idx >> 9;
    int k0 = kq * 4;
    float4 v = make_float4(W[(size_t)k0 * CC + n], W[(size_t)(k0 + 1) * CC + n],
                           W[(size_t)(k0 + 2) * CC + n], W[(size_t)(k0 + 3) * CC + n]);
    split4((ushort*)g_WH4, (ushort*)g_WL4, n * 512 + k0, v);
}
__global__ void k_prep_tail() {
    int idx = blockIdx.x * 256 + threadIdx.x;        // <<<256,256>>>
    int b = idx >> 12, rem = idx & 4095;
    int n = rem & 511, k0 = ((rem >> 9) & 7) * 4;
    const float* tp = g_tw2 + (size_t)b * MM * CC;
    float4 v = make_float4(tp[(size_t)k0 * CC + n], tp[(size_t)(k0 + 1) * CC + n],
                           tp[(size_t)(k0 + 2) * CC + n], tp[(size_t)(k0 + 3) * CC + n]);
    split4((ushort*)g_TH4, (ushort*)g_TL4, b * 16384 + n * 32 + k0, v);
}

// ---------------- cost / Gibbs via HMMA (3-pass, pure-copy operands, prefetch) ----------------
__global__ void __launch_bounds__(256) k_cost_hmma() {
    __shared__ char sm[25600];
    ushort* Ah = (ushort*)sm;                        // 128 x 40
    ushort* Al = (ushort*)(sm + 10240);
    ushort* Bh = (ushort*)(sm + 20480);              // 32 x 40
    ushort* Bl = (ushort*)(sm + 23040);
    float* scost = (float*)sm;                       // reuse: [32][132]
    int t = threadIdx.x, lane = t & 31, w = t >> 5;
    int r0 = blockIdx.x * 128, b = blockIdx.x >> 5;  // <<<512,256>>>

    float acc[4][4];
#pragma unroll
    for (int i = 0; i < 4; i++)
#pragma unroll
        for (int q = 0; q < 4; q++) acc[i][q] = 0.0f;
    int arow = lane & 15, ak = (lane >> 4) * 8;
    int brow = (lane & 7) + ((lane >> 4) & 1) * 8, bk = ((lane >> 3) & 1) * 8;
    const ushort* SH = (const ushort*)g_SH4 + (size_t)r0 * 512;
    const ushort* SL = (const ushort*)g_SL4 + (size_t)r0 * 512;
    const ushort* yb = (t < 128) ? (const ushort*)g_YH4 : (const ushort*)g_YL4;
    yb += (size_t)b * 16384;
    int tt = t & 127, bRow = tt >> 2, bQ = tt & 3;
    int aR0 = t >> 2, aQ0 = t & 3;                   // A quads: q=t and q=t+256

    uint4 rah[2], ral[2], rbv;
    {   // prefetch chunk 0
#pragma unroll
        for (int j = 0; j < 2; j++) {
            int q = t + j * 256, row = q >> 2, qq = q & 3;
            rah[j] = *(const uint4*)(SH + (size_t)row * 512 + qq * 8);
            ral[j] = *(const uint4*)(SL + (size_t)row * 512 + qq * 8);
        }
        rbv = *(const uint4*)(yb + (size_t)bRow * 512 + bQ * 8);
    }

    for (int c = 0; c < 16; c++) {
#pragma unroll
        for (int j = 0; j < 2; j++) {
            int q = t + j * 256, row = q >> 2, qq = q & 3;
            *(uint4*)(Ah + row * 40 + qq * 8) = rah[j];
            *(uint4*)(Al + row * 40 + qq * 8) = ral[j];
        }
        {
            ushort* Bd = (t < 128) ? Bh : Bl;
            *(uint4*)(Bd + bRow * 40 + bQ * 8) = rbv;
        }
        __syncthreads();
        if (c < 15) {
            int cn = c + 1;
#pragma unroll
            for (int j = 0; j < 2; j++) {
                int q = t + j * 256, row = q >> 2, qq = q & 3;
                rah[j] = *(const uint4*)(SH + (size_t)row * 512 + cn * 32 + qq * 8);
                ral[j] = *(const uint4*)(SL + (size_t)row * 512 + cn * 32 + qq * 8);
            }
            rbv = *(const uint4*)(yb + (size_t)bRow * 512 + cn * 32 + bQ * 8);
        }
#pragma unroll
        for (int ks = 0; ks < 2; ks++) {
            int k_off = ks * 16;
#pragma unroll
            for (int pass = 0; pass < 3; pass++) {
                ushort* Asel = (pass == 2) ? Al : Ah;
                ushort* Bsel = (pass == 1) ? Bl : Bh;
                uint32_t a[4];
                LDSM4(a, smem_u32(Asel + (w * 16 + arow) * 40 + k_off + ak));
                uint32_t bb2[2][4];
#pragma unroll
                for (int nj2 = 0; nj2 < 2; nj2++)
                    LDSM4(bb2[nj2], smem_u32(Bsel + (nj2 * 16 + brow) * 40 + k_off + bk));
                MMA16816(acc[0], a, bb2[0][0], bb2[0][1]);
                MMA16816(acc[1], a, bb2[0][2], bb2[0][3]);
                MMA16816(acc[2], a, bb2[1][0], bb2[1][1]);
                MMA16816(acc[3], a, bb2[1][2], bb2[1][3]);
            }
        }
        __syncthreads();
    }
    int g4 = lane >> 2, l2 = (lane & 3) * 2;
    int rA = w * 16 + g4, rB = rA + 8;
    float ia = g_rnorm[r0 + rA], ib = g_rnorm[r0 + rB];
#pragma unroll
    for (int nj = 0; nj < 4; nj++) {
        int cc = nj * 8 + l2;
        float c00 = 1.0f - acc[nj][0] * ia, c01 = 1.0f - acc[nj][1] * ia;
        float c10 = 1.0f - acc[nj][2] * ib, c11 = 1.0f - acc[nj][3] * ib;
        *(float2*)(g_cost + (size_t)(r0 + rA) * MM + cc) = make_float2(c00, c01);
        *(float2*)(g_cost + (size_t)(r0 + rB) * MM + cc) = make_float2(c10, c11);
        scost[cc * 132 + rA] = c00; scost[(cc + 1) * 132 + rA] = c01;
        scost[cc * 132 + rB] = c10; scost[(cc + 1) * 132 + rB] = c11;
    }
    __syncthreads();
    for (int i = t; i < 4096; i += 256) {
        int m = i >> 7, r = i & 127;
        g_Kt[(size_t)m * NB + r0 + r] = expf(scost[m * 132 + r] * -EPS_INV);
    }
}

// ---------------- Sinkhorn: 50 iterations, one kernel, 8-CTA clusters ----------------
__global__ void __launch_bounds__(512, 1) __cluster_dims__(8, 1, 1)
k_sink_all() {
    int g = blockIdx.x, b = g >> 3, t = threadIdx.x; // <<<128,512>>>
    int lane = t & 31, warp = t >> 5, rank0 = ((g & 7) == 0);
    __shared__ float sv[32], snu[32];
    __shared__ float cpart[2][34];
    __shared__ float wsum[16][33], werr[16];
    if (t < 32) { sv[t] = 0.0f; snu[t] = g_nu[b * 32 + t]; }
    __syncthreads();

    int row = g * 512 + t;
    float kk[32];
#pragma unroll
    for (int m = 0; m < 32; m++) kk[m] = g_Kt[(size_t)m * NB + row];
    float u = 0.0f;
    const float mu = 1.0f / 4096.0f;

    for (int it = 0; it < 50; it++) {
        float denom = 0.0f;
#pragma unroll
        for (int m = 0; m < 32; m++) denom += kk[m] * sv[m];
        float un = mu / (denom + 1e-8f);
        float du = fabsf(un - u);
        u = un;
        float red[32];
#pragma unroll
        for (int m = 0; m < 32; m++) red[m] = kk[m] * un;
#pragma unroll
        for (int o = 16; o; o >>= 1) {
            bool hi = (lane & o) != 0;
#pragma unroll
            for (int j = 0; j < o; j++) {
                float send = hi ? red[j] : red[j + o];
                float recv = __shfl_xor_sync(0xffffffffu, send, o);
                red[j] = (hi ? red[j + o] : red[j]) + recv;
            }
        }
        wsum[warp][lane] = red[0];
        du = wred(du);
        if (lane == 0) werr[warp] = du;
        __syncthreads();
        int p = it & 1;
        if (t < 32) {
            float a = 0.0f;
#pragma unroll
            for (int w2 = 0; w2 < 16; w2++) a += wsum[w2][t];
            cpart[p][t] = a;
        } else if (t == 32) {
            float e = 0.0f;
#pragma unroll
            for (int w2 = 0; w2 < 16; w2++) e += werr[w2];
            cpart[p][32] = e;
            g_errtraj8[it * 128 + g] = e;
        }
        CLUSTER_SYNC();
        if (t < 32) {
            uint32_t laddr = smem_u32(&cpart[p][t]);
            float a = 0.0f;
#pragma unroll
            for (int r = 0; r < 8; r++) a += dsmem_ld(laddr, (uint32_t)r);
            float v = snu[t] / (a + 1e-8f);
            sv[t] = v;
            if (rank0) g_vtraj[(it * 16 + b) * 32 + t] = v;
        }
        __syncthreads();
    }
    CLUSTER_SYNC();
}

// pick kept iteration
__global__ void k_pick() {
    __shared__ int midx;
    int t = threadIdx.x;                             // <<<1,64>>>
    if (t == 0) midx = 49;
    __syncthreads();
    if (t < 50) {
        float e = 0.0f;
        const float* ep = g_errtraj8 + t * 128;
        for (int k = 0; k < 128; k++) e += ep[k];
        if (e * (1.0f / 16.0f) < 0.1f) atomicMin(&midx, t);
    }
    __syncthreads();
    if (t == 0) g_kidx = midx;
}

// ---------------- Sinkhorn epilogue: pi out + bf16 pinorm images ----------------
__global__ void __launch_bounds__(512) k_sink_epi(float* __restrict__ out_pi) {
    int g = blockIdx.x, b = g >> 3, t = threadIdx.x; // <<<128,512>>>
    int lane = t & 31, warp = t >> 5;
    __shared__ float sv[32], svp[32], werr[16];
    int kidx = g_kidx;
    if (t < 32) {
        sv[t] = g_vtraj[(kidx * 16 + b) * 32 + t];
        svp[t] = (kidx > 0) ? g_vtraj[((kidx - 1) * 16 + b) * 32 + t] : 0.0f;
    }
    __syncthreads();
    int row = g * 512 + t;
    float kk[32], pi[32];
#pragma unroll
    for (int m = 0; m < 32; m++) kk[m] = g_Kt[(size_t)m * NB + row];
    float denom = 0.0f;
#pragma unroll
    for (int m = 0; m < 32; m++) denom += kk[m] * svp[m];
    float u = (1.0f / 4096.0f) / (denom + 1e-8f);
    float rs = 0.0f;
#pragma unroll
    for (int m = 0; m < 32; m++) { pi[m] = u * kk[m] * sv[m]; rs += pi[m]; }
    size_t rowbase = (size_t)row * MM;
#pragma unroll
    for (int m = 0; m < 32; m += 4)
        *(float4*)(out_pi + rowbase + m) = make_float4(pi[m], pi[m + 1], pi[m + 2], pi[m + 3]);
    float inv = 1.0f / (rs + 1e-8f);
#pragma unroll
    for (int m = 0; m < 32; m += 4)
        split4((ushort*)g_PH4, (ushort*)g_PL4, (int)(row * 32 + m),
               make_float4(pi[m] * inv, pi[m + 1] * inv, pi[m + 2] * inv, pi[m + 3] * inv));
    float oc = 0.0f;
#pragma unroll
    for (int m = 0; m < 32; m += 4) {
        float4 cq = *(const float4*)(g_cost + rowbase + m);
        oc += pi[m] * cq.x + pi[m + 1] * cq.y + pi[m + 2] * cq.z + pi[m + 3] * cq.w;
    }
    oc = wred(oc);
    if (lane == 0) werr[warp] = oc;
    __syncthreads();
    if (t == 0) {
        float e = 0.0f;
#pragma unroll
        for (int w = 0; w < 16; w++) e += werr[w];
        g_otpart[g] = e;
    }
}

__global__ void k_ot_final(float* __restrict__ out_ot) {
    int b = threadIdx.x;                             // <<<1,16>>>
    float e = 0.0f;
#pragma unroll
    for (int k = 0; k < 8; k++) e += g_otpart[b * 8 + k];
    out_ot[b] = e;
}

// ---------------- pipelined HMMA fused GEMM + clustered LayerNorm ----------------
__global__ void __launch_bounds__(256) __cluster_dims__(4, 1, 1)
k_gemm_hmma(const float* __restrict__ bias,
            const float* __restrict__ gamma, const float* __restrict__ beta,
            float* __restrict__ out) {
    __shared__ uint4 sAh4[640], sAl4[640], sBh4[640], sBl4[640];
    __shared__ float sstat[2][128][2];
    __shared__ float2 cst[128];
    __shared__ float2 srow[128];
    ushort* Ah = (ushort*)sAh4; ushort* Al = (ushort*)sAl4;
    ushort* Bh = (ushort*)sBh4; ushort* Bl = (ushort*)sBl4;
    int t = threadIdx.x, lane = t & 31, w = t >> 5;
    int r0 = blockIdx.y * 128, c0 = blockIdx.x * 128;
    int b = r0 >> 12;
    int wm = (w & 3) * 32, wn = (w >> 2) * 64;

    float acc[2][8][4];
#pragma unroll
    for (int i = 0; i < 2; i++)
#pragma unroll
        for (int j = 0; j < 8; j++)
#pragma unroll
            for (int q = 0; q < 4; q++) acc[i][j][q] = 0.0f;

    int arow = lane & 15, ak = (lane >> 4) * 8;
    int brow = (lane & 7) + ((lane >> 4) & 1) * 8, bk = ((lane >> 3) & 1) * 8;
    int bRow = t >> 2, bQ = t & 3;
    const ushort* SH = (const ushort*)g_SH4 + (size_t)r0 * 512;
    const ushort* SL = (const ushort*)g_SL4 + (size_t)r0 * 512;
    const ushort* PH = (const ushort*)g_PH4 + (size_t)r0 * 32;
    const ushort* PL = (const ushort*)g_PL4 + (size_t)r0 * 32;

    uint4 rah[2], ral[2], rbh[2], rbl[2];
    {   // prefetch chunk 0
#pragma unroll
        for (int j = 0; j < 2; j++) {
            int q = t + j * 256, row = q >> 2, qq = q & 3;
            rah[j] = *(const uint4*)(SH + (size_t)row * 512 + qq * 8);
            ral[j] = *(const uint4*)(SL + (size_t)row * 512 + qq * 8);
        }
        const ushort* bh = (const ushort*)g_WH4 + (size_t)c0 * 512;
        const ushort* bl = (const ushort*)g_WL4 + (size_t)c0 * 512;
#pragma unroll
        for (int j = 0; j < 2; j++) {
            rbh[j] = *(const uint4*)(bh + (size_t)(bRow + 64 * j) * 512 + bQ * 8);
            rbl[j] = *(const uint4*)(bl + (size_t)(bRow + 64 * j) * 512 + bQ * 8);
        }
    }

    for (int c = 0; c < 17; c++) {
#pragma unroll
        for (int j = 0; j < 2; j++) {
            int q = t + j * 256, row = q >> 2, qq = q & 3;
            *(uint4*)(Ah + row * 40 + qq * 8) = rah[j];
            *(uint4*)(Al + row * 40 + qq * 8) = ral[j];
        }
#pragma unroll
        for (int j = 0; j < 2; j++) {
            int row = bRow + 64 * j;
            *(uint4*)(Bh + row * 40 + bQ * 8) = rbh[j];
            *(uint4*)(Bl + row * 40 + bQ * 8) = rbl[j];
        }
        __syncthreads();
        if (c < 16) {
            int cn = c + 1;
            if (cn < 16) {
#pragma unroll
                for (int j = 0; j < 2; j++) {
                    int q = t + j * 256, row = q >> 2, qq = q & 3;
                    rah[j] = *(const uint4*)(SH + (size_t)row * 512 + cn * 32 + qq * 8);
                    ral[j] = *(const uint4*)(SL + (size_t)row * 512 + cn * 32 + qq * 8);
                }
                const ushort* bh = (const ushort*)g_WH4 + (size_t)c0 * 512 + cn * 32;
                const ushort* bl = (const ushort*)g_WL4 + (size_t)c0 * 512 + cn * 32;
#pragma unroll
                for (int j = 0; j < 2; j++) {
                    rbh[j] = *(const uint4*)(bh + (size_t)(bRow + 64 * j) * 512 + bQ * 8);
                    rbl[j] = *(const uint4*)(bl + (size_t)(bRow + 64 * j) * 512 + bQ * 8);
                }
            } else {
#pragma unroll
                for (int j = 0; j < 2; j++) {
                    int q = t + j * 256, row = q >> 2, qq = q & 3;
                    rah[j] = *(const uint4*)(PH + (size_t)row * 32 + qq * 8);
                    ral[j] = *(const uint4*)(PL + (size_t)row * 32 + qq * 8);
                }
                const ushort* bh = (const ushort*)g_TH4 + (size_t)b * 16384 + (size_t)c0 * 32;
                const ushort* bl = (const ushort*)g_TL4 + (size_t)b * 16384 + (size_t)c0 * 32;
#pragma unroll
                for (int j = 0; j < 2; j++) {
                    rbh[j] = *(const uint4*)(bh + (size_t)(bRow + 64 * j) * 32 + bQ * 8);
                    rbl[j] = *(const uint4*)(bl + (size_t)(bRow + 64 * j) * 32 + bQ * 8);
                }
            }
        }
#pragma unroll
        for (int ks = 0; ks < 2; ks++) {
            int k_off = ks * 16;
#pragma unroll
            for (int pass = 0; pass < 3; pass++) {
                ushort* Asel = (pass == 2) ? Al : Ah;
                ushort* Bsel = (pass == 1) ? Bl : Bh;
                uint32_t a[2][4];
#pragma unroll
                for (int mi = 0; mi < 2; mi++)
                    LDSM4(a[mi], smem_u32(Asel + (wm + mi * 16 + arow) * 40 + k_off + ak));
                uint32_t bb[4][4];
#pragma unroll
                for (int nj2 = 0; nj2 < 4; nj2++)
                    LDSM4(bb[nj2], smem_u32(Bsel + (wn + nj2 * 16 + brow) * 40 + k_off + bk));
#pragma unroll
                for (int mi = 0; mi < 2; mi++)
#pragma unroll
                    for (int nj2 = 0; nj2 < 4; nj2++) {
                        MMA16816(acc[mi][nj2 * 2],     a[mi], bb[nj2][0], bb[nj2][1]);
                        MMA16816(acc[mi][nj2 * 2 + 1], a[mi], bb[nj2][2], bb[nj2][3]);
                    }
            }
        }
        __syncthreads();
    }

    // ---- epilogue: +bias, row stats, cluster LN, store ----
    int g4 = lane >> 2, l2 = (lane & 3) * 2;
#pragma unroll
    for (int nj = 0; nj < 8; nj++) {
        float2 bi = *(const float2*)(bias + c0 + wn + nj * 8 + l2);
#pragma unroll
        for (int mi = 0; mi < 2; mi++) {
            acc[mi][nj][0] += bi.x; acc[mi][nj][1] += bi.y;
            acc[mi][nj][2] += bi.x; acc[mi][nj][3] += bi.y;
        }
    }
    float rs4[4], rq4[4];
#pragma unroll
    for (int mi = 0; mi < 2; mi++)
#pragma unroll
        for (int h = 0; h < 2; h++) {
            float s = 0.0f, q = 0.0f;
#pragma unroll
            for (int nj = 0; nj < 8; nj++) {
                float a0 = acc[mi][nj][h * 2], a1 = acc[mi][nj][h * 2 + 1];
                s += a0 + a1; q += a0 * a0 + a1 * a1;
            }
            rs4[mi * 2 + h] = s; rq4[mi * 2 + h] = q;
        }
#pragma unroll
    for (int i = 0; i < 4; i++) {
        rs4[i] += __shfl_xor_sync(0xffffffffu, rs4[i], 1);
        rs4[i] += __shfl_xor_sync(0xffffffffu, rs4[i], 2);
        rq4[i] += __shfl_xor_sync(0xffffffffu, rq4[i], 1);
        rq4[i] += __shfl_xor_sync(0xffffffffu, rq4[i], 2);
    }
    int nh = w >> 2;
    if ((lane & 3) == 0) {
#pragma unroll
        for (int mi = 0; mi < 2; mi++)
#pragma unroll
            for (int h = 0; h < 2; h++) {
                int lr = wm + mi * 16 + h * 8 + g4;
                sstat[nh][lr][0] = rs4[mi * 2 + h];
                sstat[nh][lr][1] = rq4[mi * 2 + h];
            }
    }
    __syncthreads();
    if (t < 128)
        cst[t] = make_float2(sstat[0][t][0] + sstat[1][t][0],
                             sstat[0][t][1] + sstat[1][t][1]);
    CLUSTER_SYNC();
    if (t < 128) {
        uint32_t laddr = smem_u32(&cst[t]);
        float s = 0.0f, q = 0.0f;
#pragma unroll
        for (int r = 0; r < 4; r++) {
            float2 v = dsmem_ld2(laddr, (uint32_t)r);
            s += v.x; q += v.y;
        }
        float mean = s * (1.0f / 512.0f);
        float var = q * (1.0f / 512.0f) - mean * mean;
        srow[t] = make_float2(mean, rsqrtf(var + 1e-5f));
    }
    __syncthreads();
#pragma unroll
    for (int mi = 0; mi < 2; mi++)
#pragma unroll
        for (int nj = 0; nj < 8; nj++) {
            int lr = wm + mi * 16 + g4;
            int cc = c0 + wn + nj * 8 + l2;
            float2 gm = *(const float2*)(gamma + cc);
            float2 bt = *(const float2*)(beta + cc);
            float2 st0 = srow[lr], st1 = srow[lr + 8];
            *(float2*)(out + (size_t)(r0 + lr) * CC + cc) = make_float2(
                (acc[mi][nj][0] - st0.x) * st0.y * gm.x + bt.x,
                (acc[mi][nj][1] - st0.x) * st0.y * gm.y + bt.y);
            *(float2*)(out + (size_t)(r0 + lr + 8) * CC + cc) = make_float2(
                (acc[mi][nj][2] - st1.x) * st1.y * gm.x + bt.x,
                (acc[mi][nj][3] - st1.x) * st1.y * gm.y + bt.y);
        }
    CLUSTER_SYNC();
}

// ---------------- launch ----------------
extern "C" void kernel_launch(void* const* d_in, const int* in_sizes, int n_in,
                              void* d_out, int out_size) {
    const float* src   = (const float*)d_in[0];
    const float* tgt   = (const float*)d_in[1];
    const float* score = (const float*)d_in[2];
    const float* W     = (const float*)d_in[3];
    const float* bias  = (const float*)d_in[4];
    const float* gamma = (const float*)d_in[5];
    const float* beta  = (const float*)d_in[6];
    float* out = (float*)d_out;

    const size_t OUT_OT = (size_t)BB * NN * CC;
    float* out_ot = out + OUT_OT;
    float* out_pi = out + OUT_OT + BB;

    k_init<<<1, 512>>>();
    k_nu_count<<<(BB * NN) / 256, 256>>>(score);
    k_nu_final<<<BB, MM>>>();
    k_prep_src<<<NB, 128>>>(src);
    k_ynorm<<<BB * MM, 128>>>(tgt);
    k_tw2<<<128, 256>>>(tgt, W);
    k_prep_w<<<256, 256>>>(W);
    k_prep_tail<<<256, 256>>>();
    k_cost_hmma<<<512, 256>>>();
    k_sink_all<<<128, 512>>>();
    k_pick<<<1, 64>>>();
    k_sink_epi<<<128, 512>>>(out_pi);
    k_ot_final<<<1, 16>>>(out_ot);
    k_gemm_hmma<<<dim3(4, 512), 256>>>(bias, gamma, beta, out);
}

// round 16
// speedup vs baseline: 2.7179x; 1.1119x over previous
#include <cuda_runtime.h>
#include <cuda_fp16.h>
#include <math.h>
#include <stdint.h>

#define BB 16
#define NN 4096
#define CC 512
#define MM 32
#define NB (BB*NN)
#define EPS_INV 20.0f

// ---------------- scratch (device globals; no allocation) ----------------
__device__ float g_tw2[BB*MM*CC];
__device__ float g_nu[BB*MM];
__device__ int   g_counts[BB*MM];
__device__ float g_Kt[(size_t)MM*NB];
__device__ float g_cost[(size_t)NB*MM];
__device__ float g_rnorm[NB];               // rsqrt(row norm^2) of src
__device__ float g_vtraj[50*BB*MM];
__device__ float g_errtraj8[50*128];
__device__ float g_otpart[128];
__device__ int   g_kidx;
// fp16 hi/lo images
__device__ uint4 g_WH4[32768];                      // W1^T [n][k] 512x512 (hi only)
__device__ uint4 g_TH4[32768];                      // TW2^T [b][n][k] 512x32 (hi only)
__device__ uint4 g_YH4[32768], g_YL4[32768];        // yn [b][m][k] 32x512
__device__ uint4 g_SH4[4194304], g_SL4[4194304];    // src [row][k] 65536x512
__device__ uint4 g_PH4[262144], g_PL4[262144];      // pinorm [row][m] 65536x32

__device__ __forceinline__ float wred(float v) {
#pragma unroll
    for (int o = 16; o; o >>= 1) v += __shfl_xor_sync(0xffffffffu, v, o);
    return v;
}
__device__ __forceinline__ uint32_t smem_u32(const void* p) {
    uint32_t a;
    asm("{ .reg .u64 t; cvta.to.shared.u64 t, %1; cvt.u32.u64 %0, t; }" : "=r"(a) : "l"(p));
    return a;
}
__device__ __forceinline__ float dsmem_ld(uint32_t laddr, uint32_t rank) {
    uint32_t ra; float v;
    asm("mapa.shared::cluster.u32 %0, %1, %2;" : "=r"(ra) : "r"(laddr), "r"(rank));
    asm volatile("ld.shared::cluster.f32 %0, [%1];" : "=f"(v) : "r"(ra) : "memory");
    return v;
}
__device__ __forceinline__ float2 dsmem_ld2(uint32_t laddr, uint32_t rank) {
    uint32_t ra; float2 v;
    asm("mapa.shared::cluster.u32 %0, %1, %2;" : "=r"(ra) : "r"(laddr), "r"(rank));
    asm volatile("ld.shared::cluster.v2.f32 {%0,%1}, [%2];" : "=f"(v.x), "=f"(v.y) : "r"(ra) : "memory");
    return v;
}
#define CLUSTER_SYNC() do {                                             \
    asm volatile("barrier.cluster.arrive.aligned;" ::: "memory");       \
    asm volatile("barrier.cluster.wait.aligned;" ::: "memory");         \
} while (0)
// fp16 hi/lo split
__device__ __forceinline__ void split4(ushort* hb, ushort* lb, int off, float4 v) {
    __half hx = __float2half(v.x), hy = __float2half(v.y),
           hz = __float2half(v.z), hw = __float2half(v.w);
    unsigned h0 = ((unsigned)__half_as_ushort(hy) << 16) | __half_as_ushort(hx);
    unsigned h1 = ((unsigned)__half_as_ushort(hw) << 16) | __half_as_ushort(hz);
    __half ax = __float2half(v.x - __half2float(hx));
    __half ay = __float2half(v.y - __half2float(hy));
    __half az = __float2half(v.z - __half2float(hz));
    __half aw = __float2half(v.w - __half2float(hw));
    unsigned l0 = ((unsigned)__half_as_ushort(ay) << 16) | __half_as_ushort(ax);
    unsigned l1 = ((unsigned)__half_as_ushort(aw) << 16) | __half_as_ushort(az);
    *(uint2*)(hb + off) = make_uint2(h0, h1);
    *(uint2*)(lb + off) = make_uint2(l0, l1);
}
__device__ __forceinline__ void split4hi(ushort* hb, int off, float4 v) {
    __half hx = __float2half(v.x), hy = __float2half(v.y),
           hz = __float2half(v.z), hw = __float2half(v.w);
    unsigned h0 = ((unsigned)__half_as_ushort(hy) << 16) | __half_as_ushort(hx);
    unsigned h1 = ((unsigned)__half_as_ushort(hw) << 16) | __half_as_ushort(hz);
    *(uint2*)(hb + off) = make_uint2(h0, h1);
}
#define LDSM4(r, a)                                                                      \
    asm volatile("ldmatrix.sync.aligned.m8n8.x4.shared.b16 {%0,%1,%2,%3}, [%4];"         \
        : "=r"((r)[0]), "=r"((r)[1]), "=r"((r)[2]), "=r"((r)[3]) : "r"(a))
#define MMA16816(d, a, b0, b1)                                                           \
    asm volatile("mma.sync.aligned.m16n8k16.row.col.f32.f16.f16.f32 "                    \
        "{%0,%1,%2,%3}, {%4,%5,%6,%7}, {%8,%9}, {%0,%1,%2,%3};"                          \
        : "+f"((d)[0]), "+f"((d)[1]), "+f"((d)[2]), "+f"((d)[3])                         \
        : "r"((a)[0]), "r"((a)[1]), "r"((a)[2]), "r"((a)[3]), "r"(b0), "r"(b1))

// ---------------- init ----------------
__global__ void k_init() {
    int t = threadIdx.x;                             // <<<1,512>>>
    if (t < BB * MM) g_counts[t] = 0;
}

// ---------------- nu ----------------
__global__ void k_nu_count(const float* __restrict__ score) {
    int idx = blockIdx.x * 256 + threadIdx.x;
    int b = idx >> 12, hw = idx & 4095;
    const float* p = score + (size_t)b * MM * NN + hw;
    float best = p[0]; int bi = 0;
#pragma unroll
    for (int k = 1; k < MM; k++) {
        float v = p[(size_t)k * NN];
        if (v > best) { best = v; bi = k; }
    }
    atomicAdd(&g_counts[b * MM + bi], 1);
}

__global__ void k_nu_final() {
    int b = blockIdx.x, k = threadIdx.x;             // <<<16,32>>>
    float c = (float)g_counts[b * MM + k];
    float nu = c / (4096.0f + 1e-8f) + 1e-6f;
    float s = wred(nu);
    g_nu[b * MM + k] = nu / s;
}

// ---------------- src -> fp16 hi/lo images + row norms ----------------
__global__ void k_prep_src(const float* __restrict__ src) {
    int row = blockIdx.x;                            // <<<65536,128>>>
    const float4* p = (const float4*)(src + (size_t)row * CC);
    int t = threadIdx.x;
    float4 v = p[t];
    float s = wred(v.x * v.x + v.y * v.y + v.z * v.z + v.w * v.w);
    __shared__ float ws[4];
    if ((t & 31) == 0) ws[t >> 5] = s;
    __syncthreads();
    if (t == 0) g_rnorm[row] = rsqrtf(ws[0] + ws[1] + ws[2] + ws[3]);
    split4((ushort*)g_SH4, (ushort*)g_SL4, (int)(row * 512 + t * 4), v);
}

// ---------------- normalize target rows -> fp16 hi/lo yn images ----------------
__global__ void k_ynorm(const float* __restrict__ tgt) {
    int row = blockIdx.x;                            // <<<512,128>>>
    const float4* p = (const float4*)(tgt + (size_t)row * CC);
    int t = threadIdx.x;
    float4 v = p[t];
    float s = wred(v.x * v.x + v.y * v.y + v.z * v.z + v.w * v.w);
    __shared__ float ws[4];
    if ((t & 31) == 0) ws[t >> 5] = s;
    __syncthreads();
    float inv = rsqrtf(ws[0] + ws[1] + ws[2] + ws[3]);
    float4 o = make_float4(v.x * inv, v.y * inv, v.z * inv, v.w * inv);
    split4((ushort*)g_YH4, (ushort*)g_YL4, row * 512 + t * 4, o);
}

// ---------------- TW2 = target @ W2 ----------------
__global__ void __launch_bounds__(256) k_tw2(const float* __restrict__ tgt,
                                             const float* __restrict__ W) {
    __shared__ float ts[32 * 128];
    int blk = blockIdx.x;                            // <<<128,256>>>
    int b = blk >> 3, ct = blk & 7;
    int t = threadIdx.x;
    int c = ct * 64 + (t & 63);
    int mg = t >> 6;
    float acc[8];
#pragma unroll
    for (int i = 0; i < 8; i++) acc[i] = 0.0f;
    for (int kt = 0; kt < 4; kt++) {
        __syncthreads();
        for (int i = t; i < 32 * 128 / 4; i += 256) {
            int m = i >> 5, k4 = i & 31;
            ((float4*)ts)[i] = ((const float4*)(tgt + ((size_t)(b * 32 + m)) * CC + kt * 128))[k4];
        }
        __syncthreads();
        const float* Wp = W + (size_t)(CC + kt * 128) * CC + c;
        for (int k = 0; k < 128; k++) {
            float w = Wp[(size_t)k * CC];
#pragma unroll
            for (int i = 0; i < 8; i++) acc[i] += ts[(mg * 8 + i) * 128 + k] * w;
        }
    }
#pragma unroll
    for (int i = 0; i < 8; i++)
        g_tw2[(size_t)b * MM * CC + (size_t)(mg * 8 + i) * CC + c] = acc[i];
}

// ---------------- prep fp16 hi images of W1^T and TW2^T ----------------
__global__ void k_prep_w(const float* __restrict__ W) {
    int idx = blockIdx.x * 256 + threadIdx.x;        // <<<256,256>>>
    int n = idx & 511, kq = idx >> 9;
    int k0 = kq * 4;
    float4 v = make_float4(W[(size_t)k0 * CC + n], W[(size_t)(k0 + 1) * CC + n],
                           W[(size_t)(k0 + 2) * CC + n], W[(size_t)(k0 + 3) * CC + n]);
    split4hi((ushort*)g_WH4, n * 512 + k0, v);
}
__global__ void k_prep_tail() {
    int idx = blockIdx.x * 256 + threadIdx.x;        // <<<256,256>>>
    int b = idx >> 12, rem = idx & 4095;
    int n = rem & 511, k0 = ((rem >> 9) & 7) * 4;
    const float* tp = g_tw2 + (size_t)b * MM * CC;
    float4 v = make_float4(tp[(size_t)k0 * CC + n], tp[(size_t)(k0 + 1) * CC + n],
                           tp[(size_t)(k0 + 2) * CC + n], tp[(size_t)(k0 + 3) * CC + n]);
    split4hi((ushort*)g_TH4, b * 16384 + n * 32 + k0, v);
}

// ---------------- cost / Gibbs via HMMA (3-pass fp16, pure-copy, prefetch) ----------------
__global__ void __launch_bounds__(256) k_cost_hmma() {
    __shared__ char sm[25600];
    ushort* Ah = (ushort*)sm;                        // 128 x 40
    ushort* Al = (ushort*)(sm + 10240);
    ushort* Bh = (ushort*)(sm + 20480);              // 32 x 40
    ushort* Bl = (ushort*)(sm + 23040);
    float* scost = (float*)sm;                       // reuse: [32][132]
    int t = threadIdx.x, lane = t & 31, w = t >> 5;
    int r0 = blockIdx.x * 128, b = blockIdx.x >> 5;  // <<<512,256>>>

    float acc[4][4];
#pragma unroll
    for (int i = 0; i < 4; i++)
#pragma unroll
        for (int q = 0; q < 4; q++) acc[i][q] = 0.0f;
    int arow = lane & 15, ak = (lane >> 4) * 8;
    int brow = (lane & 7) + ((lane >> 4) & 1) * 8, bk = ((lane >> 3) & 1) * 8;
    const ushort* SH = (const ushort*)g_SH4 + (size_t)r0 * 512;
    const ushort* SL = (const ushort*)g_SL4 + (size_t)r0 * 512;
    const ushort* yb = (t < 128) ? (const ushort*)g_YH4 : (const ushort*)g_YL4;
    yb += (size_t)b * 16384;
    int tt = t & 127, bRow = tt >> 2, bQ = tt & 3;

    uint4 rah[2], ral[2], rbv;
    {   // prefetch chunk 0
#pragma unroll
        for (int j = 0; j < 2; j++) {
            int q = t + j * 256, row = q >> 2, qq = q & 3;
            rah[j] = *(const uint4*)(SH + (size_t)row * 512 + qq * 8);
            ral[j] = *(const uint4*)(SL + (size_t)row * 512 + qq * 8);
        }
        rbv = *(const uint4*)(yb + (size_t)bRow * 512 + bQ * 8);
    }

    for (int c = 0; c < 16; c++) {
#pragma unroll
        for (int j = 0; j < 2; j++) {
            int q = t + j * 256, row = q >> 2, qq = q & 3;
            *(uint4*)(Ah + row * 40 + qq * 8) = rah[j];
            *(uint4*)(Al + row * 40 + qq * 8) = ral[j];
        }
        {
            ushort* Bd = (t < 128) ? Bh : Bl;
            *(uint4*)(Bd + bRow * 40 + bQ * 8) = rbv;
        }
        __syncthreads();
        if (c < 15) {
            int cn = c + 1;
#pragma unroll
            for (int j = 0; j < 2; j++) {
                int q = t + j * 256, row = q >> 2, qq = q & 3;
                rah[j] = *(const uint4*)(SH + (size_t)row * 512 + cn * 32 + qq * 8);
                ral[j] = *(const uint4*)(SL + (size_t)row * 512 + cn * 32 + qq * 8);
            }
            rbv = *(const uint4*)(yb + (size_t)bRow * 512 + cn * 32 + bQ * 8);
        }
#pragma unroll
        for (int ks = 0; ks < 2; ks++) {
            int k_off = ks * 16;
#pragma unroll
            for (int pass = 0; pass < 3; pass++) {
                ushort* Asel = (pass == 2) ? Al : Ah;
                ushort* Bsel = (pass == 1) ? Bl : Bh;
                uint32_t a[4];
                LDSM4(a, smem_u32(Asel + (w * 16 + arow) * 40 + k_off + ak));
                uint32_t bb2[2][4];
#pragma unroll
                for (int nj2 = 0; nj2 < 2; nj2++)
                    LDSM4(bb2[nj2], smem_u32(Bsel + (nj2 * 16 + brow) * 40 + k_off + bk));
                MMA16816(acc[0], a, bb2[0][0], bb2[0][1]);
                MMA16816(acc[1], a, bb2[0][2], bb2[0][3]);
                MMA16816(acc[2], a, bb2[1][0], bb2[1][1]);
                MMA16816(acc[3], a, bb2[1][2], bb2[1][3]);
            }
        }
        __syncthreads();
    }
    int g4 = lane >> 2, l2 = (lane & 3) * 2;
    int rA = w * 16 + g4, rB = rA + 8;
    float ia = g_rnorm[r0 + rA], ib = g_rnorm[r0 + rB];
#pragma unroll
    for (int nj = 0; nj < 4; nj++) {
        int cc = nj * 8 + l2;
        float c00 = 1.0f - acc[nj][0] * ia, c01 = 1.0f - acc[nj][1] * ia;
        float c10 = 1.0f - acc[nj][2] * ib, c11 = 1.0f - acc[nj][3] * ib;
        *(float2*)(g_cost + (size_t)(r0 + rA) * MM + cc) = make_float2(c00, c01);
        *(float2*)(g_cost + (size_t)(r0 + rB) * MM + cc) = make_float2(c10, c11);
        scost[cc * 132 + rA] = c00; scost[(cc + 1) * 132 + rA] = c01;
        scost[cc * 132 + rB] = c10; scost[(cc + 1) * 132 + rB] = c11;
    }
    __syncthreads();
    for (int i = t; i < 4096; i += 256) {
        int m = i >> 7, r = i & 127;
        g_Kt[(size_t)m * NB + r0 + r] = expf(scost[m * 132 + r] * -EPS_INV);
    }
}

// ---------------- Sinkhorn: 50 iterations, one kernel, 8-CTA clusters ----------------
__global__ void __launch_bounds__(512, 1) __cluster_dims__(8, 1, 1)
k_sink_all() {
    int g = blockIdx.x, b = g >> 3, t = threadIdx.x; // <<<128,512>>>
    int lane = t & 31, warp = t >> 5, rank0 = ((g & 7) == 0);
    __shared__ float sv[32], snu[32];
    __shared__ float cpart[2][34];
    __shared__ float wsum[16][33], werr[16];
    if (t < 32) { sv[t] = 0.0f; snu[t] = g_nu[b * 32 + t]; }
    __syncthreads();

    int row = g * 512 + t;
    float kk[32];
#pragma unroll
    for (int m = 0; m < 32; m++) kk[m] = g_Kt[(size_t)m * NB + row];
    float u = 0.0f;
    const float mu = 1.0f / 4096.0f;

    for (int it = 0; it < 50; it++) {
        float denom = 0.0f;
#pragma unroll
        for (int m = 0; m < 32; m++) denom += kk[m] * sv[m];
        float un = mu / (denom + 1e-8f);
        float du = fabsf(un - u);
        u = un;
        float red[32];
#pragma unroll
        for (int m = 0; m < 32; m++) red[m] = kk[m] * un;
#pragma unroll
        for (int o = 16; o; o >>= 1) {
            bool hi = (lane & o) != 0;
#pragma unroll
            for (int j = 0; j < o; j++) {
                float send = hi ? red[j] : red[j + o];
                float recv = __shfl_xor_sync(0xffffffffu, send, o);
                red[j] = (hi ? red[j + o] : red[j]) + recv;
            }
        }
        wsum[warp][lane] = red[0];
        du = wred(du);
        if (lane == 0) werr[warp] = du;
        __syncthreads();
        int p = it & 1;
        if (t < 32) {
            float a = 0.0f;
#pragma unroll
            for (int w2 = 0; w2 < 16; w2++) a += wsum[w2][t];
            cpart[p][t] = a;
        } else if (t == 32) {
            float e = 0.0f;
#pragma unroll
            for (int w2 = 0; w2 < 16; w2++) e += werr[w2];
            cpart[p][32] = e;
            g_errtraj8[it * 128 + g] = e;
        }
        CLUSTER_SYNC();
        if (t < 32) {
            uint32_t laddr = smem_u32(&cpart[p][t]);
            float a = 0.0f;
#pragma unroll
            for (int r = 0; r < 8; r++) a += dsmem_ld(laddr, (uint32_t)r);
            float v = snu[t] / (a + 1e-8f);
            sv[t] = v;
            if (rank0) g_vtraj[(it * 16 + b) * 32 + t] = v;
        }
        __syncthreads();
    }
    CLUSTER_SYNC();
}

// pick kept iteration
__global__ void k_pick() {
    __shared__ int midx;
    int t = threadIdx.x;                             // <<<1,64>>>
    if (t == 0) midx = 49;
    __syncthreads();
    if (t < 50) {
        float e = 0.0f;
        const float* ep = g_errtraj8 + t * 128;
        for (int k = 0; k < 128; k++) e += ep[k];
        if (e * (1.0f / 16.0f) < 0.1f) atomicMin(&midx, t);
    }
    __syncthreads();
    if (t == 0) g_kidx = midx;
}

// ---------------- Sinkhorn epilogue: pi out + fp16 pinorm images ----------------
__global__ void __launch_bounds__(512) k_sink_epi(float* __restrict__ out_pi) {
    int g = blockIdx.x, b = g >> 3, t = threadIdx.x; // <<<128,512>>>
    int lane = t & 31, warp = t >> 5;
    __shared__ float sv[32], svp[32], werr[16];
    int kidx = g_kidx;
    if (t < 32) {
        sv[t] = g_vtraj[(kidx * 16 + b) * 32 + t];
        svp[t] = (kidx > 0) ? g_vtraj[((kidx - 1) * 16 + b) * 32 + t] : 0.0f;
    }
    __syncthreads();
    int row = g * 512 + t;
    float kk[32], pi[32];
#pragma unroll
    for (int m = 0; m < 32; m++) kk[m] = g_Kt[(size_t)m * NB + row];
    float denom = 0.0f;
#pragma unroll
    for (int m = 0; m < 32; m++) denom += kk[m] * svp[m];
    float u = (1.0f / 4096.0f) / (denom + 1e-8f);
    float rs = 0.0f;
#pragma unroll
    for (int m = 0; m < 32; m++) { pi[m] = u * kk[m] * sv[m]; rs += pi[m]; }
    size_t rowbase = (size_t)row * MM;
#pragma unroll
    for (int m = 0; m < 32; m += 4)
        *(float4*)(out_pi + rowbase + m) = make_float4(pi[m], pi[m + 1], pi[m + 2], pi[m + 3]);
    float inv = 1.0f / (rs + 1e-8f);
#pragma unroll
    for (int m = 0; m < 32; m += 4)
        split4((ushort*)g_PH4, (ushort*)g_PL4, (int)(row * 32 + m),
               make_float4(pi[m] * inv, pi[m + 1] * inv, pi[m + 2] * inv, pi[m + 3] * inv));
    float oc = 0.0f;
#pragma unroll
    for (int m = 0; m < 32; m += 4) {
        float4 cq = *(const float4*)(g_cost + rowbase + m);
        oc += pi[m] * cq.x + pi[m + 1] * cq.y + pi[m + 2] * cq.z + pi[m + 3] * cq.w;
    }
    oc = wred(oc);
    if (lane == 0) werr[warp] = oc;
    __syncthreads();
    if (t == 0) {
        float e = 0.0f;
#pragma unroll
        for (int w = 0; w < 16; w++) e += werr[w];
        g_otpart[g] = e;
    }
}

__global__ void k_ot_final(float* __restrict__ out_ot) {
    int b = threadIdx.x;                             // <<<1,16>>>
    float e = 0.0f;
#pragma unroll
    for (int k = 0; k < 8; k++) e += g_otpart[b * 8 + k];
    out_ot[b] = e;
}

// ---------------- pipelined HMMA fused GEMM (fp16 2-pass) + clustered LayerNorm ----------------
__global__ void __launch_bounds__(256) __cluster_dims__(4, 1, 1)
k_gemm_hmma(const float* __restrict__ bias,
            const float* __restrict__ gamma, const float* __restrict__ beta,
            float* __restrict__ out) {
    __shared__ uint4 sAh4[640], sAl4[640], sBh4[640];
    __shared__ float sstat[2][128][2];
    __shared__ float2 cst[128];
    __shared__ float2 srow[128];
    ushort* Ah = (ushort*)sAh4; ushort* Al = (ushort*)sAl4;
    ushort* Bh = (ushort*)sBh4;
    int t = threadIdx.x, lane = t & 31, w = t >> 5;
    int r0 = blockIdx.y * 128, c0 = blockIdx.x * 128;
    int b = r0 >> 12;
    int wm = (w & 3) * 32, wn = (w >> 2) * 64;

    float acc[2][8][4];
#pragma unroll
    for (int i = 0; i < 2; i++)
#pragma unroll
        for (int j = 0; j < 8; j++)
#pragma unroll
            for (int q = 0; q < 4; q++) acc[i][j][q] = 0.0f;

    int arow = lane & 15, ak = (lane >> 4) * 8;
    int brow = (lane & 7) + ((lane >> 4) & 1) * 8, bk = ((lane >> 3) & 1) * 8;
    int bRow = t >> 2, bQ = t & 3;
    const ushort* SH = (const ushort*)g_SH4 + (size_t)r0 * 512;
    const ushort* SL = (const ushort*)g_SL4 + (size_t)r0 * 512;
    const ushort* PH = (const ushort*)g_PH4 + (size_t)r0 * 32;
    const ushort* PL = (const ushort*)g_PL4 + (size_t)r0 * 32;

    uint4 rah[2], ral[2], rbh[2];
    {   // prefetch chunk 0
#pragma unroll
        for (int j = 0; j < 2; j++) {
            int q = t + j * 256, row = q >> 2, qq = q & 3;
            rah[j] = *(const uint4*)(SH + (size_t)row * 512 + qq * 8);
            ral[j] = *(const uint4*)(SL + (size_t)row * 512 + qq * 8);
        }
        const ushort* bh = (const ushort*)g_WH4 + (size_t)c0 * 512;
#pragma unroll
        for (int j = 0; j < 2; j++)
            rbh[j] = *(const uint4*)(bh + (size_t)(bRow + 64 * j) * 512 + bQ * 8);
    }

    for (int c = 0; c < 17; c++) {
#pragma unroll
        for (int j = 0; j < 2; j++) {
            int q = t + j * 256, row = q >> 2, qq = q & 3;
            *(uint4*)(Ah + row * 40 + qq * 8) = rah[j];
            *(uint4*)(Al + row * 40 + qq * 8) = ral[j];
        }
#pragma unroll
        for (int j = 0; j < 2; j++) {
            int row = bRow + 64 * j;
            *(uint4*)(Bh + row * 40 + bQ * 8) = rbh[j];
        }
        __syncthreads();
        if (c < 16) {
            int cn = c + 1;
            if (cn < 16) {
#pragma unroll
                for (int j = 0; j < 2; j++) {
                    int q = t + j * 256, row = q >> 2, qq = q & 3;
                    rah[j] = *(const uint4*)(SH + (size_t)row * 512 + cn * 32 + qq * 8);
                    ral[j] = *(const uint4*)(SL + (size_t)row * 512 + cn * 32 + qq * 8);
                }
                const ushort* bh = (const ushort*)g_WH4 + (size_t)c0 * 512 + cn * 32;
#pragma unroll
                for (int j = 0; j < 2; j++)
                    rbh[j] = *(const uint4*)(bh + (size_t)(bRow + 64 * j) * 512 + bQ * 8);
            } else {
#pragma unroll
                for (int j = 0; j < 2; j++) {
                    int q = t + j * 256, row = q >> 2, qq = q & 3;
                    rah[j] = *(const uint4*)(PH + (size_t)row * 32 + qq * 8);
                    ral[j] = *(const uint4*)(PL + (size_t)row * 32 + qq * 8);
                }
                const ushort* bh = (const ushort*)g_TH4 + (size_t)b * 16384 + (size_t)c0 * 32;
#pragma unroll
                for (int j = 0; j < 2; j++)
                    rbh[j] = *(const uint4*)(bh + (size_t)(bRow + 64 * j) * 32 + bQ * 8);
            }
        }
#pragma unroll
        for (int ks = 0; ks < 2; ks++) {
            int k_off = ks * 16;
#pragma unroll
            for (int pass = 0; pass < 2; pass++) {
                ushort* Asel = pass ? Al : Ah;
                uint32_t a[2][4];
#pragma unroll
                for (int mi = 0; mi < 2; mi++)
                    LDSM4(a[mi], smem_u32(Asel + (wm + mi * 16 + arow) * 40 + k_off + ak));
                uint32_t bb[4][4];
#pragma unroll
                for (int nj2 = 0; nj2 < 4; nj2++)
                    LDSM4(bb[nj2], smem_u32(Bh + (wn + nj2 * 16 + brow) * 40 + k_off + bk));
#pragma unroll
                for (int mi = 0; mi < 2; mi++)
#pragma unroll
                    for (int nj2 = 0; nj2 < 4; nj2++) {
                        MMA16816(acc[mi][nj2 * 2],     a[mi], bb[nj2][0], bb[nj2][1]);
                        MMA16816(acc[mi][nj2 * 2 + 1], a[mi], bb[nj2][2], bb[nj2][3]);
                    }
            }
        }
        __syncthreads();
    }

    // ---- epilogue: +bias, row stats, cluster LN, store ----
    int g4 = lane >> 2, l2 = (lane & 3) * 2;
#pragma unroll
    for (int nj = 0; nj < 8; nj++) {
        float2 bi = *(const float2*)(bias + c0 + wn + nj * 8 + l2);
#pragma unroll
        for (int mi = 0; mi < 2; mi++) {
            acc[mi][nj][0] += bi.x; acc[mi][nj][1] += bi.y;
            acc[mi][nj][2] += bi.x; acc[mi][nj][3] += bi.y;
        }
    }
    float rs4[4], rq4[4];
#pragma unroll
    for (int mi = 0; mi < 2; mi++)
#pragma unroll
        for (int h = 0; h < 2; h++) {
            float s = 0.0f, q = 0.0f;
#pragma unroll
            for (int nj = 0; nj < 8; nj++) {
                float a0 = acc[mi][nj][h * 2], a1 = acc[mi][nj][h * 2 + 1];
                s += a0 + a1; q += a0 * a0 + a1 * a1;
            }
            rs4[mi * 2 + h] = s; rq4[mi * 2 + h] = q;
        }
#pragma unroll
    for (int i = 0; i < 4; i++) {
        rs4[i] += __shfl_xor_sync(0xffffffffu, rs4[i], 1);
        rs4[i] += __shfl_xor_sync(0xffffffffu, rs4[i], 2);
        rq4[i] += __shfl_xor_sync(0xffffffffu, rq4[i], 1);
        rq4[i] += __shfl_xor_sync(0xffffffffu, rq4[i], 2);
    }
    int nh = w >> 2;
    if ((lane & 3) == 0) {
#pragma unroll
        for (int mi = 0; mi < 2; mi++)
#pragma unroll
            for (int h = 0; h < 2; h++) {
                int lr = wm + mi * 16 + h * 8 + g4;
                sstat[nh][lr][0] = rs4[mi * 2 + h];
                sstat[nh][lr][1] = rq4[mi * 2 + h];
            }
    }
    __syncthreads();
    if (t < 128)
        cst[t] = make_float2(sstat[0][t][0] + sstat[1][t][0],
                             sstat[0][t][1] + sstat[1][t][1]);
    CLUSTER_SYNC();
    if (t < 128) {
        uint32_t laddr = smem_u32(&cst[t]);
        float s = 0.0f, q = 0.0f;
#pragma unroll
        for (int r = 0; r < 4; r++) {
            float2 v = dsmem_ld2(laddr, (uint32_t)r);
            s += v.x; q += v.y;
        }
        float mean = s * (1.0f / 512.0f);
        float var = q * (1.0f / 512.0f) - mean * mean;
        srow[t] = make_float2(mean, rsqrtf(var + 1e-5f));
    }
    __syncthreads();
#pragma unroll
    for (int mi = 0; mi < 2; mi++)
#pragma unroll
        for (int nj = 0; nj < 8; nj++) {
            int lr = wm + mi * 16 + g4;
            int cc = c0 + wn + nj * 8 + l2;
            float2 gm = *(const float2*)(gamma + cc);
            float2 bt = *(const float2*)(beta + cc);
            float2 st0 = srow[lr], st1 = srow[lr + 8];
            *(float2*)(out + (size_t)(r0 + lr) * CC + cc) = make_float2(
                (acc[mi][nj][0] - st0.x) * st0.y * gm.x + bt.x,
                (acc[mi][nj][1] - st0.x) * st0.y * gm.y + bt.y);
            *(float2*)(out + (size_t)(r0 + lr + 8) * CC + cc) = make_float2(
                (acc[mi][nj][2] - st1.x) * st1.y * gm.x + bt.x,
                (acc[mi][nj][3] - st1.x) * st1.y * gm.y + bt.y);
        }
    CLUSTER_SYNC();
}

// ---------------- launch ----------------
extern "C" void kernel_launch(void* const* d_in, const int* in_sizes, int n_in,
                              void* d_out, int out_size) {
    const float* src   = (const float*)d_in[0];
    const float* tgt   = (const float*)d_in[1];
    const float* score = (const float*)d_in[2];
    const float* W     = (const float*)d_in[3];
    const float* bias  = (const float*)d_in[4];
    const float* gamma = (const float*)d_in[5];
    const float* beta  = (const float*)d_in[6];
    float* out = (float*)d_out;

    const size_t OUT_OT = (size_t)BB * NN * CC;
    float* out_ot = out + OUT_OT;
    float* out_pi = out + OUT_OT + BB;

    k_init<<<1, 512>>>();
    k_nu_count<<<(BB * NN) / 256, 256>>>(score);
    k_nu_final<<<BB, MM>>>();
    k_prep_src<<<NB, 128>>>(src);
    k_ynorm<<<BB * MM, 128>>>(tgt);
    k_tw2<<<128, 256>>>(tgt, W);
    k_prep_w<<<256, 256>>>(W);
    k_prep_tail<<<256, 256>>>();
    k_cost_hmma<<<512, 256>>>();
    k_sink_all<<<128, 512>>>();
    k_pick<<<1, 64>>>();
    k_sink_epi<<<128, 512>>>(out_pi);
    k_ot_final<<<1, 16>>>(out_ot);
    k_gemm_hmma<<<dim3(4, 512), 256>>>(bias, gamma, beta, out);
}